// round 10
// baseline (speedup 1.0000x reference)
#include <cuda_runtime.h>
#include <math.h>

#define Bb 8
#define Tt 128
#define Nn 256
#define Dd 64
#define D3 192
#define BTND 16777216   // 8*128*256*64

// ---------------- device scratch ----------------
__device__ float g_ALN[BTND];          // aligner output, [B,T,N,D]
__device__ float g_X1[BTND];           // post-ln1, [B,N,T,D]
__device__ unsigned g_ADPu[Nn*Nn];     // adjacency, tf32 bits, row-major [m][n]

__device__ __forceinline__ unsigned f2tf32(float f) {
    unsigned u;
    asm("cvt.rna.tf32.f32 %0, %1;" : "=r"(u) : "f"(f));
    return u;
}
__device__ __forceinline__ float tanha(float x) {
    float y;
    asm("tanh.approx.f32 %0, %1;" : "=f"(y) : "f"(x));
    return y;
}
__device__ __forceinline__ float siga(float x) { return 0.5f*tanha(0.5f*x) + 0.5f; }

#define MMA_TF32(c0,c1,c2,c3,a0,a1,a2,a3,b0,b1) \
    asm volatile("mma.sync.aligned.m16n8k8.row.col.f32.tf32.tf32.f32 " \
        "{%0,%1,%2,%3}, {%4,%5,%6,%7}, {%8,%9}, {%0,%1,%2,%3};" \
        : "+f"(c0), "+f"(c1), "+f"(c2), "+f"(c3) \
        : "r"(a0), "r"(a1), "r"(a2), "r"(a3), "r"(b0), "r"(b1))

// ---------------- adjacency ----------------
__global__ void k_adj(const float* __restrict__ e1, const float* __restrict__ e2) {
    int m = blockIdx.x;
    int n = threadIdx.x;            // 256 threads
    float a = 0.f;
#pragma unroll
    for (int k = 0; k < 32; k++) a = fmaf(e1[m*32 + k], e2[k*256 + n], a);
    a = fmaxf(a, 0.f);
    __shared__ float red[256];
    red[n] = a; __syncthreads();
    for (int s = 128; s > 0; s >>= 1) { if (n < s) red[n] = fmaxf(red[n], red[n+s]); __syncthreads(); }
    float mx = red[0]; __syncthreads();
    float e = expf(a - mx);
    red[n] = e; __syncthreads();
    for (int s = 128; s > 0; s >>= 1) { if (n < s) red[n] += red[n+s]; __syncthreads(); }
    g_ADPu[m*256 + n] = f2tf32(e / red[0]);
}

// shared fragment helper ------------------------------------------------------
__device__ __forceinline__ void gemm_c8(const unsigned* __restrict__ As,
                                        const unsigned* __restrict__ Bs,
                                        int mrow, int qr, int kc, float c[8][4]) {
    unsigned a[8][4];
#pragma unroll
    for (int ks = 0; ks < 8; ks++) {
        a[ks][0] = As[mrow*68 + ks*8 + kc];
        a[ks][1] = As[(mrow+8)*68 + ks*8 + kc];
        a[ks][2] = As[mrow*68 + ks*8 + kc + 4];
        a[ks][3] = As[(mrow+8)*68 + ks*8 + kc + 4];
    }
#pragma unroll
    for (int nt = 0; nt < 8; nt++) {
        c[nt][0]=0.f; c[nt][1]=0.f; c[nt][2]=0.f; c[nt][3]=0.f;
        int ncol = nt*8 + qr;
#pragma unroll
        for (int ks = 0; ks < 8; ks++) {
            unsigned b0 = Bs[ncol*68 + ks*8 + kc];
            unsigned b1 = Bs[ncol*68 + ks*8 + kc + 4];
            MMA_TF32(c[nt][0],c[nt][1],c[nt][2],c[nt][3],
                     a[ks][0],a[ks][1],a[ks][2],a[ks][3], b0,b1);
        }
    }
}

// ---------------- fused QKV + temporal attention ----------------
__global__ void __launch_bounds__(256, 1) k_attn(
        const float* __restrict__ Hi, const float* __restrict__ Hj,
        const float* __restrict__ Wq, const float* __restrict__ bq,
        const float* __restrict__ Wk, const float* __restrict__ bk,
        const float* __restrict__ Wv, const float* __restrict__ bv,
        const float* __restrict__ lg, const float* __restrict__ lt) {
    extern __shared__ float sm[];
    unsigned* Hs = (unsigned*)sm;
    unsigned* Ws = Hs + 8704;
    float*    Ps = sm;
    unsigned* Pu = (unsigned*)sm;
    unsigned* Qs = Hs + 16896;
    unsigned* Ks = Hs + 25600;
    unsigned* Vt = Hs + 34304;
    float* biasr = sm + 42560;

    int tid = threadIdx.x;
    int bn = blockIdx.x;
    int b = bn >> 8, n = bn & 255;

    float gamma = fmaxf(expf(*lg), 0.01f);
    float tau   = fmaxf(expf(*lt), 0.01f);
    float scale = 1.0f / (8.0f * tau);
    if (tid < 128) biasr[tid] = logf(expf(-gamma * (float)tid * (1.0f/127.0f)) + 1e-8f);

    int w = tid >> 5, lane = tid & 31;
    int qr = lane >> 2, kc = lane & 3;
    int mrow = w*16 + qr;

    for (int idx = tid; idx < 2048; idx += 256) {
        int i = idx >> 4, c4 = idx & 15;
        float4 hv = *(const float4*)(Hj + ((size_t)(b*Tt + i)*Nn + n)*Dd + c4*4);
        uint4 pv; pv.x=f2tf32(hv.x); pv.y=f2tf32(hv.y); pv.z=f2tf32(hv.z); pv.w=f2tf32(hv.w);
        *(uint4*)(Hs + i*68 + c4*4) = pv;
    }
    for (int idx = tid; idx < 1024; idx += 256) {
        int r = idx >> 4, c4 = idx & 15;
        float4 wv = *(const float4*)(Wk + (size_t)r*64 + c4*4);
        uint4 pv; pv.x=f2tf32(wv.x); pv.y=f2tf32(wv.y); pv.z=f2tf32(wv.z); pv.w=f2tf32(wv.w);
        *(uint4*)(Ws + r*68 + c4*4) = pv;
    }
    __syncthreads();

    {
        float c[8][4];
        gemm_c8(Hs, Ws, mrow, qr, kc, c);
#pragma unroll
        for (int nt = 0; nt < 8; nt++) {
            int d = nt*8 + 2*kc;
            float bx = bk[d], by = bk[d+1];
            Ks[mrow*68 + d]       = f2tf32(c[nt][0] + bx);
            Ks[mrow*68 + d + 1]   = f2tf32(c[nt][1] + by);
            Ks[(mrow+8)*68 + d]     = f2tf32(c[nt][2] + bx);
            Ks[(mrow+8)*68 + d + 1] = f2tf32(c[nt][3] + by);
        }
    }
    __syncthreads();
    for (int idx = tid; idx < 1024; idx += 256) {
        int r = idx >> 4, c4 = idx & 15;
        float4 wv = *(const float4*)(Wv + (size_t)r*64 + c4*4);
        uint4 pv; pv.x=f2tf32(wv.x); pv.y=f2tf32(wv.y); pv.z=f2tf32(wv.z); pv.w=f2tf32(wv.w);
        *(uint4*)(Ws + r*68 + c4*4) = pv;
    }
    __syncthreads();
    {
        float c[8][4];
        gemm_c8(Hs, Ws, mrow, qr, kc, c);
#pragma unroll
        for (int nt = 0; nt < 8; nt++) {
            int d = nt*8 + 2*kc;
            float bx = bv[d], by = bv[d+1];
            Vt[d*129 + mrow]         = f2tf32(c[nt][0] + bx);
            Vt[(d+1)*129 + mrow]     = f2tf32(c[nt][1] + by);
            Vt[d*129 + mrow + 8]     = f2tf32(c[nt][2] + bx);
            Vt[(d+1)*129 + mrow + 8] = f2tf32(c[nt][3] + by);
        }
    }
    __syncthreads();
    for (int idx = tid; idx < 2048; idx += 256) {
        int i = idx >> 4, c4 = idx & 15;
        float4 hv = *(const float4*)(Hi + ((size_t)(b*Tt + i)*Nn + n)*Dd + c4*4);
        uint4 pv; pv.x=f2tf32(hv.x); pv.y=f2tf32(hv.y); pv.z=f2tf32(hv.z); pv.w=f2tf32(hv.w);
        *(uint4*)(Hs + i*68 + c4*4) = pv;
    }
    for (int idx = tid; idx < 1024; idx += 256) {
        int r = idx >> 4, c4 = idx & 15;
        float4 wv = *(const float4*)(Wq + (size_t)r*64 + c4*4);
        uint4 pv; pv.x=f2tf32(wv.x); pv.y=f2tf32(wv.y); pv.z=f2tf32(wv.z); pv.w=f2tf32(wv.w);
        *(uint4*)(Ws + r*68 + c4*4) = pv;
    }
    __syncthreads();
    {
        float c[8][4];
        gemm_c8(Hs, Ws, mrow, qr, kc, c);
#pragma unroll
        for (int nt = 0; nt < 8; nt++) {
            int d = nt*8 + 2*kc;
            float bx = bq[d], by = bq[d+1];
            Qs[mrow*68 + d]       = f2tf32(c[nt][0] + bx);
            Qs[mrow*68 + d + 1]   = f2tf32(c[nt][1] + by);
            Qs[(mrow+8)*68 + d]     = f2tf32(c[nt][2] + bx);
            Qs[(mrow+8)*68 + d + 1] = f2tf32(c[nt][3] + by);
        }
    }
    __syncthreads();

    unsigned a[8][4];
#pragma unroll
    for (int ks = 0; ks < 8; ks++) {
        a[ks][0] = Qs[mrow*68 + ks*8 + kc];
        a[ks][1] = Qs[(mrow+8)*68 + ks*8 + kc];
        a[ks][2] = Qs[mrow*68 + ks*8 + kc + 4];
        a[ks][3] = Qs[(mrow+8)*68 + ks*8 + kc + 4];
    }
    float c[16][4];
#pragma unroll
    for (int nt = 0; nt < 16; nt++) { c[nt][0]=0.f; c[nt][1]=0.f; c[nt][2]=0.f; c[nt][3]=0.f; }
#pragma unroll
    for (int nt = 0; nt < 16; nt++) {
        int ncol = nt*8 + qr;
#pragma unroll
        for (int ks = 0; ks < 8; ks++) {
            unsigned b0 = Ks[ncol*68 + ks*8 + kc];
            unsigned b1 = Ks[ncol*68 + ks*8 + kc + 4];
            MMA_TF32(c[nt][0],c[nt][1],c[nt][2],c[nt][3],
                     a[ks][0],a[ks][1],a[ks][2],a[ks][3], b0,b1);
        }
    }

    int i1 = mrow, i2 = mrow + 8;
#pragma unroll
    for (int nt = 0; nt < 16; nt++) {
        int j0 = nt*8 + 2*kc;
        int d10 = i1 - j0;     d10 = d10 < 0 ? -d10 : d10;
        int d11 = i1 - j0 - 1; d11 = d11 < 0 ? -d11 : d11;
        int d20 = i2 - j0;     d20 = d20 < 0 ? -d20 : d20;
        int d21 = i2 - j0 - 1; d21 = d21 < 0 ? -d21 : d21;
        Ps[i1*132 + j0]     = c[nt][0]*scale + biasr[d10];
        Ps[i1*132 + j0 + 1] = c[nt][1]*scale + biasr[d11];
        Ps[i2*132 + j0]     = c[nt][2]*scale + biasr[d20];
        Ps[i2*132 + j0 + 1] = c[nt][3]*scale + biasr[d21];
    }
    __syncthreads();

    for (int rr = 0; rr < 16; rr++) {
        int i = w*16 + rr;
        float v0 = Ps[i*132 + lane], v1 = Ps[i*132 + lane + 32],
              v2 = Ps[i*132 + lane + 64], v3 = Ps[i*132 + lane + 96];
        float mx = fmaxf(fmaxf(v0, v1), fmaxf(v2, v3));
#pragma unroll
        for (int off = 16; off > 0; off >>= 1) mx = fmaxf(mx, __shfl_xor_sync(0xffffffff, mx, off));
        float e0 = __expf(v0 - mx), e1 = __expf(v1 - mx), e2 = __expf(v2 - mx), e3 = __expf(v3 - mx);
        float su = (e0 + e1) + (e2 + e3);
#pragma unroll
        for (int off = 16; off > 0; off >>= 1) su += __shfl_xor_sync(0xffffffff, su, off);
        float inv = 1.0f / su;
        Pu[i*132 + lane]      = f2tf32(e0 * inv);
        Pu[i*132 + lane + 32] = f2tf32(e1 * inv);
        Pu[i*132 + lane + 64] = f2tf32(e2 * inv);
        Pu[i*132 + lane + 96] = f2tf32(e3 * inv);
    }
    __syncthreads();

    float c2[8][4];
#pragma unroll
    for (int nt = 0; nt < 8; nt++) { c2[nt][0]=0.f; c2[nt][1]=0.f; c2[nt][2]=0.f; c2[nt][3]=0.f; }
#pragma unroll
    for (int ks = 0; ks < 16; ks++) {
        unsigned a0 = Pu[mrow*132 + ks*8 + kc];
        unsigned a1 = Pu[(mrow+8)*132 + ks*8 + kc];
        unsigned a2 = Pu[mrow*132 + ks*8 + kc + 4];
        unsigned a3 = Pu[(mrow+8)*132 + ks*8 + kc + 4];
#pragma unroll
        for (int nt = 0; nt < 8; nt++) {
            unsigned b0 = Vt[(nt*8+qr)*129 + ks*8 + kc];
            unsigned b1 = Vt[(nt*8+qr)*129 + ks*8 + kc + 4];
            MMA_TF32(c2[nt][0],c2[nt][1],c2[nt][2],c2[nt][3], a0,a1,a2,a3, b0,b1);
        }
    }
#pragma unroll
    for (int nt = 0; nt < 8; nt++) {
        int d = nt*8 + 2*kc;
        float2 o0; o0.x = c2[nt][0]; o0.y = c2[nt][1];
        float2 o1; o1.x = c2[nt][2]; o1.y = c2[nt][3];
        *(float2*)(g_ALN + ((size_t)(b*Tt + mrow)*Nn + n)*Dd + d)     = o0;
        *(float2*)(g_ALN + ((size_t)(b*Tt + mrow + 8)*Nn + n)*Dd + d) = o1;
    }
}

// ---------------- GCN + residual + LN1, tf32 tensor core ----------------
__global__ void __launch_bounds__(256, 2) k_gcn(const float* __restrict__ Wg,
                                                const float* __restrict__ bg,
                                                const float* __restrict__ ln1g,
                                                const float* __restrict__ ln1b) {
    extern __shared__ float sg[];
    unsigned* As  = (unsigned*)sg;
    unsigned* Bs  = As + 8704;
    unsigned* Tmp = As + 12864;
    unsigned* Wgs = As + 21568;
    float* h2 = sg;   // overlays As

    int tid = threadIdx.x;
    int blk = blockIdx.x;
    int bt = blk >> 1, half = blk & 1;
    int m0g = half * 128;
    int b = bt >> 7, t = bt & 127;
    const float* Xbt = g_ALN + (size_t)bt * 16384;

    int w = tid >> 5, lane = tid & 31;
    int qr = lane >> 2, kc = lane & 3;
    int mrow = w*16 + qr;

    for (int idx = tid; idx < 1024; idx += 256) {
        int r = idx >> 4, c4 = idx & 15;
        float4 wv = *(const float4*)(Wg + (size_t)r*64 + c4*4);
        uint4 pv; pv.x = f2tf32(wv.x); pv.y = f2tf32(wv.y);
        pv.z = f2tf32(wv.z); pv.w = f2tf32(wv.w);
        *(uint4*)(Wgs + r*68 + c4*4) = pv;
    }

    float c1[8][4];
#pragma unroll
    for (int nt = 0; nt < 8; nt++) { c1[nt][0]=0.f; c1[nt][1]=0.f; c1[nt][2]=0.f; c1[nt][3]=0.f; }

    for (int ch = 0; ch < 4; ch++) {
        __syncthreads();
        for (int idx = tid; idx < 2048; idx += 256) {
            int r = idx >> 4, c4 = idx & 15;
            *(uint4*)(As + r*68 + c4*4) =
                *(const uint4*)(g_ADPu + (size_t)(m0g + r)*256 + ch*64 + c4*4);
        }
        for (int idx = tid; idx < 1024; idx += 256) {
            int nn = idx >> 4, c4 = idx & 15;
            float4 xv = *(const float4*)(Xbt + (size_t)(ch*64 + nn)*64 + c4*4);
            Bs[(c4*4+0)*65 + nn] = f2tf32(xv.x);
            Bs[(c4*4+1)*65 + nn] = f2tf32(xv.y);
            Bs[(c4*4+2)*65 + nn] = f2tf32(xv.z);
            Bs[(c4*4+3)*65 + nn] = f2tf32(xv.w);
        }
        __syncthreads();
#pragma unroll
        for (int ks = 0; ks < 8; ks++) {
            unsigned a0 = As[mrow*68 + ks*8 + kc];
            unsigned a1 = As[(mrow+8)*68 + ks*8 + kc];
            unsigned a2 = As[mrow*68 + ks*8 + kc + 4];
            unsigned a3 = As[(mrow+8)*68 + ks*8 + kc + 4];
#pragma unroll
            for (int nt = 0; nt < 8; nt++) {
                unsigned b0 = Bs[(nt*8+qr)*65 + ks*8 + kc];
                unsigned b1 = Bs[(nt*8+qr)*65 + ks*8 + kc + 4];
                MMA_TF32(c1[nt][0],c1[nt][1],c1[nt][2],c1[nt][3], a0,a1,a2,a3, b0,b1);
            }
        }
    }

#pragma unroll
    for (int nt = 0; nt < 8; nt++) {
        int d0 = nt*8 + 2*kc;
        Tmp[mrow*68 + d0]       = f2tf32(c1[nt][0]);
        Tmp[mrow*68 + d0 + 1]   = f2tf32(c1[nt][1]);
        Tmp[(mrow+8)*68 + d0]     = f2tf32(c1[nt][2]);
        Tmp[(mrow+8)*68 + d0 + 1] = f2tf32(c1[nt][3]);
    }
    __syncwarp();

    float c2[8][4];
#pragma unroll
    for (int nt = 0; nt < 8; nt++) { c2[nt][0]=0.f; c2[nt][1]=0.f; c2[nt][2]=0.f; c2[nt][3]=0.f; }
#pragma unroll
    for (int ks = 0; ks < 8; ks++) {
        unsigned a0 = Tmp[mrow*68 + ks*8 + kc];
        unsigned a1 = Tmp[(mrow+8)*68 + ks*8 + kc];
        unsigned a2 = Tmp[mrow*68 + ks*8 + kc + 4];
        unsigned a3 = Tmp[(mrow+8)*68 + ks*8 + kc + 4];
#pragma unroll
        for (int nt = 0; nt < 8; nt++) {
            unsigned b0 = Wgs[(nt*8+qr)*68 + ks*8 + kc];
            unsigned b1 = Wgs[(nt*8+qr)*68 + ks*8 + kc + 4];
            MMA_TF32(c2[nt][0],c2[nt][1],c2[nt][2],c2[nt][3], a0,a1,a2,a3, b0,b1);
        }
    }
    __syncthreads();

#pragma unroll
    for (int nt = 0; nt < 8; nt++) {
        int e0 = nt*8 + 2*kc;
        float bx = bg[e0], by = bg[e0+1];
        h2[mrow*68 + e0]       = fmaxf(c2[nt][0] + bx, 0.f);
        h2[mrow*68 + e0 + 1]   = fmaxf(c2[nt][1] + by, 0.f);
        h2[(mrow+8)*68 + e0]     = fmaxf(c2[nt][2] + bx, 0.f);
        h2[(mrow+8)*68 + e0 + 1] = fmaxf(c2[nt][3] + by, 0.f);
    }
    __syncthreads();

    float gg0 = ln1g[lane], gg1 = ln1g[lane+32];
    float bb0 = ln1b[lane], bb1 = ln1b[lane+32];
    for (int mm = 0; mm < 16; mm++) {
        int m = w*16 + mm;
        const float* xr = Xbt + (size_t)(m0g + m)*64;
        float u0 = xr[lane]      + h2[m*68 + lane];
        float u1 = xr[lane + 32] + h2[m*68 + lane + 32];
        float su = u0 + u1;
#pragma unroll
        for (int off = 16; off > 0; off >>= 1) su += __shfl_xor_sync(0xffffffff, su, off);
        float mean = su * (1.0f/64.0f);
        float dd0 = u0 - mean, dd1 = u1 - mean;
        float q = dd0*dd0 + dd1*dd1;
#pragma unroll
        for (int off = 16; off > 0; off >>= 1) q += __shfl_xor_sync(0xffffffff, q, off);
        float rs = rsqrtf(q*(1.0f/64.0f) + 1e-5f);
        size_t o = ((size_t)(b*Nn + m0g + m)*Tt + t)*Dd;
        g_X1[o + lane]      = dd0*rs*gg0 + bb0;
        g_X1[o + lane + 32] = dd1*rs*gg1 + bb1;
    }
}

// ---------------- tensor-core GRU: minimal serial loop, batched LN/output ----------------
// smem (words): staging Whs[192][68]@0, Wis[192][68]@13056 (26112 total).
// After hoist, reuse: X1s tf32 [4][16][68]@0 (4352), X1f fp32 @4352 (4352),
// Hb0@8704 (1088), Hb1@9792 (1088), U4 fp32 [4][16][68]@10880 (4352) -> 15232 <= 26112.
__global__ void __launch_bounds__(256) k_gru_tc(const float* __restrict__ Whh,
                                                const float* __restrict__ bhh,
                                                const float* __restrict__ Wih,
                                                const float* __restrict__ bih,
                                                const float* __restrict__ ln2g,
                                                const float* __restrict__ ln2b,
                                                float* __restrict__ out) {
    extern __shared__ unsigned su_[];
    unsigned* Whs = su_;
    unsigned* Wis = su_ + 13056;
    unsigned* X1s = su_;
    float*    X1f = (float*)(su_ + 4352);
    unsigned* Hb0 = su_ + 8704;
    unsigned* Hb1 = su_ + 9792;
    float*    U4  = (float*)(su_ + 10880);

    int tid = threadIdx.x;
    int w = tid >> 5, lane = tid & 31;
    int qr = lane >> 2, kc = lane & 3;
    int s_base = blockIdx.x * 16;
    int b = s_base >> 8;
    int node0 = s_base & 255;

    // stage weights
    for (int idx = tid; idx < 3072; idx += 256) {
        int r = idx >> 4, c4 = idx & 15;
        float4 wv = *(const float4*)(Whh + (size_t)r*64 + c4*4);
        uint4 pv; pv.x = f2tf32(wv.x); pv.y = f2tf32(wv.y);
        pv.z = f2tf32(wv.z); pv.w = f2tf32(wv.w);
        *(uint4*)(Whs + r*68 + c4*4) = pv;
        float4 iv = *(const float4*)(Wih + (size_t)r*64 + c4*4);
        uint4 qv; qv.x = f2tf32(iv.x); qv.y = f2tf32(iv.y);
        qv.z = f2tf32(iv.z); qv.w = f2tf32(iv.w);
        *(uint4*)(Wis + r*68 + c4*4) = qv;
    }
    __syncthreads();

    // hoist ALL weight fragments to registers
    unsigned br_[8][2], bz_[8][2], bn_[8][2];
    unsigned wr_[8][2], wz_[8][2], wn_[8][2];
#pragma unroll
    for (int ks = 0; ks < 8; ks++) {
        int nr = (0*64 + w*8 + qr)*68 + ks*8 + kc;
        int nz = (1*64 + w*8 + qr)*68 + ks*8 + kc;
        int nn = (2*64 + w*8 + qr)*68 + ks*8 + kc;
        br_[ks][0] = Whs[nr]; br_[ks][1] = Whs[nr + 4];
        bz_[ks][0] = Whs[nz]; bz_[ks][1] = Whs[nz + 4];
        bn_[ks][0] = Whs[nn]; bn_[ks][1] = Whs[nn + 4];
        wr_[ks][0] = Wis[nr]; wr_[ks][1] = Wis[nr + 4];
        wz_[ks][0] = Wis[nz]; wz_[ks][1] = Wis[nz + 4];
        wn_[ks][0] = Wis[nn]; wn_[ks][1] = Wis[nn + 4];
    }
    __syncthreads();   // staging region now reusable

    for (int idx = tid; idx < 1088; idx += 256) Hb0[idx] = 0;
    // covered by chunk-top barrier

    int col0 = w*8 + 2*kc;
    float2 bhr = *(const float2*)(bhh + col0);
    float2 bhz = *(const float2*)(bhh + 64 + col0);
    float2 bhn = *(const float2*)(bhh + 128 + col0);
    float2 bir = *(const float2*)(bih + col0);
    float2 biz = *(const float2*)(bih + 64 + col0);
    float2 bin_ = *(const float2*)(bih + 128 + col0);
    float g2a = ln2g[lane], g2b = ln2g[lane+32];
    float b2a = ln2b[lane], b2b = ln2b[lane+32];

    float h_old[4] = {0.f, 0.f, 0.f, 0.f};

    for (int tc = 0; tc < Tt; tc += 4) {
        __syncthreads();   // fence previous chunk's X1f/U4 reads before restaging

        // stage x1 chunk: tf32 for mma, fp32 for residual/LN
        for (int idx = tid; idx < 4096; idx += 256) {
            int s = idx >> 10, rem = idx & 1023, row = rem >> 6, col = rem & 63;
            float v = g_X1[(size_t)(s_base + row)*Tt*Dd + (size_t)(tc + s)*Dd + col];
            X1s[s*1088 + row*68 + col] = f2tf32(v);
            X1f[s*1088 + row*68 + col] = v;
        }
        __syncthreads();

        // gi for 4 steps -> registers
        float gr_[4][4], gz_[4][4], gn_[4][4];
#pragma unroll
        for (int s = 0; s < 4; s++) {
            const unsigned* Xc = X1s + s*1088;
            unsigned ax[8][4];
#pragma unroll
            for (int ks = 0; ks < 8; ks++) {
                ax[ks][0] = Xc[qr*68 + ks*8 + kc];
                ax[ks][1] = Xc[(qr+8)*68 + ks*8 + kc];
                ax[ks][2] = Xc[qr*68 + ks*8 + kc + 4];
                ax[ks][3] = Xc[(qr+8)*68 + ks*8 + kc + 4];
            }
            gr_[s][0]=0.f; gr_[s][1]=0.f; gr_[s][2]=0.f; gr_[s][3]=0.f;
            gz_[s][0]=0.f; gz_[s][1]=0.f; gz_[s][2]=0.f; gz_[s][3]=0.f;
            gn_[s][0]=0.f; gn_[s][1]=0.f; gn_[s][2]=0.f; gn_[s][3]=0.f;
#pragma unroll
            for (int ks = 0; ks < 8; ks++) {
                MMA_TF32(gr_[s][0],gr_[s][1],gr_[s][2],gr_[s][3], ax[ks][0],ax[ks][1],ax[ks][2],ax[ks][3], wr_[ks][0],wr_[ks][1]);
                MMA_TF32(gz_[s][0],gz_[s][1],gz_[s][2],gz_[s][3], ax[ks][0],ax[ks][1],ax[ks][2],ax[ks][3], wz_[ks][0],wz_[ks][1]);
                MMA_TF32(gn_[s][0],gn_[s][1],gn_[s][2],gn_[s][3], ax[ks][0],ax[ks][1],ax[ks][2],ax[ks][3], wn_[ks][0],wn_[ks][1]);
            }
        }

        // serial 4 steps: mma -> gates -> store H,u -> barrier. LN deferred.
#pragma unroll
        for (int s = 0; s < 4; s++) {
            int t = tc + s;
            unsigned* Hc = (t & 1) ? Hb1 : Hb0;
            unsigned* Hn = (t & 1) ? Hb0 : Hb1;
            float* Us = U4 + s*1088;
            const float* Xf = X1f + s*1088;

            float2 xa = *(const float2*)(Xf + qr*68 + col0);
            float2 xb = *(const float2*)(Xf + (qr+8)*68 + col0);

            float cr[4] = {0.f,0.f,0.f,0.f}, cz[4] = {0.f,0.f,0.f,0.f}, cn[4] = {0.f,0.f,0.f,0.f};
            {
                unsigned a[8][4];
#pragma unroll
                for (int ks = 0; ks < 8; ks++) {
                    a[ks][0] = Hc[qr*68 + ks*8 + kc];
                    a[ks][1] = Hc[(qr+8)*68 + ks*8 + kc];
                    a[ks][2] = Hc[qr*68 + ks*8 + kc + 4];
                    a[ks][3] = Hc[(qr+8)*68 + ks*8 + kc + 4];
                }
#pragma unroll
                for (int ks = 0; ks < 8; ks++) {
                    MMA_TF32(cr[0],cr[1],cr[2],cr[3], a[ks][0],a[ks][1],a[ks][2],a[ks][3], br_[ks][0],br_[ks][1]);
                    MMA_TF32(cz[0],cz[1],cz[2],cz[3], a[ks][0],a[ks][1],a[ks][2],a[ks][3], bz_[ks][0],bz_[ks][1]);
                    MMA_TF32(cn[0],cn[1],cn[2],cn[3], a[ks][0],a[ks][1],a[ks][2],a[ks][3], bn_[ks][0],bn_[ks][1]);
                }
            }

            float r0 = siga(gr_[s][0] + bir.x + cr[0] + bhr.x);
            float r1 = siga(gr_[s][1] + bir.y + cr[1] + bhr.y);
            float r2 = siga(gr_[s][2] + bir.x + cr[2] + bhr.x);
            float r3 = siga(gr_[s][3] + bir.y + cr[3] + bhr.y);
            float z0 = siga(gz_[s][0] + biz.x + cz[0] + bhz.x);
            float z1 = siga(gz_[s][1] + biz.y + cz[1] + bhz.y);
            float z2 = siga(gz_[s][2] + biz.x + cz[2] + bhz.x);
            float z3 = siga(gz_[s][3] + biz.y + cz[3] + bhz.y);
            float n0 = tanha(gn_[s][0] + bin_.x + r0*(cn[0] + bhn.x));
            float n1 = tanha(gn_[s][1] + bin_.y + r1*(cn[1] + bhn.y));
            float n2 = tanha(gn_[s][2] + bin_.x + r2*(cn[2] + bhn.x));
            float n3 = tanha(gn_[s][3] + bin_.y + r3*(cn[3] + bhn.y));
            float h0 = (1.f - z0)*n0 + z0*h_old[0];
            float h1 = (1.f - z1)*n1 + z1*h_old[1];
            float h2v = (1.f - z2)*n2 + z2*h_old[2];
            float h3 = (1.f - z3)*n3 + z3*h_old[3];
            h_old[0] = h0; h_old[1] = h1; h_old[2] = h2v; h_old[3] = h3;

            uint2 hp0; hp0.x = f2tf32(h0); hp0.y = f2tf32(h1);
            uint2 hp1; hp1.x = f2tf32(h2v); hp1.y = f2tf32(h3);
            *(uint2*)(Hn + qr*68 + col0)     = hp0;
            *(uint2*)(Hn + (qr+8)*68 + col0) = hp1;
            float2 up0; up0.x = xa.x + h0; up0.y = xa.y + h1;
            float2 up1; up1.x = xb.x + h2v; up1.y = xb.y + h3;
            *(float2*)(Us + qr*68 + col0)     = up0;
            *(float2*)(Us + (qr+8)*68 + col0) = up1;
            __syncthreads();
        }

        // batched LN + residual + output for the whole chunk:
        // 64 (s,row) instances; warp w handles 8 of them.
#pragma unroll
        for (int rr = 0; rr < 8; rr++) {
            int inst = w*8 + rr;           // 0..63
            int s = inst >> 4, row = inst & 15;
            const float* Us = U4 + s*1088;
            const float* Xf = X1f + s*1088;
            float v0 = Us[row*68 + lane], v1 = Us[row*68 + lane + 32];
            float sv = v0 + v1, qv = v0*v0 + v1*v1;
#pragma unroll
            for (int off = 16; off > 0; off >>= 1) {
                sv += __shfl_xor_sync(0xffffffff, sv, off);
                qv += __shfl_xor_sync(0xffffffff, qv, off);
            }
            float mean = sv * (1.0f/64.0f);
            float var = qv*(1.0f/64.0f) - mean*mean;
            float rs = rsqrtf(var + 1e-5f);
            float x0v = Xf[row*68 + lane], x1v = Xf[row*68 + lane + 32];
            size_t oo = (size_t)b*Tt*Nn*Dd + (size_t)(tc + s)*Nn*Dd + (size_t)(node0 + row)*Dd;
            out[oo + lane]      = x0v + (v0 - mean)*rs*g2a + b2a;
            out[oo + lane + 32] = x1v + (v1 - mean)*rs*g2b + b2b;
        }
    }
}

// ---------------- launcher ----------------
extern "C" void kernel_launch(void* const* d_in, const int* in_sizes, int n_in,
                              void* d_out, int out_size) {
    (void)in_sizes; (void)n_in; (void)out_size;
    const float* H_i  = (const float*)d_in[0];
    const float* H_j  = (const float*)d_in[1];
    const float* Wq   = (const float*)d_in[2];
    const float* bq   = (const float*)d_in[3];
    const float* Wk   = (const float*)d_in[4];
    const float* bk   = (const float*)d_in[5];
    const float* Wv   = (const float*)d_in[6];
    const float* bv   = (const float*)d_in[7];
    const float* lgam = (const float*)d_in[8];
    const float* ltau = (const float*)d_in[9];
    const float* e1   = (const float*)d_in[10];
    const float* e2   = (const float*)d_in[11];
    const float* Wg   = (const float*)d_in[12];
    const float* bg   = (const float*)d_in[13];
    const float* ln1g = (const float*)d_in[14];
    const float* ln1b = (const float*)d_in[15];
    const float* Wih  = (const float*)d_in[16];
    const float* Whh  = (const float*)d_in[17];
    const float* bih  = (const float*)d_in[18];
    const float* bhh  = (const float*)d_in[19];
    const float* ln2g = (const float*)d_in[20];
    const float* ln2b = (const float*)d_in[21];
    float* out = (float*)d_out;

    const int ATTN_SMEM = 42688 * 4;   // 170752 B
    const int GCN_SMEM  = 25920 * 4;   // 103680 B
    const int GRU_SMEM  = 26112 * 4;   // 104448 B
    cudaFuncSetAttribute(k_attn, cudaFuncAttributeMaxDynamicSharedMemorySize, ATTN_SMEM);
    cudaFuncSetAttribute(k_gcn,  cudaFuncAttributeMaxDynamicSharedMemorySize, GCN_SMEM);
    cudaFuncSetAttribute(k_gru_tc, cudaFuncAttributeMaxDynamicSharedMemorySize, GRU_SMEM);

    k_adj<<<256, 256>>>(e1, e2);
    k_attn<<<Bb*Nn, 256, ATTN_SMEM>>>(H_i, H_j, Wq, bq, Wk, bk, Wv, bv, lgam, ltau);
    k_gcn<<<Bb*Tt*2, 256, GCN_SMEM>>>(Wg, bg, ln1g, ln1b);
    k_gru_tc<<<Bb*Nn/16, 256, GRU_SMEM>>>(Whh, bhh, Wih, bih, ln2g, ln2b, out);
}

// round 11
// speedup vs baseline: 1.1323x; 1.1323x over previous
#include <cuda_runtime.h>
#include <math.h>

#define Bb 8
#define Tt 128
#define Nn 256
#define Dd 64
#define D3 192
#define BTND 16777216   // 8*128*256*64

// ---------------- device scratch ----------------
__device__ float g_ALN[BTND];          // aligner output, [B,T,N,D]
__device__ float g_X1[BTND];           // post-ln1, [B,N,T,D]
__device__ unsigned g_ADPu[Nn*Nn];     // adjacency, tf32 bits, row-major [m][n]

__device__ __forceinline__ unsigned f2tf32(float f) {
    unsigned u;
    asm("cvt.rna.tf32.f32 %0, %1;" : "=r"(u) : "f"(f));
    return u;
}
__device__ __forceinline__ float tanha(float x) {
    float y;
    asm("tanh.approx.f32 %0, %1;" : "=f"(y) : "f"(x));
    return y;
}
__device__ __forceinline__ float siga(float x) { return 0.5f*tanha(0.5f*x) + 0.5f; }

#define MMA_TF32(c0,c1,c2,c3,a0,a1,a2,a3,b0,b1) \
    asm volatile("mma.sync.aligned.m16n8k8.row.col.f32.tf32.tf32.f32 " \
        "{%0,%1,%2,%3}, {%4,%5,%6,%7}, {%8,%9}, {%0,%1,%2,%3};" \
        : "+f"(c0), "+f"(c1), "+f"(c2), "+f"(c3) \
        : "r"(a0), "r"(a1), "r"(a2), "r"(a3), "r"(b0), "r"(b1))

// ---------------- adjacency ----------------
__global__ void k_adj(const float* __restrict__ e1, const float* __restrict__ e2) {
    int m = blockIdx.x;
    int n = threadIdx.x;            // 256 threads
    float a = 0.f;
#pragma unroll
    for (int k = 0; k < 32; k++) a = fmaf(e1[m*32 + k], e2[k*256 + n], a);
    a = fmaxf(a, 0.f);
    __shared__ float red[256];
    red[n] = a; __syncthreads();
    for (int s = 128; s > 0; s >>= 1) { if (n < s) red[n] = fmaxf(red[n], red[n+s]); __syncthreads(); }
    float mx = red[0]; __syncthreads();
    float e = expf(a - mx);
    red[n] = e; __syncthreads();
    for (int s = 128; s > 0; s >>= 1) { if (n < s) red[n] += red[n+s]; __syncthreads(); }
    g_ADPu[m*256 + n] = f2tf32(e / red[0]);
}

// col-split projection gemm: warp computes rows [mrow,mrow+8], cols colbase..colbase+31
__device__ __forceinline__ void gemm_c4(const unsigned* __restrict__ As,
                                        const unsigned* __restrict__ Bs,
                                        int mrow, int qr, int kc, int colbase,
                                        float c[4][4]) {
    unsigned a[8][4];
#pragma unroll
    for (int ks = 0; ks < 8; ks++) {
        a[ks][0] = As[mrow*68 + ks*8 + kc];
        a[ks][1] = As[(mrow+8)*68 + ks*8 + kc];
        a[ks][2] = As[mrow*68 + ks*8 + kc + 4];
        a[ks][3] = As[(mrow+8)*68 + ks*8 + kc + 4];
    }
#pragma unroll
    for (int nt = 0; nt < 4; nt++) {
        c[nt][0]=0.f; c[nt][1]=0.f; c[nt][2]=0.f; c[nt][3]=0.f;
        int ncol = colbase + nt*8 + qr;
#pragma unroll
        for (int ks = 0; ks < 8; ks++) {
            unsigned b0 = Bs[ncol*68 + ks*8 + kc];
            unsigned b1 = Bs[ncol*68 + ks*8 + kc + 4];
            MMA_TF32(c[nt][0],c[nt][1],c[nt][2],c[nt][3],
                     a[ks][0],a[ks][1],a[ks][2],a[ks][3], b0,b1);
        }
    }
}

// ---------------- fused QKV + temporal attention, 512 threads ----------------
// smem layout identical to R9 (170752 B): Hs@0, Ws@8704 (P overlays @0 later),
// Qs@16896, Ks@25600, Vt@34304 [64][129], biasr@42560.
__global__ void __launch_bounds__(512, 1) k_attn(
        const float* __restrict__ Hi, const float* __restrict__ Hj,
        const float* __restrict__ Wq, const float* __restrict__ bq,
        const float* __restrict__ Wk, const float* __restrict__ bk,
        const float* __restrict__ Wv, const float* __restrict__ bv,
        const float* __restrict__ lg, const float* __restrict__ lt) {
    extern __shared__ float sm[];
    unsigned* Hs = (unsigned*)sm;
    unsigned* Ws = Hs + 8704;
    float*    Ps = sm;
    unsigned* Pu = (unsigned*)sm;
    unsigned* Qs = Hs + 16896;
    unsigned* Ks = Hs + 25600;
    unsigned* Vt = Hs + 34304;
    float* biasr = sm + 42560;

    int tid = threadIdx.x;
    int bn = blockIdx.x;
    int b = bn >> 8, n = bn & 255;

    float gamma = fmaxf(expf(*lg), 0.01f);
    float tau   = fmaxf(expf(*lt), 0.01f);
    float scale = 1.0f / (8.0f * tau);
    if (tid < 128) biasr[tid] = logf(expf(-gamma * (float)tid * (1.0f/127.0f)) + 1e-8f);

    int w = tid >> 5, lane = tid & 31;
    int qr = lane >> 2, kc = lane & 3;
    int wp = w >> 1, side = w & 1;       // warp pair id 0..7, column side 0/1
    int mrow = wp*16 + qr;

    // ---- load H_j + Wk ----
    for (int idx = tid; idx < 2048; idx += 512) {
        int i = idx >> 4, c4 = idx & 15;
        float4 hv = *(const float4*)(Hj + ((size_t)(b*Tt + i)*Nn + n)*Dd + c4*4);
        uint4 pv; pv.x=f2tf32(hv.x); pv.y=f2tf32(hv.y); pv.z=f2tf32(hv.z); pv.w=f2tf32(hv.w);
        *(uint4*)(Hs + i*68 + c4*4) = pv;
    }
    for (int idx = tid; idx < 1024; idx += 512) {
        int r = idx >> 4, c4 = idx & 15;
        float4 wv = *(const float4*)(Wk + (size_t)r*64 + c4*4);
        uint4 pv; pv.x=f2tf32(wv.x); pv.y=f2tf32(wv.y); pv.z=f2tf32(wv.z); pv.w=f2tf32(wv.w);
        *(uint4*)(Ws + r*68 + c4*4) = pv;
    }
    __syncthreads();

    // ---- K = Hj @ Wk^T + bk (warp: 16 rows x 32 cols) ----
    {
        float c[4][4];
        gemm_c4(Hs, Ws, mrow, qr, kc, side*32, c);
#pragma unroll
        for (int nt = 0; nt < 4; nt++) {
            int d = side*32 + nt*8 + 2*kc;
            float bx = bk[d], by = bk[d+1];
            Ks[mrow*68 + d]       = f2tf32(c[nt][0] + bx);
            Ks[mrow*68 + d + 1]   = f2tf32(c[nt][1] + by);
            Ks[(mrow+8)*68 + d]     = f2tf32(c[nt][2] + bx);
            Ks[(mrow+8)*68 + d + 1] = f2tf32(c[nt][3] + by);
        }
    }
    __syncthreads();
    // ---- load Wv ----
    for (int idx = tid; idx < 1024; idx += 512) {
        int r = idx >> 4, c4 = idx & 15;
        float4 wv = *(const float4*)(Wv + (size_t)r*64 + c4*4);
        uint4 pv; pv.x=f2tf32(wv.x); pv.y=f2tf32(wv.y); pv.z=f2tf32(wv.z); pv.w=f2tf32(wv.w);
        *(uint4*)(Ws + r*68 + c4*4) = pv;
    }
    __syncthreads();
    // ---- V = Hj @ Wv^T + bv -> Vt d-major ----
    {
        float c[4][4];
        gemm_c4(Hs, Ws, mrow, qr, kc, side*32, c);
#pragma unroll
        for (int nt = 0; nt < 4; nt++) {
            int d = side*32 + nt*8 + 2*kc;
            float bx = bv[d], by = bv[d+1];
            Vt[d*129 + mrow]         = f2tf32(c[nt][0] + bx);
            Vt[(d+1)*129 + mrow]     = f2tf32(c[nt][1] + by);
            Vt[d*129 + mrow + 8]     = f2tf32(c[nt][2] + bx);
            Vt[(d+1)*129 + mrow + 8] = f2tf32(c[nt][3] + by);
        }
    }
    __syncthreads();
    // ---- load H_i + Wq ----
    for (int idx = tid; idx < 2048; idx += 512) {
        int i = idx >> 4, c4 = idx & 15;
        float4 hv = *(const float4*)(Hi + ((size_t)(b*Tt + i)*Nn + n)*Dd + c4*4);
        uint4 pv; pv.x=f2tf32(hv.x); pv.y=f2tf32(hv.y); pv.z=f2tf32(hv.z); pv.w=f2tf32(hv.w);
        *(uint4*)(Hs + i*68 + c4*4) = pv;
    }
    for (int idx = tid; idx < 1024; idx += 512) {
        int r = idx >> 4, c4 = idx & 15;
        float4 wv = *(const float4*)(Wq + (size_t)r*64 + c4*4);
        uint4 pv; pv.x=f2tf32(wv.x); pv.y=f2tf32(wv.y); pv.z=f2tf32(wv.z); pv.w=f2tf32(wv.w);
        *(uint4*)(Ws + r*68 + c4*4) = pv;
    }
    __syncthreads();
    // ---- Q = Hi @ Wq^T + bq ----
    {
        float c[4][4];
        gemm_c4(Hs, Ws, mrow, qr, kc, side*32, c);
#pragma unroll
        for (int nt = 0; nt < 4; nt++) {
            int d = side*32 + nt*8 + 2*kc;
            float bx = bq[d], by = bq[d+1];
            Qs[mrow*68 + d]       = f2tf32(c[nt][0] + bx);
            Qs[mrow*68 + d + 1]   = f2tf32(c[nt][1] + by);
            Qs[(mrow+8)*68 + d]     = f2tf32(c[nt][2] + bx);
            Qs[(mrow+8)*68 + d + 1] = f2tf32(c[nt][3] + by);
        }
    }
    __syncthreads();

    // ---- S = Q K^T (warp: 16 rows x 64 cols, side-split) ----
    unsigned a[8][4];
#pragma unroll
    for (int ks = 0; ks < 8; ks++) {
        a[ks][0] = Qs[mrow*68 + ks*8 + kc];
        a[ks][1] = Qs[(mrow+8)*68 + ks*8 + kc];
        a[ks][2] = Qs[mrow*68 + ks*8 + kc + 4];
        a[ks][3] = Qs[(mrow+8)*68 + ks*8 + kc + 4];
    }
    float c[8][4];
#pragma unroll
    for (int nt = 0; nt < 8; nt++) { c[nt][0]=0.f; c[nt][1]=0.f; c[nt][2]=0.f; c[nt][3]=0.f; }
#pragma unroll
    for (int nt = 0; nt < 8; nt++) {
        int ncol = side*64 + nt*8 + qr;
#pragma unroll
        for (int ks = 0; ks < 8; ks++) {
            unsigned b0 = Ks[ncol*68 + ks*8 + kc];
            unsigned b1 = Ks[ncol*68 + ks*8 + kc + 4];
            MMA_TF32(c[nt][0],c[nt][1],c[nt][2],c[nt][3],
                     a[ks][0],a[ks][1],a[ks][2],a[ks][3], b0,b1);
        }
    }
    __syncthreads();   // Qs reads done before P overlay (P overlays Hs/Ws, but keep order safe)

    int i1 = mrow, i2 = mrow + 8;
#pragma unroll
    for (int nt = 0; nt < 8; nt++) {
        int j0 = side*64 + nt*8 + 2*kc;
        int d10 = i1 - j0;     d10 = d10 < 0 ? -d10 : d10;
        int d11 = i1 - j0 - 1; d11 = d11 < 0 ? -d11 : d11;
        int d20 = i2 - j0;     d20 = d20 < 0 ? -d20 : d20;
        int d21 = i2 - j0 - 1; d21 = d21 < 0 ? -d21 : d21;
        Ps[i1*132 + j0]     = c[nt][0]*scale + biasr[d10];
        Ps[i1*132 + j0 + 1] = c[nt][1]*scale + biasr[d11];
        Ps[i2*132 + j0]     = c[nt][2]*scale + biasr[d20];
        Ps[i2*132 + j0 + 1] = c[nt][3]*scale + biasr[d21];
    }
    __syncthreads();

    // ---- softmax rows (16 warps x 8 rows), write P tf32 ----
    for (int rr = 0; rr < 8; rr++) {
        int i = w*8 + rr;
        float v0 = Ps[i*132 + lane], v1 = Ps[i*132 + lane + 32],
              v2 = Ps[i*132 + lane + 64], v3 = Ps[i*132 + lane + 96];
        float mx = fmaxf(fmaxf(v0, v1), fmaxf(v2, v3));
#pragma unroll
        for (int off = 16; off > 0; off >>= 1) mx = fmaxf(mx, __shfl_xor_sync(0xffffffff, mx, off));
        float e0 = __expf(v0 - mx), e1 = __expf(v1 - mx), e2 = __expf(v2 - mx), e3 = __expf(v3 - mx);
        float su = (e0 + e1) + (e2 + e3);
#pragma unroll
        for (int off = 16; off > 0; off >>= 1) su += __shfl_xor_sync(0xffffffff, su, off);
        float inv = 1.0f / su;
        Pu[i*132 + lane]      = f2tf32(e0 * inv);
        Pu[i*132 + lane + 32] = f2tf32(e1 * inv);
        Pu[i*132 + lane + 64] = f2tf32(e2 * inv);
        Pu[i*132 + lane + 96] = f2tf32(e3 * inv);
    }
    __syncthreads();

    // ---- out = P @ V (warp: 16 rows x 32 d, side-split) ----
    float c2[4][4];
#pragma unroll
    for (int nt = 0; nt < 4; nt++) { c2[nt][0]=0.f; c2[nt][1]=0.f; c2[nt][2]=0.f; c2[nt][3]=0.f; }
#pragma unroll
    for (int ks = 0; ks < 16; ks++) {
        unsigned a0 = Pu[mrow*132 + ks*8 + kc];
        unsigned a1 = Pu[(mrow+8)*132 + ks*8 + kc];
        unsigned a2 = Pu[mrow*132 + ks*8 + kc + 4];
        unsigned a3 = Pu[(mrow+8)*132 + ks*8 + kc + 4];
#pragma unroll
        for (int nt = 0; nt < 4; nt++) {
            int dcol = side*32 + nt*8 + qr;
            unsigned b0 = Vt[dcol*129 + ks*8 + kc];
            unsigned b1 = Vt[dcol*129 + ks*8 + kc + 4];
            MMA_TF32(c2[nt][0],c2[nt][1],c2[nt][2],c2[nt][3], a0,a1,a2,a3, b0,b1);
        }
    }
#pragma unroll
    for (int nt = 0; nt < 4; nt++) {
        int d = side*32 + nt*8 + 2*kc;
        float2 o0; o0.x = c2[nt][0]; o0.y = c2[nt][1];
        float2 o1; o1.x = c2[nt][2]; o1.y = c2[nt][3];
        *(float2*)(g_ALN + ((size_t)(b*Tt + mrow)*Nn + n)*Dd + d)     = o0;
        *(float2*)(g_ALN + ((size_t)(b*Tt + mrow + 8)*Nn + n)*Dd + d) = o1;
    }
}

// ---------------- GCN + residual + LN1, tf32 tensor core (unchanged) ----------------
__global__ void __launch_bounds__(256, 2) k_gcn(const float* __restrict__ Wg,
                                                const float* __restrict__ bg,
                                                const float* __restrict__ ln1g,
                                                const float* __restrict__ ln1b) {
    extern __shared__ float sg[];
    unsigned* As  = (unsigned*)sg;
    unsigned* Bs  = As + 8704;
    unsigned* Tmp = As + 12864;
    unsigned* Wgs = As + 21568;
    float* h2 = sg;   // overlays As

    int tid = threadIdx.x;
    int blk = blockIdx.x;
    int bt = blk >> 1, half = blk & 1;
    int m0g = half * 128;
    int b = bt >> 7, t = bt & 127;
    const float* Xbt = g_ALN + (size_t)bt * 16384;

    int w = tid >> 5, lane = tid & 31;
    int qr = lane >> 2, kc = lane & 3;
    int mrow = w*16 + qr;

    for (int idx = tid; idx < 1024; idx += 256) {
        int r = idx >> 4, c4 = idx & 15;
        float4 wv = *(const float4*)(Wg + (size_t)r*64 + c4*4);
        uint4 pv; pv.x = f2tf32(wv.x); pv.y = f2tf32(wv.y);
        pv.z = f2tf32(wv.z); pv.w = f2tf32(wv.w);
        *(uint4*)(Wgs + r*68 + c4*4) = pv;
    }

    float c1[8][4];
#pragma unroll
    for (int nt = 0; nt < 8; nt++) { c1[nt][0]=0.f; c1[nt][1]=0.f; c1[nt][2]=0.f; c1[nt][3]=0.f; }

    for (int ch = 0; ch < 4; ch++) {
        __syncthreads();
        for (int idx = tid; idx < 2048; idx += 256) {
            int r = idx >> 4, c4 = idx & 15;
            *(uint4*)(As + r*68 + c4*4) =
                *(const uint4*)(g_ADPu + (size_t)(m0g + r)*256 + ch*64 + c4*4);
        }
        for (int idx = tid; idx < 1024; idx += 256) {
            int nn = idx >> 4, c4 = idx & 15;
            float4 xv = *(const float4*)(Xbt + (size_t)(ch*64 + nn)*64 + c4*4);
            Bs[(c4*4+0)*65 + nn] = f2tf32(xv.x);
            Bs[(c4*4+1)*65 + nn] = f2tf32(xv.y);
            Bs[(c4*4+2)*65 + nn] = f2tf32(xv.z);
            Bs[(c4*4+3)*65 + nn] = f2tf32(xv.w);
        }
        __syncthreads();
#pragma unroll
        for (int ks = 0; ks < 8; ks++) {
            unsigned a0 = As[mrow*68 + ks*8 + kc];
            unsigned a1 = As[(mrow+8)*68 + ks*8 + kc];
            unsigned a2 = As[mrow*68 + ks*8 + kc + 4];
            unsigned a3 = As[(mrow+8)*68 + ks*8 + kc + 4];
#pragma unroll
            for (int nt = 0; nt < 8; nt++) {
                unsigned b0 = Bs[(nt*8+qr)*65 + ks*8 + kc];
                unsigned b1 = Bs[(nt*8+qr)*65 + ks*8 + kc + 4];
                MMA_TF32(c1[nt][0],c1[nt][1],c1[nt][2],c1[nt][3], a0,a1,a2,a3, b0,b1);
            }
        }
    }

#pragma unroll
    for (int nt = 0; nt < 8; nt++) {
        int d0 = nt*8 + 2*kc;
        Tmp[mrow*68 + d0]       = f2tf32(c1[nt][0]);
        Tmp[mrow*68 + d0 + 1]   = f2tf32(c1[nt][1]);
        Tmp[(mrow+8)*68 + d0]     = f2tf32(c1[nt][2]);
        Tmp[(mrow+8)*68 + d0 + 1] = f2tf32(c1[nt][3]);
    }
    __syncwarp();

    float c2[8][4];
#pragma unroll
    for (int nt = 0; nt < 8; nt++) { c2[nt][0]=0.f; c2[nt][1]=0.f; c2[nt][2]=0.f; c2[nt][3]=0.f; }
#pragma unroll
    for (int ks = 0; ks < 8; ks++) {
        unsigned a0 = Tmp[mrow*68 + ks*8 + kc];
        unsigned a1 = Tmp[(mrow+8)*68 + ks*8 + kc];
        unsigned a2 = Tmp[mrow*68 + ks*8 + kc + 4];
        unsigned a3 = Tmp[(mrow+8)*68 + ks*8 + kc + 4];
#pragma unroll
        for (int nt = 0; nt < 8; nt++) {
            unsigned b0 = Wgs[(nt*8+qr)*68 + ks*8 + kc];
            unsigned b1 = Wgs[(nt*8+qr)*68 + ks*8 + kc + 4];
            MMA_TF32(c2[nt][0],c2[nt][1],c2[nt][2],c2[nt][3], a0,a1,a2,a3, b0,b1);
        }
    }
    __syncthreads();

#pragma unroll
    for (int nt = 0; nt < 8; nt++) {
        int e0 = nt*8 + 2*kc;
        float bx = bg[e0], by = bg[e0+1];
        h2[mrow*68 + e0]       = fmaxf(c2[nt][0] + bx, 0.f);
        h2[mrow*68 + e0 + 1]   = fmaxf(c2[nt][1] + by, 0.f);
        h2[(mrow+8)*68 + e0]     = fmaxf(c2[nt][2] + bx, 0.f);
        h2[(mrow+8)*68 + e0 + 1] = fmaxf(c2[nt][3] + by, 0.f);
    }
    __syncthreads();

    float gg0 = ln1g[lane], gg1 = ln1g[lane+32];
    float bb0 = ln1b[lane], bb1 = ln1b[lane+32];
    for (int mm = 0; mm < 16; mm++) {
        int m = w*16 + mm;
        const float* xr = Xbt + (size_t)(m0g + m)*64;
        float u0 = xr[lane]      + h2[m*68 + lane];
        float u1 = xr[lane + 32] + h2[m*68 + lane + 32];
        float su = u0 + u1;
#pragma unroll
        for (int off = 16; off > 0; off >>= 1) su += __shfl_xor_sync(0xffffffff, su, off);
        float mean = su * (1.0f/64.0f);
        float dd0 = u0 - mean, dd1 = u1 - mean;
        float q = dd0*dd0 + dd1*dd1;
#pragma unroll
        for (int off = 16; off > 0; off >>= 1) q += __shfl_xor_sync(0xffffffff, q, off);
        float rs = rsqrtf(q*(1.0f/64.0f) + 1e-5f);
        size_t o = ((size_t)(b*Nn + m0g + m)*Tt + t)*Dd;
        g_X1[o + lane]      = dd0*rs*gg0 + bb0;
        g_X1[o + lane + 32] = dd1*rs*gg1 + bb1;
    }
}

// ---------------- tensor-core GRU (unchanged from R10) ----------------
__global__ void __launch_bounds__(256) k_gru_tc(const float* __restrict__ Whh,
                                                const float* __restrict__ bhh,
                                                const float* __restrict__ Wih,
                                                const float* __restrict__ bih,
                                                const float* __restrict__ ln2g,
                                                const float* __restrict__ ln2b,
                                                float* __restrict__ out) {
    extern __shared__ unsigned su_[];
    unsigned* Whs = su_;
    unsigned* Wis = su_ + 13056;
    unsigned* X1s = su_;
    float*    X1f = (float*)(su_ + 4352);
    unsigned* Hb0 = su_ + 8704;
    unsigned* Hb1 = su_ + 9792;
    float*    U4  = (float*)(su_ + 10880);

    int tid = threadIdx.x;
    int w = tid >> 5, lane = tid & 31;
    int qr = lane >> 2, kc = lane & 3;
    int s_base = blockIdx.x * 16;
    int b = s_base >> 8;
    int node0 = s_base & 255;

    for (int idx = tid; idx < 3072; idx += 256) {
        int r = idx >> 4, c4 = idx & 15;
        float4 wv = *(const float4*)(Whh + (size_t)r*64 + c4*4);
        uint4 pv; pv.x = f2tf32(wv.x); pv.y = f2tf32(wv.y);
        pv.z = f2tf32(wv.z); pv.w = f2tf32(wv.w);
        *(uint4*)(Whs + r*68 + c4*4) = pv;
        float4 iv = *(const float4*)(Wih + (size_t)r*64 + c4*4);
        uint4 qv; qv.x = f2tf32(iv.x); qv.y = f2tf32(iv.y);
        qv.z = f2tf32(iv.z); qv.w = f2tf32(iv.w);
        *(uint4*)(Wis + r*68 + c4*4) = qv;
    }
    __syncthreads();

    unsigned br_[8][2], bz_[8][2], bn_[8][2];
    unsigned wr_[8][2], wz_[8][2], wn_[8][2];
#pragma unroll
    for (int ks = 0; ks < 8; ks++) {
        int nr = (0*64 + w*8 + qr)*68 + ks*8 + kc;
        int nz = (1*64 + w*8 + qr)*68 + ks*8 + kc;
        int nn = (2*64 + w*8 + qr)*68 + ks*8 + kc;
        br_[ks][0] = Whs[nr]; br_[ks][1] = Whs[nr + 4];
        bz_[ks][0] = Whs[nz]; bz_[ks][1] = Whs[nz + 4];
        bn_[ks][0] = Whs[nn]; bn_[ks][1] = Whs[nn + 4];
        wr_[ks][0] = Wis[nr]; wr_[ks][1] = Wis[nr + 4];
        wz_[ks][0] = Wis[nz]; wz_[ks][1] = Wis[nz + 4];
        wn_[ks][0] = Wis[nn]; wn_[ks][1] = Wis[nn + 4];
    }
    __syncthreads();

    for (int idx = tid; idx < 1088; idx += 256) Hb0[idx] = 0;

    int col0 = w*8 + 2*kc;
    float2 bhr = *(const float2*)(bhh + col0);
    float2 bhz = *(const float2*)(bhh + 64 + col0);
    float2 bhn = *(const float2*)(bhh + 128 + col0);
    float2 bir = *(const float2*)(bih + col0);
    float2 biz = *(const float2*)(bih + 64 + col0);
    float2 bin_ = *(const float2*)(bih + 128 + col0);
    float g2a = ln2g[lane], g2b = ln2g[lane+32];
    float b2a = ln2b[lane], b2b = ln2b[lane+32];

    float h_old[4] = {0.f, 0.f, 0.f, 0.f};

    for (int tc = 0; tc < Tt; tc += 4) {
        __syncthreads();

        for (int idx = tid; idx < 4096; idx += 256) {
            int s = idx >> 10, rem = idx & 1023, row = rem >> 6, col = rem & 63;
            float v = g_X1[(size_t)(s_base + row)*Tt*Dd + (size_t)(tc + s)*Dd + col];
            X1s[s*1088 + row*68 + col] = f2tf32(v);
            X1f[s*1088 + row*68 + col] = v;
        }
        __syncthreads();

        float gr_[4][4], gz_[4][4], gn_[4][4];
#pragma unroll
        for (int s = 0; s < 4; s++) {
            const unsigned* Xc = X1s + s*1088;
            unsigned ax[8][4];
#pragma unroll
            for (int ks = 0; ks < 8; ks++) {
                ax[ks][0] = Xc[qr*68 + ks*8 + kc];
                ax[ks][1] = Xc[(qr+8)*68 + ks*8 + kc];
                ax[ks][2] = Xc[qr*68 + ks*8 + kc + 4];
                ax[ks][3] = Xc[(qr+8)*68 + ks*8 + kc + 4];
            }
            gr_[s][0]=0.f; gr_[s][1]=0.f; gr_[s][2]=0.f; gr_[s][3]=0.f;
            gz_[s][0]=0.f; gz_[s][1]=0.f; gz_[s][2]=0.f; gz_[s][3]=0.f;
            gn_[s][0]=0.f; gn_[s][1]=0.f; gn_[s][2]=0.f; gn_[s][3]=0.f;
#pragma unroll
            for (int ks = 0; ks < 8; ks++) {
                MMA_TF32(gr_[s][0],gr_[s][1],gr_[s][2],gr_[s][3], ax[ks][0],ax[ks][1],ax[ks][2],ax[ks][3], wr_[ks][0],wr_[ks][1]);
                MMA_TF32(gz_[s][0],gz_[s][1],gz_[s][2],gz_[s][3], ax[ks][0],ax[ks][1],ax[ks][2],ax[ks][3], wz_[ks][0],wz_[ks][1]);
                MMA_TF32(gn_[s][0],gn_[s][1],gn_[s][2],gn_[s][3], ax[ks][0],ax[ks][1],ax[ks][2],ax[ks][3], wn_[ks][0],wn_[ks][1]);
            }
        }

#pragma unroll
        for (int s = 0; s < 4; s++) {
            int t = tc + s;
            unsigned* Hc = (t & 1) ? Hb1 : Hb0;
            unsigned* Hn = (t & 1) ? Hb0 : Hb1;
            float* Us = U4 + s*1088;
            const float* Xf = X1f + s*1088;

            float2 xa = *(const float2*)(Xf + qr*68 + col0);
            float2 xb = *(const float2*)(Xf + (qr+8)*68 + col0);

            float cr[4] = {0.f,0.f,0.f,0.f}, cz[4] = {0.f,0.f,0.f,0.f}, cn[4] = {0.f,0.f,0.f,0.f};
            {
                unsigned a[8][4];
#pragma unroll
                for (int ks = 0; ks < 8; ks++) {
                    a[ks][0] = Hc[qr*68 + ks*8 + kc];
                    a[ks][1] = Hc[(qr+8)*68 + ks*8 + kc];
                    a[ks][2] = Hc[qr*68 + ks*8 + kc + 4];
                    a[ks][3] = Hc[(qr+8)*68 + ks*8 + kc + 4];
                }
#pragma unroll
                for (int ks = 0; ks < 8; ks++) {
                    MMA_TF32(cr[0],cr[1],cr[2],cr[3], a[ks][0],a[ks][1],a[ks][2],a[ks][3], br_[ks][0],br_[ks][1]);
                    MMA_TF32(cz[0],cz[1],cz[2],cz[3], a[ks][0],a[ks][1],a[ks][2],a[ks][3], bz_[ks][0],bz_[ks][1]);
                    MMA_TF32(cn[0],cn[1],cn[2],cn[3], a[ks][0],a[ks][1],a[ks][2],a[ks][3], bn_[ks][0],bn_[ks][1]);
                }
            }

            float r0 = siga(gr_[s][0] + bir.x + cr[0] + bhr.x);
            float r1 = siga(gr_[s][1] + bir.y + cr[1] + bhr.y);
            float r2 = siga(gr_[s][2] + bir.x + cr[2] + bhr.x);
            float r3 = siga(gr_[s][3] + bir.y + cr[3] + bhr.y);
            float z0 = siga(gz_[s][0] + biz.x + cz[0] + bhz.x);
            float z1 = siga(gz_[s][1] + biz.y + cz[1] + bhz.y);
            float z2 = siga(gz_[s][2] + biz.x + cz[2] + bhz.x);
            float z3 = siga(gz_[s][3] + biz.y + cz[3] + bhz.y);
            float n0 = tanha(gn_[s][0] + bin_.x + r0*(cn[0] + bhn.x));
            float n1 = tanha(gn_[s][1] + bin_.y + r1*(cn[1] + bhn.y));
            float n2 = tanha(gn_[s][2] + bin_.x + r2*(cn[2] + bhn.x));
            float n3 = tanha(gn_[s][3] + bin_.y + r3*(cn[3] + bhn.y));
            float h0 = (1.f - z0)*n0 + z0*h_old[0];
            float h1 = (1.f - z1)*n1 + z1*h_old[1];
            float h2v = (1.f - z2)*n2 + z2*h_old[2];
            float h3 = (1.f - z3)*n3 + z3*h_old[3];
            h_old[0] = h0; h_old[1] = h1; h_old[2] = h2v; h_old[3] = h3;

            uint2 hp0; hp0.x = f2tf32(h0); hp0.y = f2tf32(h1);
            uint2 hp1; hp1.x = f2tf32(h2v); hp1.y = f2tf32(h3);
            *(uint2*)(Hn + qr*68 + col0)     = hp0;
            *(uint2*)(Hn + (qr+8)*68 + col0) = hp1;
            float2 up0; up0.x = xa.x + h0; up0.y = xa.y + h1;
            float2 up1; up1.x = xb.x + h2v; up1.y = xb.y + h3;
            *(float2*)(Us + qr*68 + col0)     = up0;
            *(float2*)(Us + (qr+8)*68 + col0) = up1;
            __syncthreads();
        }

#pragma unroll
        for (int rr = 0; rr < 8; rr++) {
            int inst = w*8 + rr;
            int s = inst >> 4, row = inst & 15;
            const float* Us = U4 + s*1088;
            const float* Xf = X1f + s*1088;
            float v0 = Us[row*68 + lane], v1 = Us[row*68 + lane + 32];
            float sv = v0 + v1, qv = v0*v0 + v1*v1;
#pragma unroll
            for (int off = 16; off > 0; off >>= 1) {
                sv += __shfl_xor_sync(0xffffffff, sv, off);
                qv += __shfl_xor_sync(0xffffffff, qv, off);
            }
            float mean = sv * (1.0f/64.0f);
            float var = qv*(1.0f/64.0f) - mean*mean;
            float rs = rsqrtf(var + 1e-5f);
            float x0v = Xf[row*68 + lane], x1v = Xf[row*68 + lane + 32];
            size_t oo = (size_t)b*Tt*Nn*Dd + (size_t)(tc + s)*Nn*Dd + (size_t)(node0 + row)*Dd;
            out[oo + lane]      = x0v + (v0 - mean)*rs*g2a + b2a;
            out[oo + lane + 32] = x1v + (v1 - mean)*rs*g2b + b2b;
        }
    }
}

// ---------------- launcher ----------------
extern "C" void kernel_launch(void* const* d_in, const int* in_sizes, int n_in,
                              void* d_out, int out_size) {
    (void)in_sizes; (void)n_in; (void)out_size;
    const float* H_i  = (const float*)d_in[0];
    const float* H_j  = (const float*)d_in[1];
    const float* Wq   = (const float*)d_in[2];
    const float* bq   = (const float*)d_in[3];
    const float* Wk   = (const float*)d_in[4];
    const float* bk   = (const float*)d_in[5];
    const float* Wv   = (const float*)d_in[6];
    const float* bv   = (const float*)d_in[7];
    const float* lgam = (const float*)d_in[8];
    const float* ltau = (const float*)d_in[9];
    const float* e1   = (const float*)d_in[10];
    const float* e2   = (const float*)d_in[11];
    const float* Wg   = (const float*)d_in[12];
    const float* bg   = (const float*)d_in[13];
    const float* ln1g = (const float*)d_in[14];
    const float* ln1b = (const float*)d_in[15];
    const float* Wih  = (const float*)d_in[16];
    const float* Whh  = (const float*)d_in[17];
    const float* bih  = (const float*)d_in[18];
    const float* bhh  = (const float*)d_in[19];
    const float* ln2g = (const float*)d_in[20];
    const float* ln2b = (const float*)d_in[21];
    float* out = (float*)d_out;

    const int ATTN_SMEM = 42688 * 4;   // 170752 B
    const int GCN_SMEM  = 25920 * 4;   // 103680 B
    const int GRU_SMEM  = 26112 * 4;   // 104448 B
    cudaFuncSetAttribute(k_attn, cudaFuncAttributeMaxDynamicSharedMemorySize, ATTN_SMEM);
    cudaFuncSetAttribute(k_gcn,  cudaFuncAttributeMaxDynamicSharedMemorySize, GCN_SMEM);
    cudaFuncSetAttribute(k_gru_tc, cudaFuncAttributeMaxDynamicSharedMemorySize, GRU_SMEM);

    k_adj<<<256, 256>>>(e1, e2);
    k_attn<<<Bb*Nn, 512, ATTN_SMEM>>>(H_i, H_j, Wq, bq, Wk, bk, Wv, bv, lgam, ltau);
    k_gcn<<<Bb*Tt*2, 256, GCN_SMEM>>>(Wg, bg, ln1g, ln1b);
    k_gru_tc<<<Bb*Nn/16, 256, GRU_SMEM>>>(Whh, bhh, Wih, bih, ln2g, ln2b, out);
}

// round 12
// speedup vs baseline: 1.1799x; 1.0420x over previous
#include <cuda_runtime.h>
#include <math.h>

#define Bb 8
#define Tt 128
#define Nn 256
#define Dd 64
#define D3 192
#define BTND 16777216   // 8*128*256*64

// ---------------- device scratch ----------------
__device__ float g_ALN[BTND];          // aligner output, [B,T,N,D]
__device__ float g_X1[BTND];           // post-ln1, [B,N,T,D]
__device__ unsigned g_ADPu[Nn*Nn];     // adjacency, tf32 bits, row-major [m][n]

__device__ __forceinline__ unsigned f2tf32(float f) {
    unsigned u;
    asm("cvt.rna.tf32.f32 %0, %1;" : "=r"(u) : "f"(f));
    return u;
}
__device__ __forceinline__ float tanha(float x) {
    float y;
    asm("tanh.approx.f32 %0, %1;" : "=f"(y) : "f"(x));
    return y;
}
__device__ __forceinline__ float siga(float x) { return 0.5f*tanha(0.5f*x) + 0.5f; }

#define MMA_TF32(c0,c1,c2,c3,a0,a1,a2,a3,b0,b1) \
    asm volatile("mma.sync.aligned.m16n8k8.row.col.f32.tf32.tf32.f32 " \
        "{%0,%1,%2,%3}, {%4,%5,%6,%7}, {%8,%9}, {%0,%1,%2,%3};" \
        : "+f"(c0), "+f"(c1), "+f"(c2), "+f"(c3) \
        : "r"(a0), "r"(a1), "r"(a2), "r"(a3), "r"(b0), "r"(b1))

// ---------------- adjacency ----------------
__global__ void k_adj(const float* __restrict__ e1, const float* __restrict__ e2) {
    int m = blockIdx.x;
    int n = threadIdx.x;            // 256 threads
    float a = 0.f;
#pragma unroll
    for (int k = 0; k < 32; k++) a = fmaf(e1[m*32 + k], e2[k*256 + n], a);
    a = fmaxf(a, 0.f);
    __shared__ float red[256];
    red[n] = a; __syncthreads();
    for (int s = 128; s > 0; s >>= 1) { if (n < s) red[n] = fmaxf(red[n], red[n+s]); __syncthreads(); }
    float mx = red[0]; __syncthreads();
    float e = expf(a - mx);
    red[n] = e; __syncthreads();
    for (int s = 128; s > 0; s >>= 1) { if (n < s) red[n] += red[n+s]; __syncthreads(); }
    g_ADPu[m*256 + n] = f2tf32(e / red[0]);
}

// col-split projection gemm: warp computes rows [mrow,mrow+8], cols colbase..colbase+31
__device__ __forceinline__ void gemm_c4(const unsigned* __restrict__ As,
                                        const unsigned* __restrict__ Bs,
                                        int mrow, int qr, int kc, int colbase,
                                        float c[4][4]) {
    unsigned a[8][4];
#pragma unroll
    for (int ks = 0; ks < 8; ks++) {
        a[ks][0] = As[mrow*68 + ks*8 + kc];
        a[ks][1] = As[(mrow+8)*68 + ks*8 + kc];
        a[ks][2] = As[mrow*68 + ks*8 + kc + 4];
        a[ks][3] = As[(mrow+8)*68 + ks*8 + kc + 4];
    }
#pragma unroll
    for (int nt = 0; nt < 4; nt++) {
        c[nt][0]=0.f; c[nt][1]=0.f; c[nt][2]=0.f; c[nt][3]=0.f;
        int ncol = colbase + nt*8 + qr;
#pragma unroll
        for (int ks = 0; ks < 8; ks++) {
            unsigned b0 = Bs[ncol*68 + ks*8 + kc];
            unsigned b1 = Bs[ncol*68 + ks*8 + kc + 4];
            MMA_TF32(c[nt][0],c[nt][1],c[nt][2],c[nt][3],
                     a[ks][0],a[ks][1],a[ks][2],a[ks][3], b0,b1);
        }
    }
}

// ---------------- fused QKV + temporal attention, 512 threads ----------------
__global__ void __launch_bounds__(512, 1) k_attn(
        const float* __restrict__ Hi, const float* __restrict__ Hj,
        const float* __restrict__ Wq, const float* __restrict__ bq,
        const float* __restrict__ Wk, const float* __restrict__ bk,
        const float* __restrict__ Wv, const float* __restrict__ bv,
        const float* __restrict__ lg, const float* __restrict__ lt) {
    extern __shared__ float sm[];
    unsigned* Hs = (unsigned*)sm;
    unsigned* Ws = Hs + 8704;
    float*    Ps = sm;
    unsigned* Pu = (unsigned*)sm;
    unsigned* Qs = Hs + 16896;
    unsigned* Ks = Hs + 25600;
    unsigned* Vt = Hs + 34304;
    float* biasr = sm + 42560;

    int tid = threadIdx.x;
    int bn = blockIdx.x;
    int b = bn >> 8, n = bn & 255;

    float gamma = fmaxf(expf(*lg), 0.01f);
    float tau   = fmaxf(expf(*lt), 0.01f);
    float scale = 1.0f / (8.0f * tau);
    if (tid < 128) biasr[tid] = logf(expf(-gamma * (float)tid * (1.0f/127.0f)) + 1e-8f);

    int w = tid >> 5, lane = tid & 31;
    int qr = lane >> 2, kc = lane & 3;
    int wp = w >> 1, side = w & 1;
    int mrow = wp*16 + qr;

    for (int idx = tid; idx < 2048; idx += 512) {
        int i = idx >> 4, c4 = idx & 15;
        float4 hv = *(const float4*)(Hj + ((size_t)(b*Tt + i)*Nn + n)*Dd + c4*4);
        uint4 pv; pv.x=f2tf32(hv.x); pv.y=f2tf32(hv.y); pv.z=f2tf32(hv.z); pv.w=f2tf32(hv.w);
        *(uint4*)(Hs + i*68 + c4*4) = pv;
    }
    for (int idx = tid; idx < 1024; idx += 512) {
        int r = idx >> 4, c4 = idx & 15;
        float4 wv = *(const float4*)(Wk + (size_t)r*64 + c4*4);
        uint4 pv; pv.x=f2tf32(wv.x); pv.y=f2tf32(wv.y); pv.z=f2tf32(wv.z); pv.w=f2tf32(wv.w);
        *(uint4*)(Ws + r*68 + c4*4) = pv;
    }
    __syncthreads();

    {
        float c[4][4];
        gemm_c4(Hs, Ws, mrow, qr, kc, side*32, c);
#pragma unroll
        for (int nt = 0; nt < 4; nt++) {
            int d = side*32 + nt*8 + 2*kc;
            float bx = bk[d], by = bk[d+1];
            Ks[mrow*68 + d]       = f2tf32(c[nt][0] + bx);
            Ks[mrow*68 + d + 1]   = f2tf32(c[nt][1] + by);
            Ks[(mrow+8)*68 + d]     = f2tf32(c[nt][2] + bx);
            Ks[(mrow+8)*68 + d + 1] = f2tf32(c[nt][3] + by);
        }
    }
    __syncthreads();
    for (int idx = tid; idx < 1024; idx += 512) {
        int r = idx >> 4, c4 = idx & 15;
        float4 wv = *(const float4*)(Wv + (size_t)r*64 + c4*4);
        uint4 pv; pv.x=f2tf32(wv.x); pv.y=f2tf32(wv.y); pv.z=f2tf32(wv.z); pv.w=f2tf32(wv.w);
        *(uint4*)(Ws + r*68 + c4*4) = pv;
    }
    __syncthreads();
    {
        float c[4][4];
        gemm_c4(Hs, Ws, mrow, qr, kc, side*32, c);
#pragma unroll
        for (int nt = 0; nt < 4; nt++) {
            int d = side*32 + nt*8 + 2*kc;
            float bx = bv[d], by = bv[d+1];
            Vt[d*129 + mrow]         = f2tf32(c[nt][0] + bx);
            Vt[(d+1)*129 + mrow]     = f2tf32(c[nt][1] + by);
            Vt[d*129 + mrow + 8]     = f2tf32(c[nt][2] + bx);
            Vt[(d+1)*129 + mrow + 8] = f2tf32(c[nt][3] + by);
        }
    }
    __syncthreads();
    for (int idx = tid; idx < 2048; idx += 512) {
        int i = idx >> 4, c4 = idx & 15;
        float4 hv = *(const float4*)(Hi + ((size_t)(b*Tt + i)*Nn + n)*Dd + c4*4);
        uint4 pv; pv.x=f2tf32(hv.x); pv.y=f2tf32(hv.y); pv.z=f2tf32(hv.z); pv.w=f2tf32(hv.w);
        *(uint4*)(Hs + i*68 + c4*4) = pv;
    }
    for (int idx = tid; idx < 1024; idx += 512) {
        int r = idx >> 4, c4 = idx & 15;
        float4 wv = *(const float4*)(Wq + (size_t)r*64 + c4*4);
        uint4 pv; pv.x=f2tf32(wv.x); pv.y=f2tf32(wv.y); pv.z=f2tf32(wv.z); pv.w=f2tf32(wv.w);
        *(uint4*)(Ws + r*68 + c4*4) = pv;
    }
    __syncthreads();
    {
        float c[4][4];
        gemm_c4(Hs, Ws, mrow, qr, kc, side*32, c);
#pragma unroll
        for (int nt = 0; nt < 4; nt++) {
            int d = side*32 + nt*8 + 2*kc;
            float bx = bq[d], by = bq[d+1];
            Qs[mrow*68 + d]       = f2tf32(c[nt][0] + bx);
            Qs[mrow*68 + d + 1]   = f2tf32(c[nt][1] + by);
            Qs[(mrow+8)*68 + d]     = f2tf32(c[nt][2] + bx);
            Qs[(mrow+8)*68 + d + 1] = f2tf32(c[nt][3] + by);
        }
    }
    __syncthreads();

    // ---- S = Q K^T ----
    unsigned a[8][4];
#pragma unroll
    for (int ks = 0; ks < 8; ks++) {
        a[ks][0] = Qs[mrow*68 + ks*8 + kc];
        a[ks][1] = Qs[(mrow+8)*68 + ks*8 + kc];
        a[ks][2] = Qs[mrow*68 + ks*8 + kc + 4];
        a[ks][3] = Qs[(mrow+8)*68 + ks*8 + kc + 4];
    }
    float c[8][4];
#pragma unroll
    for (int nt = 0; nt < 8; nt++) { c[nt][0]=0.f; c[nt][1]=0.f; c[nt][2]=0.f; c[nt][3]=0.f; }
#pragma unroll
    for (int nt = 0; nt < 8; nt++) {
        int ncol = side*64 + nt*8 + qr;
#pragma unroll
        for (int ks = 0; ks < 8; ks++) {
            unsigned b0 = Ks[ncol*68 + ks*8 + kc];
            unsigned b1 = Ks[ncol*68 + ks*8 + kc + 4];
            MMA_TF32(c[nt][0],c[nt][1],c[nt][2],c[nt][3],
                     a[ks][0],a[ks][1],a[ks][2],a[ks][3], b0,b1);
        }
    }
    __syncthreads();

    int i1 = mrow, i2 = mrow + 8;
#pragma unroll
    for (int nt = 0; nt < 8; nt++) {
        int j0 = side*64 + nt*8 + 2*kc;
        int d10 = i1 - j0;     d10 = d10 < 0 ? -d10 : d10;
        int d11 = i1 - j0 - 1; d11 = d11 < 0 ? -d11 : d11;
        int d20 = i2 - j0;     d20 = d20 < 0 ? -d20 : d20;
        int d21 = i2 - j0 - 1; d21 = d21 < 0 ? -d21 : d21;
        Ps[i1*132 + j0]     = c[nt][0]*scale + biasr[d10];
        Ps[i1*132 + j0 + 1] = c[nt][1]*scale + biasr[d11];
        Ps[i2*132 + j0]     = c[nt][2]*scale + biasr[d20];
        Ps[i2*132 + j0 + 1] = c[nt][3]*scale + biasr[d21];
    }
    __syncthreads();

    for (int rr = 0; rr < 8; rr++) {
        int i = w*8 + rr;
        float v0 = Ps[i*132 + lane], v1 = Ps[i*132 + lane + 32],
              v2 = Ps[i*132 + lane + 64], v3 = Ps[i*132 + lane + 96];
        float mx = fmaxf(fmaxf(v0, v1), fmaxf(v2, v3));
#pragma unroll
        for (int off = 16; off > 0; off >>= 1) mx = fmaxf(mx, __shfl_xor_sync(0xffffffff, mx, off));
        float e0 = __expf(v0 - mx), e1 = __expf(v1 - mx), e2 = __expf(v2 - mx), e3 = __expf(v3 - mx);
        float su = (e0 + e1) + (e2 + e3);
#pragma unroll
        for (int off = 16; off > 0; off >>= 1) su += __shfl_xor_sync(0xffffffff, su, off);
        float inv = 1.0f / su;
        Pu[i*132 + lane]      = f2tf32(e0 * inv);
        Pu[i*132 + lane + 32] = f2tf32(e1 * inv);
        Pu[i*132 + lane + 64] = f2tf32(e2 * inv);
        Pu[i*132 + lane + 96] = f2tf32(e3 * inv);
    }
    __syncthreads();

    float c2[4][4];
#pragma unroll
    for (int nt = 0; nt < 4; nt++) { c2[nt][0]=0.f; c2[nt][1]=0.f; c2[nt][2]=0.f; c2[nt][3]=0.f; }
#pragma unroll
    for (int ks = 0; ks < 16; ks++) {
        unsigned a0 = Pu[mrow*132 + ks*8 + kc];
        unsigned a1 = Pu[(mrow+8)*132 + ks*8 + kc];
        unsigned a2 = Pu[mrow*132 + ks*8 + kc + 4];
        unsigned a3 = Pu[(mrow+8)*132 + ks*8 + kc + 4];
#pragma unroll
        for (int nt = 0; nt < 4; nt++) {
            int dcol = side*32 + nt*8 + qr;
            unsigned b0 = Vt[dcol*129 + ks*8 + kc];
            unsigned b1 = Vt[dcol*129 + ks*8 + kc + 4];
            MMA_TF32(c2[nt][0],c2[nt][1],c2[nt][2],c2[nt][3], a0,a1,a2,a3, b0,b1);
        }
    }
#pragma unroll
    for (int nt = 0; nt < 4; nt++) {
        int d = side*32 + nt*8 + 2*kc;
        float2 o0; o0.x = c2[nt][0]; o0.y = c2[nt][1];
        float2 o1; o1.x = c2[nt][2]; o1.y = c2[nt][3];
        *(float2*)(g_ALN + ((size_t)(b*Tt + mrow)*Nn + n)*Dd + d)     = o0;
        *(float2*)(g_ALN + ((size_t)(b*Tt + mrow + 8)*Nn + n)*Dd + d) = o1;
    }
}

// ---------------- GCN + residual + LN1, 512 threads, col-split warps ----------------
__global__ void __launch_bounds__(512, 2) k_gcn(const float* __restrict__ Wg,
                                                const float* __restrict__ bg,
                                                const float* __restrict__ ln1g,
                                                const float* __restrict__ ln1b) {
    extern __shared__ float sg[];
    unsigned* As  = (unsigned*)sg;
    unsigned* Bs  = As + 8704;
    unsigned* Tmp = As + 12864;
    unsigned* Wgs = As + 21568;
    float* h2 = sg;   // overlays As

    int tid = threadIdx.x;
    int blk = blockIdx.x;
    int bt = blk >> 1, half = blk & 1;
    int m0g = half * 128;
    int b = bt >> 7, t = bt & 127;
    const float* Xbt = g_ALN + (size_t)bt * 16384;

    int w = tid >> 5, lane = tid & 31;
    int qr = lane >> 2, kc = lane & 3;
    int wp = w >> 1, side = w & 1;
    int mrow = wp*16 + qr;

    for (int idx = tid; idx < 1024; idx += 512) {
        int r = idx >> 4, c4 = idx & 15;
        float4 wv = *(const float4*)(Wg + (size_t)r*64 + c4*4);
        uint4 pv; pv.x = f2tf32(wv.x); pv.y = f2tf32(wv.y);
        pv.z = f2tf32(wv.z); pv.w = f2tf32(wv.w);
        *(uint4*)(Wgs + r*68 + c4*4) = pv;
    }

    // GEMM1: c1[4][4] = adp rows x X cols (side-split d)
    float c1[4][4];
#pragma unroll
    for (int nt = 0; nt < 4; nt++) { c1[nt][0]=0.f; c1[nt][1]=0.f; c1[nt][2]=0.f; c1[nt][3]=0.f; }

    for (int ch = 0; ch < 4; ch++) {
        __syncthreads();
        for (int idx = tid; idx < 2048; idx += 512) {
            int r = idx >> 4, c4 = idx & 15;
            *(uint4*)(As + r*68 + c4*4) =
                *(const uint4*)(g_ADPu + (size_t)(m0g + r)*256 + ch*64 + c4*4);
        }
        for (int idx = tid; idx < 1024; idx += 512) {
            int nn = idx >> 4, c4 = idx & 15;
            float4 xv = *(const float4*)(Xbt + (size_t)(ch*64 + nn)*64 + c4*4);
            Bs[(c4*4+0)*65 + nn] = f2tf32(xv.x);
            Bs[(c4*4+1)*65 + nn] = f2tf32(xv.y);
            Bs[(c4*4+2)*65 + nn] = f2tf32(xv.z);
            Bs[(c4*4+3)*65 + nn] = f2tf32(xv.w);
        }
        __syncthreads();
#pragma unroll
        for (int ks = 0; ks < 8; ks++) {
            unsigned a0 = As[mrow*68 + ks*8 + kc];
            unsigned a1 = As[(mrow+8)*68 + ks*8 + kc];
            unsigned a2 = As[mrow*68 + ks*8 + kc + 4];
            unsigned a3 = As[(mrow+8)*68 + ks*8 + kc + 4];
#pragma unroll
            for (int nt = 0; nt < 4; nt++) {
                int dcol = side*32 + nt*8 + qr;
                unsigned b0 = Bs[dcol*65 + ks*8 + kc];
                unsigned b1 = Bs[dcol*65 + ks*8 + kc + 4];
                MMA_TF32(c1[nt][0],c1[nt][1],c1[nt][2],c1[nt][3], a0,a1,a2,a3, b0,b1);
            }
        }
    }

    // write Tmp (col-split) -> need block sync before GEMM2 cross-reads
#pragma unroll
    for (int nt = 0; nt < 4; nt++) {
        int d0 = side*32 + nt*8 + 2*kc;
        Tmp[mrow*68 + d0]       = f2tf32(c1[nt][0]);
        Tmp[mrow*68 + d0 + 1]   = f2tf32(c1[nt][1]);
        Tmp[(mrow+8)*68 + d0]     = f2tf32(c1[nt][2]);
        Tmp[(mrow+8)*68 + d0 + 1] = f2tf32(c1[nt][3]);
    }
    __syncthreads();

    // GEMM2: h2 = relu(Tmp @ Wg^T + bg), side-split e
    float c2[4][4];
#pragma unroll
    for (int nt = 0; nt < 4; nt++) { c2[nt][0]=0.f; c2[nt][1]=0.f; c2[nt][2]=0.f; c2[nt][3]=0.f; }
#pragma unroll
    for (int ks = 0; ks < 8; ks++) {
        unsigned a0 = Tmp[mrow*68 + ks*8 + kc];
        unsigned a1 = Tmp[(mrow+8)*68 + ks*8 + kc];
        unsigned a2 = Tmp[mrow*68 + ks*8 + kc + 4];
        unsigned a3 = Tmp[(mrow+8)*68 + ks*8 + kc + 4];
#pragma unroll
        for (int nt = 0; nt < 4; nt++) {
            int ncol = side*32 + nt*8 + qr;
            unsigned b0 = Wgs[ncol*68 + ks*8 + kc];
            unsigned b1 = Wgs[ncol*68 + ks*8 + kc + 4];
            MMA_TF32(c2[nt][0],c2[nt][1],c2[nt][2],c2[nt][3], a0,a1,a2,a3, b0,b1);
        }
    }
    __syncthreads();   // everyone done reading As before h2 overlay

#pragma unroll
    for (int nt = 0; nt < 4; nt++) {
        int e0 = side*32 + nt*8 + 2*kc;
        float bx = bg[e0], by = bg[e0+1];
        h2[mrow*68 + e0]       = fmaxf(c2[nt][0] + bx, 0.f);
        h2[mrow*68 + e0 + 1]   = fmaxf(c2[nt][1] + by, 0.f);
        h2[(mrow+8)*68 + e0]     = fmaxf(c2[nt][2] + bx, 0.f);
        h2[(mrow+8)*68 + e0 + 1] = fmaxf(c2[nt][3] + by, 0.f);
    }
    __syncthreads();

    // residual + LN1: 16 warps x 8 rows
    float gg0 = ln1g[lane], gg1 = ln1g[lane+32];
    float bb0 = ln1b[lane], bb1 = ln1b[lane+32];
    for (int mm = 0; mm < 8; mm++) {
        int m = w*8 + mm;
        const float* xr = Xbt + (size_t)(m0g + m)*64;
        float u0 = xr[lane]      + h2[m*68 + lane];
        float u1 = xr[lane + 32] + h2[m*68 + lane + 32];
        float su = u0 + u1;
#pragma unroll
        for (int off = 16; off > 0; off >>= 1) su += __shfl_xor_sync(0xffffffff, su, off);
        float mean = su * (1.0f/64.0f);
        float dd0 = u0 - mean, dd1 = u1 - mean;
        float q = dd0*dd0 + dd1*dd1;
#pragma unroll
        for (int off = 16; off > 0; off >>= 1) q += __shfl_xor_sync(0xffffffff, q, off);
        float rs = rsqrtf(q*(1.0f/64.0f) + 1e-5f);
        size_t o = ((size_t)(b*Nn + m0g + m)*Tt + t)*Dd;
        g_X1[o + lane]      = dd0*rs*gg0 + bb0;
        g_X1[o + lane + 32] = dd1*rs*gg1 + bb1;
    }
}

// ---------------- tensor-core GRU (unchanged from R10) ----------------
__global__ void __launch_bounds__(256) k_gru_tc(const float* __restrict__ Whh,
                                                const float* __restrict__ bhh,
                                                const float* __restrict__ Wih,
                                                const float* __restrict__ bih,
                                                const float* __restrict__ ln2g,
                                                const float* __restrict__ ln2b,
                                                float* __restrict__ out) {
    extern __shared__ unsigned su_[];
    unsigned* Whs = su_;
    unsigned* Wis = su_ + 13056;
    unsigned* X1s = su_;
    float*    X1f = (float*)(su_ + 4352);
    unsigned* Hb0 = su_ + 8704;
    unsigned* Hb1 = su_ + 9792;
    float*    U4  = (float*)(su_ + 10880);

    int tid = threadIdx.x;
    int w = tid >> 5, lane = tid & 31;
    int qr = lane >> 2, kc = lane & 3;
    int s_base = blockIdx.x * 16;
    int b = s_base >> 8;
    int node0 = s_base & 255;

    for (int idx = tid; idx < 3072; idx += 256) {
        int r = idx >> 4, c4 = idx & 15;
        float4 wv = *(const float4*)(Whh + (size_t)r*64 + c4*4);
        uint4 pv; pv.x = f2tf32(wv.x); pv.y = f2tf32(wv.y);
        pv.z = f2tf32(wv.z); pv.w = f2tf32(wv.w);
        *(uint4*)(Whs + r*68 + c4*4) = pv;
        float4 iv = *(const float4*)(Wih + (size_t)r*64 + c4*4);
        uint4 qv; qv.x = f2tf32(iv.x); qv.y = f2tf32(iv.y);
        qv.z = f2tf32(iv.z); qv.w = f2tf32(iv.w);
        *(uint4*)(Wis + r*68 + c4*4) = qv;
    }
    __syncthreads();

    unsigned br_[8][2], bz_[8][2], bn_[8][2];
    unsigned wr_[8][2], wz_[8][2], wn_[8][2];
#pragma unroll
    for (int ks = 0; ks < 8; ks++) {
        int nr = (0*64 + w*8 + qr)*68 + ks*8 + kc;
        int nz = (1*64 + w*8 + qr)*68 + ks*8 + kc;
        int nn = (2*64 + w*8 + qr)*68 + ks*8 + kc;
        br_[ks][0] = Whs[nr]; br_[ks][1] = Whs[nr + 4];
        bz_[ks][0] = Whs[nz]; bz_[ks][1] = Whs[nz + 4];
        bn_[ks][0] = Whs[nn]; bn_[ks][1] = Whs[nn + 4];
        wr_[ks][0] = Wis[nr]; wr_[ks][1] = Wis[nr + 4];
        wz_[ks][0] = Wis[nz]; wz_[ks][1] = Wis[nz + 4];
        wn_[ks][0] = Wis[nn]; wn_[ks][1] = Wis[nn + 4];
    }
    __syncthreads();

    for (int idx = tid; idx < 1088; idx += 256) Hb0[idx] = 0;

    int col0 = w*8 + 2*kc;
    float2 bhr = *(const float2*)(bhh + col0);
    float2 bhz = *(const float2*)(bhh + 64 + col0);
    float2 bhn = *(const float2*)(bhh + 128 + col0);
    float2 bir = *(const float2*)(bih + col0);
    float2 biz = *(const float2*)(bih + 64 + col0);
    float2 bin_ = *(const float2*)(bih + 128 + col0);
    float g2a = ln2g[lane], g2b = ln2g[lane+32];
    float b2a = ln2b[lane], b2b = ln2b[lane+32];

    float h_old[4] = {0.f, 0.f, 0.f, 0.f};

    for (int tc = 0; tc < Tt; tc += 4) {
        __syncthreads();

        for (int idx = tid; idx < 4096; idx += 256) {
            int s = idx >> 10, rem = idx & 1023, row = rem >> 6, col = rem & 63;
            float v = g_X1[(size_t)(s_base + row)*Tt*Dd + (size_t)(tc + s)*Dd + col];
            X1s[s*1088 + row*68 + col] = f2tf32(v);
            X1f[s*1088 + row*68 + col] = v;
        }
        __syncthreads();

        float gr_[4][4], gz_[4][4], gn_[4][4];
#pragma unroll
        for (int s = 0; s < 4; s++) {
            const unsigned* Xc = X1s + s*1088;
            unsigned ax[8][4];
#pragma unroll
            for (int ks = 0; ks < 8; ks++) {
                ax[ks][0] = Xc[qr*68 + ks*8 + kc];
                ax[ks][1] = Xc[(qr+8)*68 + ks*8 + kc];
                ax[ks][2] = Xc[qr*68 + ks*8 + kc + 4];
                ax[ks][3] = Xc[(qr+8)*68 + ks*8 + kc + 4];
            }
            gr_[s][0]=0.f; gr_[s][1]=0.f; gr_[s][2]=0.f; gr_[s][3]=0.f;
            gz_[s][0]=0.f; gz_[s][1]=0.f; gz_[s][2]=0.f; gz_[s][3]=0.f;
            gn_[s][0]=0.f; gn_[s][1]=0.f; gn_[s][2]=0.f; gn_[s][3]=0.f;
#pragma unroll
            for (int ks = 0; ks < 8; ks++) {
                MMA_TF32(gr_[s][0],gr_[s][1],gr_[s][2],gr_[s][3], ax[ks][0],ax[ks][1],ax[ks][2],ax[ks][3], wr_[ks][0],wr_[ks][1]);
                MMA_TF32(gz_[s][0],gz_[s][1],gz_[s][2],gz_[s][3], ax[ks][0],ax[ks][1],ax[ks][2],ax[ks][3], wz_[ks][0],wz_[ks][1]);
                MMA_TF32(gn_[s][0],gn_[s][1],gn_[s][2],gn_[s][3], ax[ks][0],ax[ks][1],ax[ks][2],ax[ks][3], wn_[ks][0],wn_[ks][1]);
            }
        }

#pragma unroll
        for (int s = 0; s < 4; s++) {
            int t = tc + s;
            unsigned* Hc = (t & 1) ? Hb1 : Hb0;
            unsigned* Hn = (t & 1) ? Hb0 : Hb1;
            float* Us = U4 + s*1088;
            const float* Xf = X1f + s*1088;

            float2 xa = *(const float2*)(Xf + qr*68 + col0);
            float2 xb = *(const float2*)(Xf + (qr+8)*68 + col0);

            float cr[4] = {0.f,0.f,0.f,0.f}, cz[4] = {0.f,0.f,0.f,0.f}, cn[4] = {0.f,0.f,0.f,0.f};
            {
                unsigned a[8][4];
#pragma unroll
                for (int ks = 0; ks < 8; ks++) {
                    a[ks][0] = Hc[qr*68 + ks*8 + kc];
                    a[ks][1] = Hc[(qr+8)*68 + ks*8 + kc];
                    a[ks][2] = Hc[qr*68 + ks*8 + kc + 4];
                    a[ks][3] = Hc[(qr+8)*68 + ks*8 + kc + 4];
                }
#pragma unroll
                for (int ks = 0; ks < 8; ks++) {
                    MMA_TF32(cr[0],cr[1],cr[2],cr[3], a[ks][0],a[ks][1],a[ks][2],a[ks][3], br_[ks][0],br_[ks][1]);
                    MMA_TF32(cz[0],cz[1],cz[2],cz[3], a[ks][0],a[ks][1],a[ks][2],a[ks][3], bz_[ks][0],bz_[ks][1]);
                    MMA_TF32(cn[0],cn[1],cn[2],cn[3], a[ks][0],a[ks][1],a[ks][2],a[ks][3], bn_[ks][0],bn_[ks][1]);
                }
            }

            float r0 = siga(gr_[s][0] + bir.x + cr[0] + bhr.x);
            float r1 = siga(gr_[s][1] + bir.y + cr[1] + bhr.y);
            float r2 = siga(gr_[s][2] + bir.x + cr[2] + bhr.x);
            float r3 = siga(gr_[s][3] + bir.y + cr[3] + bhr.y);
            float z0 = siga(gz_[s][0] + biz.x + cz[0] + bhz.x);
            float z1 = siga(gz_[s][1] + biz.y + cz[1] + bhz.y);
            float z2 = siga(gz_[s][2] + biz.x + cz[2] + bhz.x);
            float z3 = siga(gz_[s][3] + biz.y + cz[3] + bhz.y);
            float n0 = tanha(gn_[s][0] + bin_.x + r0*(cn[0] + bhn.x));
            float n1 = tanha(gn_[s][1] + bin_.y + r1*(cn[1] + bhn.y));
            float n2 = tanha(gn_[s][2] + bin_.x + r2*(cn[2] + bhn.x));
            float n3 = tanha(gn_[s][3] + bin_.y + r3*(cn[3] + bhn.y));
            float h0 = (1.f - z0)*n0 + z0*h_old[0];
            float h1 = (1.f - z1)*n1 + z1*h_old[1];
            float h2v = (1.f - z2)*n2 + z2*h_old[2];
            float h3 = (1.f - z3)*n3 + z3*h_old[3];
            h_old[0] = h0; h_old[1] = h1; h_old[2] = h2v; h_old[3] = h3;

            uint2 hp0; hp0.x = f2tf32(h0); hp0.y = f2tf32(h1);
            uint2 hp1; hp1.x = f2tf32(h2v); hp1.y = f2tf32(h3);
            *(uint2*)(Hn + qr*68 + col0)     = hp0;
            *(uint2*)(Hn + (qr+8)*68 + col0) = hp1;
            float2 up0; up0.x = xa.x + h0; up0.y = xa.y + h1;
            float2 up1; up1.x = xb.x + h2v; up1.y = xb.y + h3;
            *(float2*)(Us + qr*68 + col0)     = up0;
            *(float2*)(Us + (qr+8)*68 + col0) = up1;
            __syncthreads();
        }

#pragma unroll
        for (int rr = 0; rr < 8; rr++) {
            int inst = w*8 + rr;
            int s = inst >> 4, row = inst & 15;
            const float* Us = U4 + s*1088;
            const float* Xf = X1f + s*1088;
            float v0 = Us[row*68 + lane], v1 = Us[row*68 + lane + 32];
            float sv = v0 + v1, qv = v0*v0 + v1*v1;
#pragma unroll
            for (int off = 16; off > 0; off >>= 1) {
                sv += __shfl_xor_sync(0xffffffff, sv, off);
                qv += __shfl_xor_sync(0xffffffff, qv, off);
            }
            float mean = sv * (1.0f/64.0f);
            float var = qv*(1.0f/64.0f) - mean*mean;
            float rs = rsqrtf(var + 1e-5f);
            float x0v = Xf[row*68 + lane], x1v = Xf[row*68 + lane + 32];
            size_t oo = (size_t)b*Tt*Nn*Dd + (size_t)(tc + s)*Nn*Dd + (size_t)(node0 + row)*Dd;
            out[oo + lane]      = x0v + (v0 - mean)*rs*g2a + b2a;
            out[oo + lane + 32] = x1v + (v1 - mean)*rs*g2b + b2b;
        }
    }
}

// ---------------- launcher ----------------
extern "C" void kernel_launch(void* const* d_in, const int* in_sizes, int n_in,
                              void* d_out, int out_size) {
    (void)in_sizes; (void)n_in; (void)out_size;
    const float* H_i  = (const float*)d_in[0];
    const float* H_j  = (const float*)d_in[1];
    const float* Wq   = (const float*)d_in[2];
    const float* bq   = (const float*)d_in[3];
    const float* Wk   = (const float*)d_in[4];
    const float* bk   = (const float*)d_in[5];
    const float* Wv   = (const float*)d_in[6];
    const float* bv   = (const float*)d_in[7];
    const float* lgam = (const float*)d_in[8];
    const float* ltau = (const float*)d_in[9];
    const float* e1   = (const float*)d_in[10];
    const float* e2   = (const float*)d_in[11];
    const float* Wg   = (const float*)d_in[12];
    const float* bg   = (const float*)d_in[13];
    const float* ln1g = (const float*)d_in[14];
    const float* ln1b = (const float*)d_in[15];
    const float* Wih  = (const float*)d_in[16];
    const float* Whh  = (const float*)d_in[17];
    const float* bih  = (const float*)d_in[18];
    const float* bhh  = (const float*)d_in[19];
    const float* ln2g = (const float*)d_in[20];
    const float* ln2b = (const float*)d_in[21];
    float* out = (float*)d_out;

    const int ATTN_SMEM = 42688 * 4;   // 170752 B
    const int GCN_SMEM  = 25920 * 4;   // 103680 B
    const int GRU_SMEM  = 26112 * 4;   // 104448 B
    cudaFuncSetAttribute(k_attn, cudaFuncAttributeMaxDynamicSharedMemorySize, ATTN_SMEM);
    cudaFuncSetAttribute(k_gcn,  cudaFuncAttributeMaxDynamicSharedMemorySize, GCN_SMEM);
    cudaFuncSetAttribute(k_gru_tc, cudaFuncAttributeMaxDynamicSharedMemorySize, GRU_SMEM);

    k_adj<<<256, 256>>>(e1, e2);
    k_attn<<<Bb*Nn, 512, ATTN_SMEM>>>(H_i, H_j, Wq, bq, Wk, bk, Wv, bv, lgam, ltau);
    k_gcn<<<Bb*Tt*2, 512, GCN_SMEM>>>(Wg, bg, ln1g, ln1b);
    k_gru_tc<<<Bb*Nn/16, 256, GRU_SMEM>>>(Whh, bhh, Wih, bih, ln2g, ln2b, out);
}

// round 13
// speedup vs baseline: 1.2487x; 1.0583x over previous
#include <cuda_runtime.h>
#include <math.h>

#define Bb 8
#define Tt 128
#define Nn 256
#define Dd 64
#define D3 192
#define BTND 16777216   // 8*128*256*64

// ---------------- device scratch ----------------
__device__ float g_ALN[BTND];          // aligner output, [B,T,N,D]
__device__ float g_X1[BTND];           // post-ln1, [B,N,T,D]
__device__ unsigned g_ADPu[Nn*Nn];     // adjacency, tf32 bits, row-major [m][n]

__device__ __forceinline__ unsigned f2tf32(float f) {
    unsigned u;
    asm("cvt.rna.tf32.f32 %0, %1;" : "=r"(u) : "f"(f));
    return u;
}
__device__ __forceinline__ float tanha(float x) {
    float y;
    asm("tanh.approx.f32 %0, %1;" : "=f"(y) : "f"(x));
    return y;
}
__device__ __forceinline__ float siga(float x) { return 0.5f*tanha(0.5f*x) + 0.5f; }

#define MMA_TF32(c0,c1,c2,c3,a0,a1,a2,a3,b0,b1) \
    asm volatile("mma.sync.aligned.m16n8k8.row.col.f32.tf32.tf32.f32 " \
        "{%0,%1,%2,%3}, {%4,%5,%6,%7}, {%8,%9}, {%0,%1,%2,%3};" \
        : "+f"(c0), "+f"(c1), "+f"(c2), "+f"(c3) \
        : "r"(a0), "r"(a1), "r"(a2), "r"(a3), "r"(b0), "r"(b1))

// ---------------- adjacency ----------------
__global__ void k_adj(const float* __restrict__ e1, const float* __restrict__ e2) {
    int m = blockIdx.x;
    int n = threadIdx.x;            // 256 threads
    float a = 0.f;
#pragma unroll
    for (int k = 0; k < 32; k++) a = fmaf(e1[m*32 + k], e2[k*256 + n], a);
    a = fmaxf(a, 0.f);
    __shared__ float red[256];
    red[n] = a; __syncthreads();
    for (int s = 128; s > 0; s >>= 1) { if (n < s) red[n] = fmaxf(red[n], red[n+s]); __syncthreads(); }
    float mx = red[0]; __syncthreads();
    float e = expf(a - mx);
    red[n] = e; __syncthreads();
    for (int s = 128; s > 0; s >>= 1) { if (n < s) red[n] += red[n+s]; __syncthreads(); }
    g_ADPu[m*256 + n] = f2tf32(e / red[0]);
}

// col-split projection gemm: warp computes rows [mrow,mrow+8], cols colbase..colbase+31
__device__ __forceinline__ void gemm_c4(const unsigned* __restrict__ As,
                                        const unsigned* __restrict__ Bs,
                                        int mrow, int qr, int kc, int colbase,
                                        float c[4][4]) {
    unsigned a[8][4];
#pragma unroll
    for (int ks = 0; ks < 8; ks++) {
        a[ks][0] = As[mrow*68 + ks*8 + kc];
        a[ks][1] = As[(mrow+8)*68 + ks*8 + kc];
        a[ks][2] = As[mrow*68 + ks*8 + kc + 4];
        a[ks][3] = As[(mrow+8)*68 + ks*8 + kc + 4];
    }
#pragma unroll
    for (int nt = 0; nt < 4; nt++) {
        c[nt][0]=0.f; c[nt][1]=0.f; c[nt][2]=0.f; c[nt][3]=0.f;
        int ncol = colbase + nt*8 + qr;
#pragma unroll
        for (int ks = 0; ks < 8; ks++) {
            unsigned b0 = Bs[ncol*68 + ks*8 + kc];
            unsigned b1 = Bs[ncol*68 + ks*8 + kc + 4];
            MMA_TF32(c[nt][0],c[nt][1],c[nt][2],c[nt][3],
                     a[ks][0],a[ks][1],a[ks][2],a[ks][3], b0,b1);
        }
    }
}

// ---------------- fused QKV + temporal attention, 512 threads, 5 barriers ----------------
// smem words (190208 B): Hs(Hj)@0 [128][68], Qi(Hi)@8704 [128][68],
// Ws (Wk@17408, Wv@21760, Wq@26112, each [64][68]),
// Qst(Q)@17408 overlays Wk+Wv after phase2, Ks@30464 [128][68],
// Vt@39168 [64][129], biasr@47424 [128]. P [128][132] fp32 overlays Hs+Qi.
__global__ void __launch_bounds__(512, 1) k_attn(
        const float* __restrict__ Hi, const float* __restrict__ Hj,
        const float* __restrict__ Wq, const float* __restrict__ bq,
        const float* __restrict__ Wk, const float* __restrict__ bk,
        const float* __restrict__ Wv, const float* __restrict__ bv,
        const float* __restrict__ lg, const float* __restrict__ lt) {
    extern __shared__ float sm[];
    unsigned* Hs  = (unsigned*)sm;
    unsigned* Qi  = Hs + 8704;
    unsigned* Wks = Hs + 17408;
    unsigned* Wvs = Hs + 21760;
    unsigned* Wqs = Hs + 26112;
    unsigned* Qst = Hs + 17408;     // overlays Wks+Wvs after phase 2
    unsigned* Ks  = Hs + 30464;
    unsigned* Vt  = Hs + 39168;
    float* biasr  = sm + 47424;
    float*    Ps  = sm;             // overlays Hs+Qi
    unsigned* Pu  = (unsigned*)sm;

    int tid = threadIdx.x;
    int bn = blockIdx.x;
    int b = bn >> 8, n = bn & 255;

    float gamma = fmaxf(expf(*lg), 0.01f);
    float tau   = fmaxf(expf(*lt), 0.01f);
    float scale = 1.0f / (8.0f * tau);
    if (tid < 128) biasr[tid] = logf(expf(-gamma * (float)tid * (1.0f/127.0f)) + 1e-8f);

    int w = tid >> 5, lane = tid & 31;
    int qr = lane >> 2, kc = lane & 3;
    int wp = w >> 1, side = w & 1;
    int mrow = wp*16 + qr;

    // ---- phase 1: ALL loads ----
    for (int idx = tid; idx < 2048; idx += 512) {
        int i = idx >> 4, c4 = idx & 15;
        size_t g = ((size_t)(b*Tt + i)*Nn + n)*Dd + c4*4;
        float4 hj = *(const float4*)(Hj + g);
        float4 hi = *(const float4*)(Hi + g);
        uint4 pj; pj.x=f2tf32(hj.x); pj.y=f2tf32(hj.y); pj.z=f2tf32(hj.z); pj.w=f2tf32(hj.w);
        uint4 pi; pi.x=f2tf32(hi.x); pi.y=f2tf32(hi.y); pi.z=f2tf32(hi.z); pi.w=f2tf32(hi.w);
        *(uint4*)(Hs + i*68 + c4*4) = pj;
        *(uint4*)(Qi + i*68 + c4*4) = pi;
    }
    for (int idx = tid; idx < 1024; idx += 512) {
        int r = idx >> 4, c4 = idx & 15;
        float4 wk = *(const float4*)(Wk + (size_t)r*64 + c4*4);
        float4 wv = *(const float4*)(Wv + (size_t)r*64 + c4*4);
        float4 wq = *(const float4*)(Wq + (size_t)r*64 + c4*4);
        uint4 pk; pk.x=f2tf32(wk.x); pk.y=f2tf32(wk.y); pk.z=f2tf32(wk.z); pk.w=f2tf32(wk.w);
        uint4 pv; pv.x=f2tf32(wv.x); pv.y=f2tf32(wv.y); pv.z=f2tf32(wv.z); pv.w=f2tf32(wv.w);
        uint4 pq; pq.x=f2tf32(wq.x); pq.y=f2tf32(wq.y); pq.z=f2tf32(wq.z); pq.w=f2tf32(wq.w);
        *(uint4*)(Wks + r*68 + c4*4) = pk;
        *(uint4*)(Wvs + r*68 + c4*4) = pv;
        *(uint4*)(Wqs + r*68 + c4*4) = pq;
    }
    __syncthreads();

    // ---- phase 2: K and V gemms (disjoint outputs, one barrier after) ----
    {
        float c[4][4];
        gemm_c4(Hs, Wks, mrow, qr, kc, side*32, c);
#pragma unroll
        for (int nt = 0; nt < 4; nt++) {
            int d = side*32 + nt*8 + 2*kc;
            float bx = bk[d], by = bk[d+1];
            Ks[mrow*68 + d]       = f2tf32(c[nt][0] + bx);
            Ks[mrow*68 + d + 1]   = f2tf32(c[nt][1] + by);
            Ks[(mrow+8)*68 + d]     = f2tf32(c[nt][2] + bx);
            Ks[(mrow+8)*68 + d + 1] = f2tf32(c[nt][3] + by);
        }
        float cv[4][4];
        gemm_c4(Hs, Wvs, mrow, qr, kc, side*32, cv);
#pragma unroll
        for (int nt = 0; nt < 4; nt++) {
            int d = side*32 + nt*8 + 2*kc;
            float bx = bv[d], by = bv[d+1];
            Vt[d*129 + mrow]         = f2tf32(cv[nt][0] + bx);
            Vt[(d+1)*129 + mrow]     = f2tf32(cv[nt][1] + by);
            Vt[d*129 + mrow + 8]     = f2tf32(cv[nt][2] + bx);
            Vt[(d+1)*129 + mrow + 8] = f2tf32(cv[nt][3] + by);
        }
    }
    __syncthreads();

    // ---- phase 3: Q gemm (A=Qi, B=Wqs) -> Qst (overlays dead Wk/Wv) ----
    {
        float c[4][4];
        gemm_c4(Qi, Wqs, mrow, qr, kc, side*32, c);
#pragma unroll
        for (int nt = 0; nt < 4; nt++) {
            int d = side*32 + nt*8 + 2*kc;
            float bx = bq[d], by = bq[d+1];
            Qst[mrow*68 + d]       = f2tf32(c[nt][0] + bx);
            Qst[mrow*68 + d + 1]   = f2tf32(c[nt][1] + by);
            Qst[(mrow+8)*68 + d]     = f2tf32(c[nt][2] + bx);
            Qst[(mrow+8)*68 + d + 1] = f2tf32(c[nt][3] + by);
        }
    }
    __syncthreads();

    // ---- phase 4: S = Q K^T, write P directly (overlays dead Hs/Qi) ----
    unsigned a[8][4];
#pragma unroll
    for (int ks = 0; ks < 8; ks++) {
        a[ks][0] = Qst[mrow*68 + ks*8 + kc];
        a[ks][1] = Qst[(mrow+8)*68 + ks*8 + kc];
        a[ks][2] = Qst[mrow*68 + ks*8 + kc + 4];
        a[ks][3] = Qst[(mrow+8)*68 + ks*8 + kc + 4];
    }
    float c[8][4];
#pragma unroll
    for (int nt = 0; nt < 8; nt++) { c[nt][0]=0.f; c[nt][1]=0.f; c[nt][2]=0.f; c[nt][3]=0.f; }
#pragma unroll
    for (int nt = 0; nt < 8; nt++) {
        int ncol = side*64 + nt*8 + qr;
#pragma unroll
        for (int ks = 0; ks < 8; ks++) {
            unsigned b0 = Ks[ncol*68 + ks*8 + kc];
            unsigned b1 = Ks[ncol*68 + ks*8 + kc + 4];
            MMA_TF32(c[nt][0],c[nt][1],c[nt][2],c[nt][3],
                     a[ks][0],a[ks][1],a[ks][2],a[ks][3], b0,b1);
        }
    }
    int i1 = mrow, i2 = mrow + 8;
#pragma unroll
    for (int nt = 0; nt < 8; nt++) {
        int j0 = side*64 + nt*8 + 2*kc;
        int d10 = i1 - j0;     d10 = d10 < 0 ? -d10 : d10;
        int d11 = i1 - j0 - 1; d11 = d11 < 0 ? -d11 : d11;
        int d20 = i2 - j0;     d20 = d20 < 0 ? -d20 : d20;
        int d21 = i2 - j0 - 1; d21 = d21 < 0 ? -d21 : d21;
        Ps[i1*132 + j0]     = c[nt][0]*scale + biasr[d10];
        Ps[i1*132 + j0 + 1] = c[nt][1]*scale + biasr[d11];
        Ps[i2*132 + j0]     = c[nt][2]*scale + biasr[d20];
        Ps[i2*132 + j0 + 1] = c[nt][3]*scale + biasr[d21];
    }
    __syncthreads();

    // ---- phase 5: softmax, write P tf32 ----
    for (int rr = 0; rr < 8; rr++) {
        int i = w*8 + rr;
        float v0 = Ps[i*132 + lane], v1 = Ps[i*132 + lane + 32],
              v2 = Ps[i*132 + lane + 64], v3 = Ps[i*132 + lane + 96];
        float mx = fmaxf(fmaxf(v0, v1), fmaxf(v2, v3));
#pragma unroll
        for (int off = 16; off > 0; off >>= 1) mx = fmaxf(mx, __shfl_xor_sync(0xffffffff, mx, off));
        float e0 = __expf(v0 - mx), e1 = __expf(v1 - mx), e2 = __expf(v2 - mx), e3 = __expf(v3 - mx);
        float su = (e0 + e1) + (e2 + e3);
#pragma unroll
        for (int off = 16; off > 0; off >>= 1) su += __shfl_xor_sync(0xffffffff, su, off);
        float inv = 1.0f / su;
        Pu[i*132 + lane]      = f2tf32(e0 * inv);
        Pu[i*132 + lane + 32] = f2tf32(e1 * inv);
        Pu[i*132 + lane + 64] = f2tf32(e2 * inv);
        Pu[i*132 + lane + 96] = f2tf32(e3 * inv);
    }
    __syncthreads();

    // ---- phase 6: out = P @ V ----
    float c2[4][4];
#pragma unroll
    for (int nt = 0; nt < 4; nt++) { c2[nt][0]=0.f; c2[nt][1]=0.f; c2[nt][2]=0.f; c2[nt][3]=0.f; }
#pragma unroll
    for (int ks = 0; ks < 16; ks++) {
        unsigned a0 = Pu[mrow*132 + ks*8 + kc];
        unsigned a1 = Pu[(mrow+8)*132 + ks*8 + kc];
        unsigned a2 = Pu[mrow*132 + ks*8 + kc + 4];
        unsigned a3 = Pu[(mrow+8)*132 + ks*8 + kc + 4];
#pragma unroll
        for (int nt = 0; nt < 4; nt++) {
            int dcol = side*32 + nt*8 + qr;
            unsigned b0 = Vt[dcol*129 + ks*8 + kc];
            unsigned b1 = Vt[dcol*129 + ks*8 + kc + 4];
            MMA_TF32(c2[nt][0],c2[nt][1],c2[nt][2],c2[nt][3], a0,a1,a2,a3, b0,b1);
        }
    }
#pragma unroll
    for (int nt = 0; nt < 4; nt++) {
        int d = side*32 + nt*8 + 2*kc;
        float2 o0; o0.x = c2[nt][0]; o0.y = c2[nt][1];
        float2 o1; o1.x = c2[nt][2]; o1.y = c2[nt][3];
        *(float2*)(g_ALN + ((size_t)(b*Tt + mrow)*Nn + n)*Dd + d)     = o0;
        *(float2*)(g_ALN + ((size_t)(b*Tt + mrow + 8)*Nn + n)*Dd + d) = o1;
    }
}

// ---------------- GCN + residual + LN1, 512 threads (unchanged from R12) ----------------
__global__ void __launch_bounds__(512, 2) k_gcn(const float* __restrict__ Wg,
                                                const float* __restrict__ bg,
                                                const float* __restrict__ ln1g,
                                                const float* __restrict__ ln1b) {
    extern __shared__ float sg[];
    unsigned* As  = (unsigned*)sg;
    unsigned* Bs  = As + 8704;
    unsigned* Tmp = As + 12864;
    unsigned* Wgs = As + 21568;
    float* h2 = sg;   // overlays As

    int tid = threadIdx.x;
    int blk = blockIdx.x;
    int bt = blk >> 1, half = blk & 1;
    int m0g = half * 128;
    int b = bt >> 7, t = bt & 127;
    const float* Xbt = g_ALN + (size_t)bt * 16384;

    int w = tid >> 5, lane = tid & 31;
    int qr = lane >> 2, kc = lane & 3;
    int wp = w >> 1, side = w & 1;
    int mrow = wp*16 + qr;

    for (int idx = tid; idx < 1024; idx += 512) {
        int r = idx >> 4, c4 = idx & 15;
        float4 wv = *(const float4*)(Wg + (size_t)r*64 + c4*4);
        uint4 pv; pv.x = f2tf32(wv.x); pv.y = f2tf32(wv.y);
        pv.z = f2tf32(wv.z); pv.w = f2tf32(wv.w);
        *(uint4*)(Wgs + r*68 + c4*4) = pv;
    }

    float c1[4][4];
#pragma unroll
    for (int nt = 0; nt < 4; nt++) { c1[nt][0]=0.f; c1[nt][1]=0.f; c1[nt][2]=0.f; c1[nt][3]=0.f; }

    for (int ch = 0; ch < 4; ch++) {
        __syncthreads();
        for (int idx = tid; idx < 2048; idx += 512) {
            int r = idx >> 4, c4 = idx & 15;
            *(uint4*)(As + r*68 + c4*4) =
                *(const uint4*)(g_ADPu + (size_t)(m0g + r)*256 + ch*64 + c4*4);
        }
        for (int idx = tid; idx < 1024; idx += 512) {
            int nn = idx >> 4, c4 = idx & 15;
            float4 xv = *(const float4*)(Xbt + (size_t)(ch*64 + nn)*64 + c4*4);
            Bs[(c4*4+0)*65 + nn] = f2tf32(xv.x);
            Bs[(c4*4+1)*65 + nn] = f2tf32(xv.y);
            Bs[(c4*4+2)*65 + nn] = f2tf32(xv.z);
            Bs[(c4*4+3)*65 + nn] = f2tf32(xv.w);
        }
        __syncthreads();
#pragma unroll
        for (int ks = 0; ks < 8; ks++) {
            unsigned a0 = As[mrow*68 + ks*8 + kc];
            unsigned a1 = As[(mrow+8)*68 + ks*8 + kc];
            unsigned a2 = As[mrow*68 + ks*8 + kc + 4];
            unsigned a3 = As[(mrow+8)*68 + ks*8 + kc + 4];
#pragma unroll
            for (int nt = 0; nt < 4; nt++) {
                int dcol = side*32 + nt*8 + qr;
                unsigned b0 = Bs[dcol*65 + ks*8 + kc];
                unsigned b1 = Bs[dcol*65 + ks*8 + kc + 4];
                MMA_TF32(c1[nt][0],c1[nt][1],c1[nt][2],c1[nt][3], a0,a1,a2,a3, b0,b1);
            }
        }
    }

#pragma unroll
    for (int nt = 0; nt < 4; nt++) {
        int d0 = side*32 + nt*8 + 2*kc;
        Tmp[mrow*68 + d0]       = f2tf32(c1[nt][0]);
        Tmp[mrow*68 + d0 + 1]   = f2tf32(c1[nt][1]);
        Tmp[(mrow+8)*68 + d0]     = f2tf32(c1[nt][2]);
        Tmp[(mrow+8)*68 + d0 + 1] = f2tf32(c1[nt][3]);
    }
    __syncthreads();

    float c2[4][4];
#pragma unroll
    for (int nt = 0; nt < 4; nt++) { c2[nt][0]=0.f; c2[nt][1]=0.f; c2[nt][2]=0.f; c2[nt][3]=0.f; }
#pragma unroll
    for (int ks = 0; ks < 8; ks++) {
        unsigned a0 = Tmp[mrow*68 + ks*8 + kc];
        unsigned a1 = Tmp[(mrow+8)*68 + ks*8 + kc];
        unsigned a2 = Tmp[mrow*68 + ks*8 + kc + 4];
        unsigned a3 = Tmp[(mrow+8)*68 + ks*8 + kc + 4];
#pragma unroll
        for (int nt = 0; nt < 4; nt++) {
            int ncol = side*32 + nt*8 + qr;
            unsigned b0 = Wgs[ncol*68 + ks*8 + kc];
            unsigned b1 = Wgs[ncol*68 + ks*8 + kc + 4];
            MMA_TF32(c2[nt][0],c2[nt][1],c2[nt][2],c2[nt][3], a0,a1,a2,a3, b0,b1);
        }
    }
    __syncthreads();

#pragma unroll
    for (int nt = 0; nt < 4; nt++) {
        int e0 = side*32 + nt*8 + 2*kc;
        float bx = bg[e0], by = bg[e0+1];
        h2[mrow*68 + e0]       = fmaxf(c2[nt][0] + bx, 0.f);
        h2[mrow*68 + e0 + 1]   = fmaxf(c2[nt][1] + by, 0.f);
        h2[(mrow+8)*68 + e0]     = fmaxf(c2[nt][2] + bx, 0.f);
        h2[(mrow+8)*68 + e0 + 1] = fmaxf(c2[nt][3] + by, 0.f);
    }
    __syncthreads();

    float gg0 = ln1g[lane], gg1 = ln1g[lane+32];
    float bb0 = ln1b[lane], bb1 = ln1b[lane+32];
    for (int mm = 0; mm < 8; mm++) {
        int m = w*8 + mm;
        const float* xr = Xbt + (size_t)(m0g + m)*64;
        float u0 = xr[lane]      + h2[m*68 + lane];
        float u1 = xr[lane + 32] + h2[m*68 + lane + 32];
        float su = u0 + u1;
#pragma unroll
        for (int off = 16; off > 0; off >>= 1) su += __shfl_xor_sync(0xffffffff, su, off);
        float mean = su * (1.0f/64.0f);
        float dd0 = u0 - mean, dd1 = u1 - mean;
        float q = dd0*dd0 + dd1*dd1;
#pragma unroll
        for (int off = 16; off > 0; off >>= 1) q += __shfl_xor_sync(0xffffffff, q, off);
        float rs = rsqrtf(q*(1.0f/64.0f) + 1e-5f);
        size_t o = ((size_t)(b*Nn + m0g + m)*Tt + t)*Dd;
        g_X1[o + lane]      = dd0*rs*gg0 + bb0;
        g_X1[o + lane + 32] = dd1*rs*gg1 + bb1;
    }
}

// ---------------- tensor-core GRU (unchanged from R10) ----------------
__global__ void __launch_bounds__(256) k_gru_tc(const float* __restrict__ Whh,
                                                const float* __restrict__ bhh,
                                                const float* __restrict__ Wih,
                                                const float* __restrict__ bih,
                                                const float* __restrict__ ln2g,
                                                const float* __restrict__ ln2b,
                                                float* __restrict__ out) {
    extern __shared__ unsigned su_[];
    unsigned* Whs = su_;
    unsigned* Wis = su_ + 13056;
    unsigned* X1s = su_;
    float*    X1f = (float*)(su_ + 4352);
    unsigned* Hb0 = su_ + 8704;
    unsigned* Hb1 = su_ + 9792;
    float*    U4  = (float*)(su_ + 10880);

    int tid = threadIdx.x;
    int w = tid >> 5, lane = tid & 31;
    int qr = lane >> 2, kc = lane & 3;
    int s_base = blockIdx.x * 16;
    int b = s_base >> 8;
    int node0 = s_base & 255;

    for (int idx = tid; idx < 3072; idx += 256) {
        int r = idx >> 4, c4 = idx & 15;
        float4 wv = *(const float4*)(Whh + (size_t)r*64 + c4*4);
        uint4 pv; pv.x = f2tf32(wv.x); pv.y = f2tf32(wv.y);
        pv.z = f2tf32(wv.z); pv.w = f2tf32(wv.w);
        *(uint4*)(Whs + r*68 + c4*4) = pv;
        float4 iv = *(const float4*)(Wih + (size_t)r*64 + c4*4);
        uint4 qv; qv.x = f2tf32(iv.x); qv.y = f2tf32(iv.y);
        qv.z = f2tf32(iv.z); qv.w = f2tf32(iv.w);
        *(uint4*)(Wis + r*68 + c4*4) = qv;
    }
    __syncthreads();

    unsigned br_[8][2], bz_[8][2], bn_[8][2];
    unsigned wr_[8][2], wz_[8][2], wn_[8][2];
#pragma unroll
    for (int ks = 0; ks < 8; ks++) {
        int nr = (0*64 + w*8 + qr)*68 + ks*8 + kc;
        int nz = (1*64 + w*8 + qr)*68 + ks*8 + kc;
        int nn = (2*64 + w*8 + qr)*68 + ks*8 + kc;
        br_[ks][0] = Whs[nr]; br_[ks][1] = Whs[nr + 4];
        bz_[ks][0] = Whs[nz]; bz_[ks][1] = Whs[nz + 4];
        bn_[ks][0] = Whs[nn]; bn_[ks][1] = Whs[nn + 4];
        wr_[ks][0] = Wis[nr]; wr_[ks][1] = Wis[nr + 4];
        wz_[ks][0] = Wis[nz]; wz_[ks][1] = Wis[nz + 4];
        wn_[ks][0] = Wis[nn]; wn_[ks][1] = Wis[nn + 4];
    }
    __syncthreads();

    for (int idx = tid; idx < 1088; idx += 256) Hb0[idx] = 0;

    int col0 = w*8 + 2*kc;
    float2 bhr = *(const float2*)(bhh + col0);
    float2 bhz = *(const float2*)(bhh + 64 + col0);
    float2 bhn = *(const float2*)(bhh + 128 + col0);
    float2 bir = *(const float2*)(bih + col0);
    float2 biz = *(const float2*)(bih + 64 + col0);
    float2 bin_ = *(const float2*)(bih + 128 + col0);
    float g2a = ln2g[lane], g2b = ln2g[lane+32];
    float b2a = ln2b[lane], b2b = ln2b[lane+32];

    float h_old[4] = {0.f, 0.f, 0.f, 0.f};

    for (int tc = 0; tc < Tt; tc += 4) {
        __syncthreads();

        for (int idx = tid; idx < 4096; idx += 256) {
            int s = idx >> 10, rem = idx & 1023, row = rem >> 6, col = rem & 63;
            float v = g_X1[(size_t)(s_base + row)*Tt*Dd + (size_t)(tc + s)*Dd + col];
            X1s[s*1088 + row*68 + col] = f2tf32(v);
            X1f[s*1088 + row*68 + col] = v;
        }
        __syncthreads();

        float gr_[4][4], gz_[4][4], gn_[4][4];
#pragma unroll
        for (int s = 0; s < 4; s++) {
            const unsigned* Xc = X1s + s*1088;
            unsigned ax[8][4];
#pragma unroll
            for (int ks = 0; ks < 8; ks++) {
                ax[ks][0] = Xc[qr*68 + ks*8 + kc];
                ax[ks][1] = Xc[(qr+8)*68 + ks*8 + kc];
                ax[ks][2] = Xc[qr*68 + ks*8 + kc + 4];
                ax[ks][3] = Xc[(qr+8)*68 + ks*8 + kc + 4];
            }
            gr_[s][0]=0.f; gr_[s][1]=0.f; gr_[s][2]=0.f; gr_[s][3]=0.f;
            gz_[s][0]=0.f; gz_[s][1]=0.f; gz_[s][2]=0.f; gz_[s][3]=0.f;
            gn_[s][0]=0.f; gn_[s][1]=0.f; gn_[s][2]=0.f; gn_[s][3]=0.f;
#pragma unroll
            for (int ks = 0; ks < 8; ks++) {
                MMA_TF32(gr_[s][0],gr_[s][1],gr_[s][2],gr_[s][3], ax[ks][0],ax[ks][1],ax[ks][2],ax[ks][3], wr_[ks][0],wr_[ks][1]);
                MMA_TF32(gz_[s][0],gz_[s][1],gz_[s][2],gz_[s][3], ax[ks][0],ax[ks][1],ax[ks][2],ax[ks][3], wz_[ks][0],wz_[ks][1]);
                MMA_TF32(gn_[s][0],gn_[s][1],gn_[s][2],gn_[s][3], ax[ks][0],ax[ks][1],ax[ks][2],ax[ks][3], wn_[ks][0],wn_[ks][1]);
            }
        }

#pragma unroll
        for (int s = 0; s < 4; s++) {
            int t = tc + s;
            unsigned* Hc = (t & 1) ? Hb1 : Hb0;
            unsigned* Hn = (t & 1) ? Hb0 : Hb1;
            float* Us = U4 + s*1088;
            const float* Xf = X1f + s*1088;

            float2 xa = *(const float2*)(Xf + qr*68 + col0);
            float2 xb = *(const float2*)(Xf + (qr+8)*68 + col0);

            float cr[4] = {0.f,0.f,0.f,0.f}, cz[4] = {0.f,0.f,0.f,0.f}, cn[4] = {0.f,0.f,0.f,0.f};
            {
                unsigned a[8][4];
#pragma unroll
                for (int ks = 0; ks < 8; ks++) {
                    a[ks][0] = Hc[qr*68 + ks*8 + kc];
                    a[ks][1] = Hc[(qr+8)*68 + ks*8 + kc];
                    a[ks][2] = Hc[qr*68 + ks*8 + kc + 4];
                    a[ks][3] = Hc[(qr+8)*68 + ks*8 + kc + 4];
                }
#pragma unroll
                for (int ks = 0; ks < 8; ks++) {
                    MMA_TF32(cr[0],cr[1],cr[2],cr[3], a[ks][0],a[ks][1],a[ks][2],a[ks][3], br_[ks][0],br_[ks][1]);
                    MMA_TF32(cz[0],cz[1],cz[2],cz[3], a[ks][0],a[ks][1],a[ks][2],a[ks][3], bz_[ks][0],bz_[ks][1]);
                    MMA_TF32(cn[0],cn[1],cn[2],cn[3], a[ks][0],a[ks][1],a[ks][2],a[ks][3], bn_[ks][0],bn_[ks][1]);
                }
            }

            float r0 = siga(gr_[s][0] + bir.x + cr[0] + bhr.x);
            float r1 = siga(gr_[s][1] + bir.y + cr[1] + bhr.y);
            float r2 = siga(gr_[s][2] + bir.x + cr[2] + bhr.x);
            float r3 = siga(gr_[s][3] + bir.y + cr[3] + bhr.y);
            float z0 = siga(gz_[s][0] + biz.x + cz[0] + bhz.x);
            float z1 = siga(gz_[s][1] + biz.y + cz[1] + bhz.y);
            float z2 = siga(gz_[s][2] + biz.x + cz[2] + bhz.x);
            float z3 = siga(gz_[s][3] + biz.y + cz[3] + bhz.y);
            float n0 = tanha(gn_[s][0] + bin_.x + r0*(cn[0] + bhn.x));
            float n1 = tanha(gn_[s][1] + bin_.y + r1*(cn[1] + bhn.y));
            float n2 = tanha(gn_[s][2] + bin_.x + r2*(cn[2] + bhn.x));
            float n3 = tanha(gn_[s][3] + bin_.y + r3*(cn[3] + bhn.y));
            float h0 = (1.f - z0)*n0 + z0*h_old[0];
            float h1 = (1.f - z1)*n1 + z1*h_old[1];
            float h2v = (1.f - z2)*n2 + z2*h_old[2];
            float h3 = (1.f - z3)*n3 + z3*h_old[3];
            h_old[0] = h0; h_old[1] = h1; h_old[2] = h2v; h_old[3] = h3;

            uint2 hp0; hp0.x = f2tf32(h0); hp0.y = f2tf32(h1);
            uint2 hp1; hp1.x = f2tf32(h2v); hp1.y = f2tf32(h3);
            *(uint2*)(Hn + qr*68 + col0)     = hp0;
            *(uint2*)(Hn + (qr+8)*68 + col0) = hp1;
            float2 up0; up0.x = xa.x + h0; up0.y = xa.y + h1;
            float2 up1; up1.x = xb.x + h2v; up1.y = xb.y + h3;
            *(float2*)(Us + qr*68 + col0)     = up0;
            *(float2*)(Us + (qr+8)*68 + col0) = up1;
            __syncthreads();
        }

#pragma unroll
        for (int rr = 0; rr < 8; rr++) {
            int inst = w*8 + rr;
            int s = inst >> 4, row = inst & 15;
            const float* Us = U4 + s*1088;
            const float* Xf = X1f + s*1088;
            float v0 = Us[row*68 + lane], v1 = Us[row*68 + lane + 32];
            float sv = v0 + v1, qv = v0*v0 + v1*v1;
#pragma unroll
            for (int off = 16; off > 0; off >>= 1) {
                sv += __shfl_xor_sync(0xffffffff, sv, off);
                qv += __shfl_xor_sync(0xffffffff, qv, off);
            }
            float mean = sv * (1.0f/64.0f);
            float var = qv*(1.0f/64.0f) - mean*mean;
            float rs = rsqrtf(var + 1e-5f);
            float x0v = Xf[row*68 + lane], x1v = Xf[row*68 + lane + 32];
            size_t oo = (size_t)b*Tt*Nn*Dd + (size_t)(tc + s)*Nn*Dd + (size_t)(node0 + row)*Dd;
            out[oo + lane]      = x0v + (v0 - mean)*rs*g2a + b2a;
            out[oo + lane + 32] = x1v + (v1 - mean)*rs*g2b + b2b;
        }
    }
}

// ---------------- launcher ----------------
extern "C" void kernel_launch(void* const* d_in, const int* in_sizes, int n_in,
                              void* d_out, int out_size) {
    (void)in_sizes; (void)n_in; (void)out_size;
    const float* H_i  = (const float*)d_in[0];
    const float* H_j  = (const float*)d_in[1];
    const float* Wq   = (const float*)d_in[2];
    const float* bq   = (const float*)d_in[3];
    const float* Wk   = (const float*)d_in[4];
    const float* bk   = (const float*)d_in[5];
    const float* Wv   = (const float*)d_in[6];
    const float* bv   = (const float*)d_in[7];
    const float* lgam = (const float*)d_in[8];
    const float* ltau = (const float*)d_in[9];
    const float* e1   = (const float*)d_in[10];
    const float* e2   = (const float*)d_in[11];
    const float* Wg   = (const float*)d_in[12];
    const float* bg   = (const float*)d_in[13];
    const float* ln1g = (const float*)d_in[14];
    const float* ln1b = (const float*)d_in[15];
    const float* Wih  = (const float*)d_in[16];
    const float* Whh  = (const float*)d_in[17];
    const float* bih  = (const float*)d_in[18];
    const float* bhh  = (const float*)d_in[19];
    const float* ln2g = (const float*)d_in[20];
    const float* ln2b = (const float*)d_in[21];
    float* out = (float*)d_out;

    const int ATTN_SMEM = 47552 * 4;   // 190208 B
    const int GCN_SMEM  = 25920 * 4;   // 103680 B
    const int GRU_SMEM  = 26112 * 4;   // 104448 B
    cudaFuncSetAttribute(k_attn, cudaFuncAttributeMaxDynamicSharedMemorySize, ATTN_SMEM);
    cudaFuncSetAttribute(k_gcn,  cudaFuncAttributeMaxDynamicSharedMemorySize, GCN_SMEM);
    cudaFuncSetAttribute(k_gru_tc, cudaFuncAttributeMaxDynamicSharedMemorySize, GRU_SMEM);

    k_adj<<<256, 256>>>(e1, e2);
    k_attn<<<Bb*Nn, 512, ATTN_SMEM>>>(H_i, H_j, Wq, bq, Wk, bk, Wv, bv, lgam, ltau);
    k_gcn<<<Bb*Tt*2, 512, GCN_SMEM>>>(Wg, bg, ln1g, ln1b);
    k_gru_tc<<<Bb*Nn/16, 256, GRU_SMEM>>>(Whh, bhh, Wih, bih, ln2g, ln2b, out);
}

// round 14
// speedup vs baseline: 1.3793x; 1.1046x over previous
#include <cuda_runtime.h>
#include <math.h>

#define Bb 8
#define Tt 128
#define Nn 256
#define Dd 64
#define D3 192
#define BTND 16777216   // 8*128*256*64

// ---------------- device scratch ----------------
__device__ float g_ALN[BTND];          // aligner output, [B,T,N,D]
__device__ float g_X1[BTND];           // post-ln1, [B,N,T,D]
__device__ unsigned g_ADPu[Nn*Nn];     // adjacency, tf32 bits, row-major [m][n]

__device__ __forceinline__ unsigned f2tf32(float f) {
    unsigned u;
    asm("cvt.rna.tf32.f32 %0, %1;" : "=r"(u) : "f"(f));
    return u;
}
__device__ __forceinline__ float tanha(float x) {
    float y;
    asm("tanh.approx.f32 %0, %1;" : "=f"(y) : "f"(x));
    return y;
}
__device__ __forceinline__ float siga(float x) { return 0.5f*tanha(0.5f*x) + 0.5f; }

#define MMA_TF32(c0,c1,c2,c3,a0,a1,a2,a3,b0,b1) \
    asm volatile("mma.sync.aligned.m16n8k8.row.col.f32.tf32.tf32.f32 " \
        "{%0,%1,%2,%3}, {%4,%5,%6,%7}, {%8,%9}, {%0,%1,%2,%3};" \
        : "+f"(c0), "+f"(c1), "+f"(c2), "+f"(c3) \
        : "r"(a0), "r"(a1), "r"(a2), "r"(a3), "r"(b0), "r"(b1))

// ---------------- adjacency ----------------
__global__ void k_adj(const float* __restrict__ e1, const float* __restrict__ e2) {
    int m = blockIdx.x;
    int n = threadIdx.x;            // 256 threads
    float a = 0.f;
#pragma unroll
    for (int k = 0; k < 32; k++) a = fmaf(e1[m*32 + k], e2[k*256 + n], a);
    a = fmaxf(a, 0.f);
    __shared__ float red[256];
    red[n] = a; __syncthreads();
    for (int s = 128; s > 0; s >>= 1) { if (n < s) red[n] = fmaxf(red[n], red[n+s]); __syncthreads(); }
    float mx = red[0]; __syncthreads();
    float e = expf(a - mx);
    red[n] = e; __syncthreads();
    for (int s = 128; s > 0; s >>= 1) { if (n < s) red[n] += red[n+s]; __syncthreads(); }
    g_ADPu[m*256 + n] = f2tf32(e / red[0]);
}

// ---------------- fused QKV + temporal attention, 512 threads, 4 barriers ----------------
// smem words (225024 B): Hs(Hj)@0 8704, Qi(Hi)@8704 8704,
// Wks@17408, Wvs@21760, Wqs@26112 (each 4352), Qst@30464 8704,
// Ks@39168 8704, Vt@47872 [64][129] 8256, biasr@56128 128.
// P [128][132] fp32/tf32 overlays Hs+Qi after phase 2.
__global__ void __launch_bounds__(512, 1) k_attn(
        const float* __restrict__ Hi, const float* __restrict__ Hj,
        const float* __restrict__ Wq, const float* __restrict__ bq,
        const float* __restrict__ Wk, const float* __restrict__ bk,
        const float* __restrict__ Wv, const float* __restrict__ bv,
        const float* __restrict__ lg, const float* __restrict__ lt) {
    extern __shared__ float sm[];
    unsigned* Hs  = (unsigned*)sm;
    unsigned* Qi  = Hs + 8704;
    unsigned* Wks = Hs + 17408;
    unsigned* Wvs = Hs + 21760;
    unsigned* Wqs = Hs + 26112;
    unsigned* Qst = Hs + 30464;
    unsigned* Ks  = Hs + 39168;
    unsigned* Vt  = Hs + 47872;
    float* biasr  = sm + 56128;
    float*    Ps  = sm;             // overlays Hs+Qi
    unsigned* Pu  = (unsigned*)sm;

    int tid = threadIdx.x;
    int bn = blockIdx.x;
    int b = bn >> 8, n = bn & 255;

    float gamma = fmaxf(expf(*lg), 0.01f);
    float tau   = fmaxf(expf(*lt), 0.01f);
    float scale = 1.0f / (8.0f * tau);
    if (tid < 128) biasr[tid] = logf(expf(-gamma * (float)tid * (1.0f/127.0f)) + 1e-8f);

    int w = tid >> 5, lane = tid & 31;
    int qr = lane >> 2, kc = lane & 3;
    int wp = w >> 1, side = w & 1;
    int mrow = wp*16 + qr;

    // ---- phase 1: ALL loads ----
    for (int idx = tid; idx < 2048; idx += 512) {
        int i = idx >> 4, c4 = idx & 15;
        size_t g = ((size_t)(b*Tt + i)*Nn + n)*Dd + c4*4;
        float4 hj = *(const float4*)(Hj + g);
        float4 hi = *(const float4*)(Hi + g);
        uint4 pj; pj.x=f2tf32(hj.x); pj.y=f2tf32(hj.y); pj.z=f2tf32(hj.z); pj.w=f2tf32(hj.w);
        uint4 pi; pi.x=f2tf32(hi.x); pi.y=f2tf32(hi.y); pi.z=f2tf32(hi.z); pi.w=f2tf32(hi.w);
        *(uint4*)(Hs + i*68 + c4*4) = pj;
        *(uint4*)(Qi + i*68 + c4*4) = pi;
    }
    for (int idx = tid; idx < 1024; idx += 512) {
        int r = idx >> 4, c4 = idx & 15;
        float4 wk = *(const float4*)(Wk + (size_t)r*64 + c4*4);
        float4 wv = *(const float4*)(Wv + (size_t)r*64 + c4*4);
        float4 wq = *(const float4*)(Wq + (size_t)r*64 + c4*4);
        uint4 pk; pk.x=f2tf32(wk.x); pk.y=f2tf32(wk.y); pk.z=f2tf32(wk.z); pk.w=f2tf32(wk.w);
        uint4 pv; pv.x=f2tf32(wv.x); pv.y=f2tf32(wv.y); pv.z=f2tf32(wv.z); pv.w=f2tf32(wv.w);
        uint4 pq; pq.x=f2tf32(wq.x); pq.y=f2tf32(wq.y); pq.z=f2tf32(wq.z); pq.w=f2tf32(wq.w);
        *(uint4*)(Wks + r*68 + c4*4) = pk;
        *(uint4*)(Wvs + r*68 + c4*4) = pv;
        *(uint4*)(Wqs + r*68 + c4*4) = pq;
    }
    __syncthreads();

    // ---- phase 2: K, V, Q gemms (all outputs disjoint from inputs) ----
    {
        unsigned aH[8][4];
#pragma unroll
        for (int ks = 0; ks < 8; ks++) {
            aH[ks][0] = Hs[mrow*68 + ks*8 + kc];
            aH[ks][1] = Hs[(mrow+8)*68 + ks*8 + kc];
            aH[ks][2] = Hs[mrow*68 + ks*8 + kc + 4];
            aH[ks][3] = Hs[(mrow+8)*68 + ks*8 + kc + 4];
        }
        float cK[4][4], cV[4][4];
#pragma unroll
        for (int nt = 0; nt < 4; nt++) {
            cK[nt][0]=0.f; cK[nt][1]=0.f; cK[nt][2]=0.f; cK[nt][3]=0.f;
            cV[nt][0]=0.f; cV[nt][1]=0.f; cV[nt][2]=0.f; cV[nt][3]=0.f;
            int ncol = side*32 + nt*8 + qr;
#pragma unroll
            for (int ks = 0; ks < 8; ks++) {
                unsigned bk0 = Wks[ncol*68 + ks*8 + kc];
                unsigned bk1 = Wks[ncol*68 + ks*8 + kc + 4];
                unsigned bv0 = Wvs[ncol*68 + ks*8 + kc];
                unsigned bv1 = Wvs[ncol*68 + ks*8 + kc + 4];
                MMA_TF32(cK[nt][0],cK[nt][1],cK[nt][2],cK[nt][3],
                         aH[ks][0],aH[ks][1],aH[ks][2],aH[ks][3], bk0,bk1);
                MMA_TF32(cV[nt][0],cV[nt][1],cV[nt][2],cV[nt][3],
                         aH[ks][0],aH[ks][1],aH[ks][2],aH[ks][3], bv0,bv1);
            }
        }
#pragma unroll
        for (int nt = 0; nt < 4; nt++) {
            int d = side*32 + nt*8 + 2*kc;
            float bkx = bk[d], bky = bk[d+1];
            Ks[mrow*68 + d]       = f2tf32(cK[nt][0] + bkx);
            Ks[mrow*68 + d + 1]   = f2tf32(cK[nt][1] + bky);
            Ks[(mrow+8)*68 + d]     = f2tf32(cK[nt][2] + bkx);
            Ks[(mrow+8)*68 + d + 1] = f2tf32(cK[nt][3] + bky);
            float bvx = bv[d], bvy = bv[d+1];
            Vt[d*129 + mrow]         = f2tf32(cV[nt][0] + bvx);
            Vt[(d+1)*129 + mrow]     = f2tf32(cV[nt][1] + bvy);
            Vt[d*129 + mrow + 8]     = f2tf32(cV[nt][2] + bvx);
            Vt[(d+1)*129 + mrow + 8] = f2tf32(cV[nt][3] + bvy);
        }
        unsigned aI[8][4];
#pragma unroll
        for (int ks = 0; ks < 8; ks++) {
            aI[ks][0] = Qi[mrow*68 + ks*8 + kc];
            aI[ks][1] = Qi[(mrow+8)*68 + ks*8 + kc];
            aI[ks][2] = Qi[mrow*68 + ks*8 + kc + 4];
            aI[ks][3] = Qi[(mrow+8)*68 + ks*8 + kc + 4];
        }
        float cQ[4][4];
#pragma unroll
        for (int nt = 0; nt < 4; nt++) {
            cQ[nt][0]=0.f; cQ[nt][1]=0.f; cQ[nt][2]=0.f; cQ[nt][3]=0.f;
            int ncol = side*32 + nt*8 + qr;
#pragma unroll
            for (int ks = 0; ks < 8; ks++) {
                unsigned b0 = Wqs[ncol*68 + ks*8 + kc];
                unsigned b1 = Wqs[ncol*68 + ks*8 + kc + 4];
                MMA_TF32(cQ[nt][0],cQ[nt][1],cQ[nt][2],cQ[nt][3],
                         aI[ks][0],aI[ks][1],aI[ks][2],aI[ks][3], b0,b1);
            }
        }
#pragma unroll
        for (int nt = 0; nt < 4; nt++) {
            int d = side*32 + nt*8 + 2*kc;
            float bx = bq[d], by = bq[d+1];
            Qst[mrow*68 + d]       = f2tf32(cQ[nt][0] + bx);
            Qst[mrow*68 + d + 1]   = f2tf32(cQ[nt][1] + by);
            Qst[(mrow+8)*68 + d]     = f2tf32(cQ[nt][2] + bx);
            Qst[(mrow+8)*68 + d + 1] = f2tf32(cQ[nt][3] + by);
        }
    }
    __syncthreads();

    // ---- phase 3: S = Q K^T, write P (overlays dead Hs/Qi) ----
    unsigned a[8][4];
#pragma unroll
    for (int ks = 0; ks < 8; ks++) {
        a[ks][0] = Qst[mrow*68 + ks*8 + kc];
        a[ks][1] = Qst[(mrow+8)*68 + ks*8 + kc];
        a[ks][2] = Qst[mrow*68 + ks*8 + kc + 4];
        a[ks][3] = Qst[(mrow+8)*68 + ks*8 + kc + 4];
    }
    float c[8][4];
#pragma unroll
    for (int nt = 0; nt < 8; nt++) { c[nt][0]=0.f; c[nt][1]=0.f; c[nt][2]=0.f; c[nt][3]=0.f; }
#pragma unroll
    for (int nt = 0; nt < 8; nt++) {
        int ncol = side*64 + nt*8 + qr;
#pragma unroll
        for (int ks = 0; ks < 8; ks++) {
            unsigned b0 = Ks[ncol*68 + ks*8 + kc];
            unsigned b1 = Ks[ncol*68 + ks*8 + kc + 4];
            MMA_TF32(c[nt][0],c[nt][1],c[nt][2],c[nt][3],
                     a[ks][0],a[ks][1],a[ks][2],a[ks][3], b0,b1);
        }
    }
    int i1 = mrow, i2 = mrow + 8;
#pragma unroll
    for (int nt = 0; nt < 8; nt++) {
        int j0 = side*64 + nt*8 + 2*kc;
        int d10 = i1 - j0;     d10 = d10 < 0 ? -d10 : d10;
        int d11 = i1 - j0 - 1; d11 = d11 < 0 ? -d11 : d11;
        int d20 = i2 - j0;     d20 = d20 < 0 ? -d20 : d20;
        int d21 = i2 - j0 - 1; d21 = d21 < 0 ? -d21 : d21;
        Ps[i1*132 + j0]     = c[nt][0]*scale + biasr[d10];
        Ps[i1*132 + j0 + 1] = c[nt][1]*scale + biasr[d11];
        Ps[i2*132 + j0]     = c[nt][2]*scale + biasr[d20];
        Ps[i2*132 + j0 + 1] = c[nt][3]*scale + biasr[d21];
    }
    __syncthreads();

    // ---- phase 4: softmax, write P tf32 ----
    for (int rr = 0; rr < 8; rr++) {
        int i = w*8 + rr;
        float v0 = Ps[i*132 + lane], v1 = Ps[i*132 + lane + 32],
              v2 = Ps[i*132 + lane + 64], v3 = Ps[i*132 + lane + 96];
        float mx = fmaxf(fmaxf(v0, v1), fmaxf(v2, v3));
#pragma unroll
        for (int off = 16; off > 0; off >>= 1) mx = fmaxf(mx, __shfl_xor_sync(0xffffffff, mx, off));
        float e0 = __expf(v0 - mx), e1 = __expf(v1 - mx), e2 = __expf(v2 - mx), e3 = __expf(v3 - mx);
        float su = (e0 + e1) + (e2 + e3);
#pragma unroll
        for (int off = 16; off > 0; off >>= 1) su += __shfl_xor_sync(0xffffffff, su, off);
        float inv = 1.0f / su;
        Pu[i*132 + lane]      = f2tf32(e0 * inv);
        Pu[i*132 + lane + 32] = f2tf32(e1 * inv);
        Pu[i*132 + lane + 64] = f2tf32(e2 * inv);
        Pu[i*132 + lane + 96] = f2tf32(e3 * inv);
    }
    __syncthreads();

    // ---- phase 5: out = P @ V ----
    float c2[4][4];
#pragma unroll
    for (int nt = 0; nt < 4; nt++) { c2[nt][0]=0.f; c2[nt][1]=0.f; c2[nt][2]=0.f; c2[nt][3]=0.f; }
#pragma unroll
    for (int ks = 0; ks < 16; ks++) {
        unsigned a0 = Pu[mrow*132 + ks*8 + kc];
        unsigned a1 = Pu[(mrow+8)*132 + ks*8 + kc];
        unsigned a2 = Pu[mrow*132 + ks*8 + kc + 4];
        unsigned a3 = Pu[(mrow+8)*132 + ks*8 + kc + 4];
#pragma unroll
        for (int nt = 0; nt < 4; nt++) {
            int dcol = side*32 + nt*8 + qr;
            unsigned b0 = Vt[dcol*129 + ks*8 + kc];
            unsigned b1 = Vt[dcol*129 + ks*8 + kc + 4];
            MMA_TF32(c2[nt][0],c2[nt][1],c2[nt][2],c2[nt][3], a0,a1,a2,a3, b0,b1);
        }
    }
#pragma unroll
    for (int nt = 0; nt < 4; nt++) {
        int d = side*32 + nt*8 + 2*kc;
        float2 o0; o0.x = c2[nt][0]; o0.y = c2[nt][1];
        float2 o1; o1.x = c2[nt][2]; o1.y = c2[nt][3];
        *(float2*)(g_ALN + ((size_t)(b*Tt + mrow)*Nn + n)*Dd + d)     = o0;
        *(float2*)(g_ALN + ((size_t)(b*Tt + mrow + 8)*Nn + n)*Dd + d) = o1;
    }
}

// ---------------- GCN + residual + LN1, 512 threads, X-chunk prefetch ----------------
__global__ void __launch_bounds__(512, 2) k_gcn(const float* __restrict__ Wg,
                                                const float* __restrict__ bg,
                                                const float* __restrict__ ln1g,
                                                const float* __restrict__ ln1b) {
    extern __shared__ float sg[];
    unsigned* As  = (unsigned*)sg;
    unsigned* Bs  = As + 8704;
    unsigned* Tmp = As + 12864;
    unsigned* Wgs = As + 21568;
    float* h2 = sg;   // overlays As

    int tid = threadIdx.x;
    int blk = blockIdx.x;
    int bt = blk >> 1, half = blk & 1;
    int m0g = half * 128;
    int b = bt >> 7, t = bt & 127;
    const float* Xbt = g_ALN + (size_t)bt * 16384;

    int w = tid >> 5, lane = tid & 31;
    int qr = lane >> 2, kc = lane & 3;
    int wp = w >> 1, side = w & 1;
    int mrow = wp*16 + qr;

    for (int idx = tid; idx < 1024; idx += 512) {
        int r = idx >> 4, c4 = idx & 15;
        float4 wv = *(const float4*)(Wg + (size_t)r*64 + c4*4);
        uint4 pv; pv.x = f2tf32(wv.x); pv.y = f2tf32(wv.y);
        pv.z = f2tf32(wv.z); pv.w = f2tf32(wv.w);
        *(uint4*)(Wgs + r*68 + c4*4) = pv;
    }

    float c1[4][4];
#pragma unroll
    for (int nt = 0; nt < 4; nt++) { c1[nt][0]=0.f; c1[nt][1]=0.f; c1[nt][2]=0.f; c1[nt][3]=0.f; }

    // prefetch chunk 0 of X into regs
    float4 pb[2];
#pragma unroll
    for (int j = 0; j < 2; j++) {
        int idx = tid + j*512;
        int nn = idx >> 4, c4 = idx & 15;
        pb[j] = *(const float4*)(Xbt + (size_t)nn*64 + c4*4);
    }

    for (int ch = 0; ch < 4; ch++) {
        __syncthreads();
        for (int idx = tid; idx < 2048; idx += 512) {
            int r = idx >> 4, c4 = idx & 15;
            *(uint4*)(As + r*68 + c4*4) =
                *(const uint4*)(g_ADPu + (size_t)(m0g + r)*256 + ch*64 + c4*4);
        }
#pragma unroll
        for (int j = 0; j < 2; j++) {
            int idx = tid + j*512;
            int nn = idx >> 4, c4 = idx & 15;
            Bs[(c4*4+0)*65 + nn] = f2tf32(pb[j].x);
            Bs[(c4*4+1)*65 + nn] = f2tf32(pb[j].y);
            Bs[(c4*4+2)*65 + nn] = f2tf32(pb[j].z);
            Bs[(c4*4+3)*65 + nn] = f2tf32(pb[j].w);
        }
        __syncthreads();
        if (ch < 3) {
#pragma unroll
            for (int j = 0; j < 2; j++) {
                int idx = tid + j*512;
                int nn = idx >> 4, c4 = idx & 15;
                pb[j] = *(const float4*)(Xbt + (size_t)((ch+1)*64 + nn)*64 + c4*4);
            }
        }
#pragma unroll
        for (int ks = 0; ks < 8; ks++) {
            unsigned a0 = As[mrow*68 + ks*8 + kc];
            unsigned a1 = As[(mrow+8)*68 + ks*8 + kc];
            unsigned a2 = As[mrow*68 + ks*8 + kc + 4];
            unsigned a3 = As[(mrow+8)*68 + ks*8 + kc + 4];
#pragma unroll
            for (int nt = 0; nt < 4; nt++) {
                int dcol = side*32 + nt*8 + qr;
                unsigned b0 = Bs[dcol*65 + ks*8 + kc];
                unsigned b1 = Bs[dcol*65 + ks*8 + kc + 4];
                MMA_TF32(c1[nt][0],c1[nt][1],c1[nt][2],c1[nt][3], a0,a1,a2,a3, b0,b1);
            }
        }
    }

#pragma unroll
    for (int nt = 0; nt < 4; nt++) {
        int d0 = side*32 + nt*8 + 2*kc;
        Tmp[mrow*68 + d0]       = f2tf32(c1[nt][0]);
        Tmp[mrow*68 + d0 + 1]   = f2tf32(c1[nt][1]);
        Tmp[(mrow+8)*68 + d0]     = f2tf32(c1[nt][2]);
        Tmp[(mrow+8)*68 + d0 + 1] = f2tf32(c1[nt][3]);
    }
    __syncthreads();

    float c2[4][4];
#pragma unroll
    for (int nt = 0; nt < 4; nt++) { c2[nt][0]=0.f; c2[nt][1]=0.f; c2[nt][2]=0.f; c2[nt][3]=0.f; }
#pragma unroll
    for (int ks = 0; ks < 8; ks++) {
        unsigned a0 = Tmp[mrow*68 + ks*8 + kc];
        unsigned a1 = Tmp[(mrow+8)*68 + ks*8 + kc];
        unsigned a2 = Tmp[mrow*68 + ks*8 + kc + 4];
        unsigned a3 = Tmp[(mrow+8)*68 + ks*8 + kc + 4];
#pragma unroll
        for (int nt = 0; nt < 4; nt++) {
            int ncol = side*32 + nt*8 + qr;
            unsigned b0 = Wgs[ncol*68 + ks*8 + kc];
            unsigned b1 = Wgs[ncol*68 + ks*8 + kc + 4];
            MMA_TF32(c2[nt][0],c2[nt][1],c2[nt][2],c2[nt][3], a0,a1,a2,a3, b0,b1);
        }
    }
    __syncthreads();

#pragma unroll
    for (int nt = 0; nt < 4; nt++) {
        int e0 = side*32 + nt*8 + 2*kc;
        float bx = bg[e0], by = bg[e0+1];
        h2[mrow*68 + e0]       = fmaxf(c2[nt][0] + bx, 0.f);
        h2[mrow*68 + e0 + 1]   = fmaxf(c2[nt][1] + by, 0.f);
        h2[(mrow+8)*68 + e0]     = fmaxf(c2[nt][2] + bx, 0.f);
        h2[(mrow+8)*68 + e0 + 1] = fmaxf(c2[nt][3] + by, 0.f);
    }
    __syncthreads();

    float gg0 = ln1g[lane], gg1 = ln1g[lane+32];
    float bb0 = ln1b[lane], bb1 = ln1b[lane+32];
    for (int mm = 0; mm < 8; mm++) {
        int m = w*8 + mm;
        const float* xr = Xbt + (size_t)(m0g + m)*64;
        float u0 = xr[lane]      + h2[m*68 + lane];
        float u1 = xr[lane + 32] + h2[m*68 + lane + 32];
        float su = u0 + u1;
#pragma unroll
        for (int off = 16; off > 0; off >>= 1) su += __shfl_xor_sync(0xffffffff, su, off);
        float mean = su * (1.0f/64.0f);
        float dd0 = u0 - mean, dd1 = u1 - mean;
        float q = dd0*dd0 + dd1*dd1;
#pragma unroll
        for (int off = 16; off > 0; off >>= 1) q += __shfl_xor_sync(0xffffffff, q, off);
        float rs = rsqrtf(q*(1.0f/64.0f) + 1e-5f);
        size_t o = ((size_t)(b*Nn + m0g + m)*Tt + t)*Dd;
        g_X1[o + lane]      = dd0*rs*gg0 + bb0;
        g_X1[o + lane + 32] = dd1*rs*gg1 + bb1;
    }
}

// ---------------- tensor-core GRU with half-chunk prefetch ----------------
__global__ void __launch_bounds__(256) k_gru_tc(const float* __restrict__ Whh,
                                                const float* __restrict__ bhh,
                                                const float* __restrict__ Wih,
                                                const float* __restrict__ bih,
                                                const float* __restrict__ ln2g,
                                                const float* __restrict__ ln2b,
                                                float* __restrict__ out) {
    extern __shared__ unsigned su_[];
    unsigned* Whs = su_;
    unsigned* Wis = su_ + 13056;
    unsigned* X1s = su_;
    float*    X1f = (float*)(su_ + 4352);
    unsigned* Hb0 = su_ + 8704;
    unsigned* Hb1 = su_ + 9792;
    float*    U4  = (float*)(su_ + 10880);

    int tid = threadIdx.x;
    int w = tid >> 5, lane = tid & 31;
    int qr = lane >> 2, kc = lane & 3;
    int s_base = blockIdx.x * 16;
    int b = s_base >> 8;
    int node0 = s_base & 255;

    for (int idx = tid; idx < 3072; idx += 256) {
        int r = idx >> 4, c4 = idx & 15;
        float4 wv = *(const float4*)(Whh + (size_t)r*64 + c4*4);
        uint4 pv; pv.x = f2tf32(wv.x); pv.y = f2tf32(wv.y);
        pv.z = f2tf32(wv.z); pv.w = f2tf32(wv.w);
        *(uint4*)(Whs + r*68 + c4*4) = pv;
        float4 iv = *(const float4*)(Wih + (size_t)r*64 + c4*4);
        uint4 qv; qv.x = f2tf32(iv.x); qv.y = f2tf32(iv.y);
        qv.z = f2tf32(iv.z); qv.w = f2tf32(iv.w);
        *(uint4*)(Wis + r*68 + c4*4) = qv;
    }
    __syncthreads();

    unsigned br_[8][2], bz_[8][2], bn_[8][2];
    unsigned wr_[8][2], wz_[8][2], wn_[8][2];
#pragma unroll
    for (int ks = 0; ks < 8; ks++) {
        int nr = (0*64 + w*8 + qr)*68 + ks*8 + kc;
        int nz = (1*64 + w*8 + qr)*68 + ks*8 + kc;
        int nn = (2*64 + w*8 + qr)*68 + ks*8 + kc;
        br_[ks][0] = Whs[nr]; br_[ks][1] = Whs[nr + 4];
        bz_[ks][0] = Whs[nz]; bz_[ks][1] = Whs[nz + 4];
        bn_[ks][0] = Whs[nn]; bn_[ks][1] = Whs[nn + 4];
        wr_[ks][0] = Wis[nr]; wr_[ks][1] = Wis[nr + 4];
        wz_[ks][0] = Wis[nz]; wz_[ks][1] = Wis[nz + 4];
        wn_[ks][0] = Wis[nn]; wn_[ks][1] = Wis[nn + 4];
    }
    __syncthreads();

    for (int idx = tid; idx < 1088; idx += 256) Hb0[idx] = 0;

    int col0 = w*8 + 2*kc;
    float2 bhr = *(const float2*)(bhh + col0);
    float2 bhz = *(const float2*)(bhh + 64 + col0);
    float2 bhn = *(const float2*)(bhh + 128 + col0);
    float2 bir = *(const float2*)(bih + col0);
    float2 biz = *(const float2*)(bih + 64 + col0);
    float2 bin_ = *(const float2*)(bih + 128 + col0);
    float g2a = ln2g[lane], g2b = ln2g[lane+32];
    float b2a = ln2b[lane], b2b = ln2b[lane+32];

    float h_old[4] = {0.f, 0.f, 0.f, 0.f};

    // prefetch chunk 0 first half (steps s=0,1)
    float px[8];
#pragma unroll
    for (int i = 0; i < 8; i++) {
        int idx = tid + i*256;
        int s = idx >> 10, rem = idx & 1023, row = rem >> 6, col = rem & 63;
        px[i] = g_X1[(size_t)(s_base + row)*Tt*Dd + (size_t)s*Dd + col];
    }

    for (int tc = 0; tc < Tt; tc += 4) {
        __syncthreads();

        // store prefetched first half, load+store second half
#pragma unroll
        for (int i = 0; i < 8; i++) {
            int idx = tid + i*256;
            int s = idx >> 10, rem = idx & 1023, row = rem >> 6, col = rem & 63;
            X1s[s*1088 + row*68 + col] = f2tf32(px[i]);
            X1f[s*1088 + row*68 + col] = px[i];
        }
#pragma unroll
        for (int i = 8; i < 16; i++) {
            int idx = tid + i*256;
            int s = idx >> 10, rem = idx & 1023, row = rem >> 6, col = rem & 63;
            float v = g_X1[(size_t)(s_base + row)*Tt*Dd + (size_t)(tc + s)*Dd + col];
            X1s[s*1088 + row*68 + col] = f2tf32(v);
            X1f[s*1088 + row*68 + col] = v;
        }
        __syncthreads();

        // prefetch next chunk first half (overlaps gi + serial section)
        if (tc + 4 < Tt) {
#pragma unroll
            for (int i = 0; i < 8; i++) {
                int idx = tid + i*256;
                int s = idx >> 10, rem = idx & 1023, row = rem >> 6, col = rem & 63;
                px[i] = g_X1[(size_t)(s_base + row)*Tt*Dd + (size_t)(tc + 4 + s)*Dd + col];
            }
        }

        float gr_[4][4], gz_[4][4], gn_[4][4];
#pragma unroll
        for (int s = 0; s < 4; s++) {
            const unsigned* Xc = X1s + s*1088;
            unsigned ax[8][4];
#pragma unroll
            for (int ks = 0; ks < 8; ks++) {
                ax[ks][0] = Xc[qr*68 + ks*8 + kc];
                ax[ks][1] = Xc[(qr+8)*68 + ks*8 + kc];
                ax[ks][2] = Xc[qr*68 + ks*8 + kc + 4];
                ax[ks][3] = Xc[(qr+8)*68 + ks*8 + kc + 4];
            }
            gr_[s][0]=0.f; gr_[s][1]=0.f; gr_[s][2]=0.f; gr_[s][3]=0.f;
            gz_[s][0]=0.f; gz_[s][1]=0.f; gz_[s][2]=0.f; gz_[s][3]=0.f;
            gn_[s][0]=0.f; gn_[s][1]=0.f; gn_[s][2]=0.f; gn_[s][3]=0.f;
#pragma unroll
            for (int ks = 0; ks < 8; ks++) {
                MMA_TF32(gr_[s][0],gr_[s][1],gr_[s][2],gr_[s][3], ax[ks][0],ax[ks][1],ax[ks][2],ax[ks][3], wr_[ks][0],wr_[ks][1]);
                MMA_TF32(gz_[s][0],gz_[s][1],gz_[s][2],gz_[s][3], ax[ks][0],ax[ks][1],ax[ks][2],ax[ks][3], wz_[ks][0],wz_[ks][1]);
                MMA_TF32(gn_[s][0],gn_[s][1],gn_[s][2],gn_[s][3], ax[ks][0],ax[ks][1],ax[ks][2],ax[ks][3], wn_[ks][0],wn_[ks][1]);
            }
        }

#pragma unroll
        for (int s = 0; s < 4; s++) {
            int t = tc + s;
            unsigned* Hc = (t & 1) ? Hb1 : Hb0;
            unsigned* Hn = (t & 1) ? Hb0 : Hb1;
            float* Us = U4 + s*1088;
            const float* Xf = X1f + s*1088;

            float2 xa = *(const float2*)(Xf + qr*68 + col0);
            float2 xb = *(const float2*)(Xf + (qr+8)*68 + col0);

            float cr[4] = {0.f,0.f,0.f,0.f}, cz[4] = {0.f,0.f,0.f,0.f}, cn[4] = {0.f,0.f,0.f,0.f};
            {
                unsigned a[8][4];
#pragma unroll
                for (int ks = 0; ks < 8; ks++) {
                    a[ks][0] = Hc[qr*68 + ks*8 + kc];
                    a[ks][1] = Hc[(qr+8)*68 + ks*8 + kc];
                    a[ks][2] = Hc[qr*68 + ks*8 + kc + 4];
                    a[ks][3] = Hc[(qr+8)*68 + ks*8 + kc + 4];
                }
#pragma unroll
                for (int ks = 0; ks < 8; ks++) {
                    MMA_TF32(cr[0],cr[1],cr[2],cr[3], a[ks][0],a[ks][1],a[ks][2],a[ks][3], br_[ks][0],br_[ks][1]);
                    MMA_TF32(cz[0],cz[1],cz[2],cz[3], a[ks][0],a[ks][1],a[ks][2],a[ks][3], bz_[ks][0],bz_[ks][1]);
                    MMA_TF32(cn[0],cn[1],cn[2],cn[3], a[ks][0],a[ks][1],a[ks][2],a[ks][3], bn_[ks][0],bn_[ks][1]);
                }
            }

            float r0 = siga(gr_[s][0] + bir.x + cr[0] + bhr.x);
            float r1 = siga(gr_[s][1] + bir.y + cr[1] + bhr.y);
            float r2 = siga(gr_[s][2] + bir.x + cr[2] + bhr.x);
            float r3 = siga(gr_[s][3] + bir.y + cr[3] + bhr.y);
            float z0 = siga(gz_[s][0] + biz.x + cz[0] + bhz.x);
            float z1 = siga(gz_[s][1] + biz.y + cz[1] + bhz.y);
            float z2 = siga(gz_[s][2] + biz.x + cz[2] + bhz.x);
            float z3 = siga(gz_[s][3] + biz.y + cz[3] + bhz.y);
            float n0 = tanha(gn_[s][0] + bin_.x + r0*(cn[0] + bhn.x));
            float n1 = tanha(gn_[s][1] + bin_.y + r1*(cn[1] + bhn.y));
            float n2 = tanha(gn_[s][2] + bin_.x + r2*(cn[2] + bhn.x));
            float n3 = tanha(gn_[s][3] + bin_.y + r3*(cn[3] + bhn.y));
            float h0 = (1.f - z0)*n0 + z0*h_old[0];
            float h1 = (1.f - z1)*n1 + z1*h_old[1];
            float h2v = (1.f - z2)*n2 + z2*h_old[2];
            float h3 = (1.f - z3)*n3 + z3*h_old[3];
            h_old[0] = h0; h_old[1] = h1; h_old[2] = h2v; h_old[3] = h3;

            uint2 hp0; hp0.x = f2tf32(h0); hp0.y = f2tf32(h1);
            uint2 hp1; hp1.x = f2tf32(h2v); hp1.y = f2tf32(h3);
            *(uint2*)(Hn + qr*68 + col0)     = hp0;
            *(uint2*)(Hn + (qr+8)*68 + col0) = hp1;
            float2 up0; up0.x = xa.x + h0; up0.y = xa.y + h1;
            float2 up1; up1.x = xb.x + h2v; up1.y = xb.y + h3;
            *(float2*)(Us + qr*68 + col0)     = up0;
            *(float2*)(Us + (qr+8)*68 + col0) = up1;
            __syncthreads();
        }

#pragma unroll
        for (int rr = 0; rr < 8; rr++) {
            int inst = w*8 + rr;
            int s = inst >> 4, row = inst & 15;
            const float* Us = U4 + s*1088;
            const float* Xf = X1f + s*1088;
            float v0 = Us[row*68 + lane], v1 = Us[row*68 + lane + 32];
            float sv = v0 + v1, qv = v0*v0 + v1*v1;
#pragma unroll
            for (int off = 16; off > 0; off >>= 1) {
                sv += __shfl_xor_sync(0xffffffff, sv, off);
                qv += __shfl_xor_sync(0xffffffff, qv, off);
            }
            float mean = sv * (1.0f/64.0f);
            float var = qv*(1.0f/64.0f) - mean*mean;
            float rs = rsqrtf(var + 1e-5f);
            float x0v = Xf[row*68 + lane], x1v = Xf[row*68 + lane + 32];
            size_t oo = (size_t)b*Tt*Nn*Dd + (size_t)(tc + s)*Nn*Dd + (size_t)(node0 + row)*Dd;
            out[oo + lane]      = x0v + (v0 - mean)*rs*g2a + b2a;
            out[oo + lane + 32] = x1v + (v1 - mean)*rs*g2b + b2b;
        }
    }
}

// ---------------- launcher ----------------
extern "C" void kernel_launch(void* const* d_in, const int* in_sizes, int n_in,
                              void* d_out, int out_size) {
    (void)in_sizes; (void)n_in; (void)out_size;
    const float* H_i  = (const float*)d_in[0];
    const float* H_j  = (const float*)d_in[1];
    const float* Wq   = (const float*)d_in[2];
    const float* bq   = (const float*)d_in[3];
    const float* Wk   = (const float*)d_in[4];
    const float* bk   = (const float*)d_in[5];
    const float* Wv   = (const float*)d_in[6];
    const float* bv   = (const float*)d_in[7];
    const float* lgam = (const float*)d_in[8];
    const float* ltau = (const float*)d_in[9];
    const float* e1   = (const float*)d_in[10];
    const float* e2   = (const float*)d_in[11];
    const float* Wg   = (const float*)d_in[12];
    const float* bg   = (const float*)d_in[13];
    const float* ln1g = (const float*)d_in[14];
    const float* ln1b = (const float*)d_in[15];
    const float* Wih  = (const float*)d_in[16];
    const float* Whh  = (const float*)d_in[17];
    const float* bih  = (const float*)d_in[18];
    const float* bhh  = (const float*)d_in[19];
    const float* ln2g = (const float*)d_in[20];
    const float* ln2b = (const float*)d_in[21];
    float* out = (float*)d_out;

    const int ATTN_SMEM = 56256 * 4;   // 225024 B
    const int GCN_SMEM  = 25920 * 4;   // 103680 B
    const int GRU_SMEM  = 26112 * 4;   // 104448 B
    cudaFuncSetAttribute(k_attn, cudaFuncAttributeMaxDynamicSharedMemorySize, ATTN_SMEM);
    cudaFuncSetAttribute(k_gcn,  cudaFuncAttributeMaxDynamicSharedMemorySize, GCN_SMEM);
    cudaFuncSetAttribute(k_gru_tc, cudaFuncAttributeMaxDynamicSharedMemorySize, GRU_SMEM);

    k_adj<<<256, 256>>>(e1, e2);
    k_attn<<<Bb*Nn, 512, ATTN_SMEM>>>(H_i, H_j, Wq, bq, Wk, bk, Wv, bv, lgam, ltau);
    k_gcn<<<Bb*Tt*2, 512, GCN_SMEM>>>(Wg, bg, ln1g, ln1b);
    k_gru_tc<<<Bb*Nn/16, 256, GRU_SMEM>>>(Whh, bhh, Wih, bih, ln2g, ln2b, out);
}

// round 15
// speedup vs baseline: 1.4443x; 1.0471x over previous
#include <cuda_runtime.h>
#include <math.h>

#define Bb 8
#define Tt 128
#define Nn 256
#define Dd 64
#define D3 192
#define BTND 16777216   // 8*128*256*64

// ---------------- device scratch ----------------
__device__ float g_ALN[BTND];          // aligner output, [B,T,N,D]
__device__ float g_X1[BTND];           // post-ln1, [B,N,T,D]
__device__ unsigned g_ADPu[Nn*Nn];     // adjacency, tf32 bits, row-major [m][n]

__device__ __forceinline__ unsigned f2tf32(float f) {
    unsigned u;
    asm("cvt.rna.tf32.f32 %0, %1;" : "=r"(u) : "f"(f));
    return u;
}
__device__ __forceinline__ float tanha(float x) {
    float y;
    asm("tanh.approx.f32 %0, %1;" : "=f"(y) : "f"(x));
    return y;
}
__device__ __forceinline__ float siga(float x) { return 0.5f*tanha(0.5f*x) + 0.5f; }

#define MMA_TF32(c0,c1,c2,c3,a0,a1,a2,a3,b0,b1) \
    asm volatile("mma.sync.aligned.m16n8k8.row.col.f32.tf32.tf32.f32 " \
        "{%0,%1,%2,%3}, {%4,%5,%6,%7}, {%8,%9}, {%0,%1,%2,%3};" \
        : "+f"(c0), "+f"(c1), "+f"(c2), "+f"(c3) \
        : "r"(a0), "r"(a1), "r"(a2), "r"(a3), "r"(b0), "r"(b1))

// ---------------- adjacency ----------------
__global__ void k_adj(const float* __restrict__ e1, const float* __restrict__ e2) {
    int m = blockIdx.x;
    int n = threadIdx.x;            // 256 threads
    float a = 0.f;
#pragma unroll
    for (int k = 0; k < 32; k++) a = fmaf(e1[m*32 + k], e2[k*256 + n], a);
    a = fmaxf(a, 0.f);
    __shared__ float red[256];
    red[n] = a; __syncthreads();
    for (int s = 128; s > 0; s >>= 1) { if (n < s) red[n] = fmaxf(red[n], red[n+s]); __syncthreads(); }
    float mx = red[0]; __syncthreads();
    float e = expf(a - mx);
    red[n] = e; __syncthreads();
    for (int s = 128; s > 0; s >>= 1) { if (n < s) red[n] += red[n+s]; __syncthreads(); }
    g_ADPu[m*256 + n] = f2tf32(e / red[0]);
}

// ---------------- fused QKV + temporal attention, 512 threads (unchanged R14) ----------------
__global__ void __launch_bounds__(512, 1) k_attn(
        const float* __restrict__ Hi, const float* __restrict__ Hj,
        const float* __restrict__ Wq, const float* __restrict__ bq,
        const float* __restrict__ Wk, const float* __restrict__ bk,
        const float* __restrict__ Wv, const float* __restrict__ bv,
        const float* __restrict__ lg, const float* __restrict__ lt) {
    extern __shared__ float sm[];
    unsigned* Hs  = (unsigned*)sm;
    unsigned* Qi  = Hs + 8704;
    unsigned* Wks = Hs + 17408;
    unsigned* Wvs = Hs + 21760;
    unsigned* Wqs = Hs + 26112;
    unsigned* Qst = Hs + 30464;
    unsigned* Ks  = Hs + 39168;
    unsigned* Vt  = Hs + 47872;
    float* biasr  = sm + 56128;
    float*    Ps  = sm;             // overlays Hs+Qi
    unsigned* Pu  = (unsigned*)sm;

    int tid = threadIdx.x;
    int bn = blockIdx.x;
    int b = bn >> 8, n = bn & 255;

    float gamma = fmaxf(expf(*lg), 0.01f);
    float tau   = fmaxf(expf(*lt), 0.01f);
    float scale = 1.0f / (8.0f * tau);
    if (tid < 128) biasr[tid] = logf(expf(-gamma * (float)tid * (1.0f/127.0f)) + 1e-8f);

    int w = tid >> 5, lane = tid & 31;
    int qr = lane >> 2, kc = lane & 3;
    int wp = w >> 1, side = w & 1;
    int mrow = wp*16 + qr;

    // ---- phase 1: ALL loads ----
    for (int idx = tid; idx < 2048; idx += 512) {
        int i = idx >> 4, c4 = idx & 15;
        size_t g = ((size_t)(b*Tt + i)*Nn + n)*Dd + c4*4;
        float4 hj = *(const float4*)(Hj + g);
        float4 hi = *(const float4*)(Hi + g);
        uint4 pj; pj.x=f2tf32(hj.x); pj.y=f2tf32(hj.y); pj.z=f2tf32(hj.z); pj.w=f2tf32(hj.w);
        uint4 pi; pi.x=f2tf32(hi.x); pi.y=f2tf32(hi.y); pi.z=f2tf32(hi.z); pi.w=f2tf32(hi.w);
        *(uint4*)(Hs + i*68 + c4*4) = pj;
        *(uint4*)(Qi + i*68 + c4*4) = pi;
    }
    for (int idx = tid; idx < 1024; idx += 512) {
        int r = idx >> 4, c4 = idx & 15;
        float4 wk = *(const float4*)(Wk + (size_t)r*64 + c4*4);
        float4 wv = *(const float4*)(Wv + (size_t)r*64 + c4*4);
        float4 wq = *(const float4*)(Wq + (size_t)r*64 + c4*4);
        uint4 pk; pk.x=f2tf32(wk.x); pk.y=f2tf32(wk.y); pk.z=f2tf32(wk.z); pk.w=f2tf32(wk.w);
        uint4 pv; pv.x=f2tf32(wv.x); pv.y=f2tf32(wv.y); pv.z=f2tf32(wv.z); pv.w=f2tf32(wv.w);
        uint4 pq; pq.x=f2tf32(wq.x); pq.y=f2tf32(wq.y); pq.z=f2tf32(wq.z); pq.w=f2tf32(wq.w);
        *(uint4*)(Wks + r*68 + c4*4) = pk;
        *(uint4*)(Wvs + r*68 + c4*4) = pv;
        *(uint4*)(Wqs + r*68 + c4*4) = pq;
    }
    __syncthreads();

    // ---- phase 2: K, V, Q gemms ----
    {
        unsigned aH[8][4];
#pragma unroll
        for (int ks = 0; ks < 8; ks++) {
            aH[ks][0] = Hs[mrow*68 + ks*8 + kc];
            aH[ks][1] = Hs[(mrow+8)*68 + ks*8 + kc];
            aH[ks][2] = Hs[mrow*68 + ks*8 + kc + 4];
            aH[ks][3] = Hs[(mrow+8)*68 + ks*8 + kc + 4];
        }
        float cK[4][4], cV[4][4];
#pragma unroll
        for (int nt = 0; nt < 4; nt++) {
            cK[nt][0]=0.f; cK[nt][1]=0.f; cK[nt][2]=0.f; cK[nt][3]=0.f;
            cV[nt][0]=0.f; cV[nt][1]=0.f; cV[nt][2]=0.f; cV[nt][3]=0.f;
            int ncol = side*32 + nt*8 + qr;
#pragma unroll
            for (int ks = 0; ks < 8; ks++) {
                unsigned bk0 = Wks[ncol*68 + ks*8 + kc];
                unsigned bk1 = Wks[ncol*68 + ks*8 + kc + 4];
                unsigned bv0 = Wvs[ncol*68 + ks*8 + kc];
                unsigned bv1 = Wvs[ncol*68 + ks*8 + kc + 4];
                MMA_TF32(cK[nt][0],cK[nt][1],cK[nt][2],cK[nt][3],
                         aH[ks][0],aH[ks][1],aH[ks][2],aH[ks][3], bk0,bk1);
                MMA_TF32(cV[nt][0],cV[nt][1],cV[nt][2],cV[nt][3],
                         aH[ks][0],aH[ks][1],aH[ks][2],aH[ks][3], bv0,bv1);
            }
        }
#pragma unroll
        for (int nt = 0; nt < 4; nt++) {
            int d = side*32 + nt*8 + 2*kc;
            float bkx = bk[d], bky = bk[d+1];
            Ks[mrow*68 + d]       = f2tf32(cK[nt][0] + bkx);
            Ks[mrow*68 + d + 1]   = f2tf32(cK[nt][1] + bky);
            Ks[(mrow+8)*68 + d]     = f2tf32(cK[nt][2] + bkx);
            Ks[(mrow+8)*68 + d + 1] = f2tf32(cK[nt][3] + bky);
            float bvx = bv[d], bvy = bv[d+1];
            Vt[d*129 + mrow]         = f2tf32(cV[nt][0] + bvx);
            Vt[(d+1)*129 + mrow]     = f2tf32(cV[nt][1] + bvy);
            Vt[d*129 + mrow + 8]     = f2tf32(cV[nt][2] + bvx);
            Vt[(d+1)*129 + mrow + 8] = f2tf32(cV[nt][3] + bvy);
        }
        unsigned aI[8][4];
#pragma unroll
        for (int ks = 0; ks < 8; ks++) {
            aI[ks][0] = Qi[mrow*68 + ks*8 + kc];
            aI[ks][1] = Qi[(mrow+8)*68 + ks*8 + kc];
            aI[ks][2] = Qi[mrow*68 + ks*8 + kc + 4];
            aI[ks][3] = Qi[(mrow+8)*68 + ks*8 + kc + 4];
        }
        float cQ[4][4];
#pragma unroll
        for (int nt = 0; nt < 4; nt++) {
            cQ[nt][0]=0.f; cQ[nt][1]=0.f; cQ[nt][2]=0.f; cQ[nt][3]=0.f;
            int ncol = side*32 + nt*8 + qr;
#pragma unroll
            for (int ks = 0; ks < 8; ks++) {
                unsigned b0 = Wqs[ncol*68 + ks*8 + kc];
                unsigned b1 = Wqs[ncol*68 + ks*8 + kc + 4];
                MMA_TF32(cQ[nt][0],cQ[nt][1],cQ[nt][2],cQ[nt][3],
                         aI[ks][0],aI[ks][1],aI[ks][2],aI[ks][3], b0,b1);
            }
        }
#pragma unroll
        for (int nt = 0; nt < 4; nt++) {
            int d = side*32 + nt*8 + 2*kc;
            float bx = bq[d], by = bq[d+1];
            Qst[mrow*68 + d]       = f2tf32(cQ[nt][0] + bx);
            Qst[mrow*68 + d + 1]   = f2tf32(cQ[nt][1] + by);
            Qst[(mrow+8)*68 + d]     = f2tf32(cQ[nt][2] + bx);
            Qst[(mrow+8)*68 + d + 1] = f2tf32(cQ[nt][3] + by);
        }
    }
    __syncthreads();

    // ---- phase 3: S = Q K^T -> P ----
    unsigned a[8][4];
#pragma unroll
    for (int ks = 0; ks < 8; ks++) {
        a[ks][0] = Qst[mrow*68 + ks*8 + kc];
        a[ks][1] = Qst[(mrow+8)*68 + ks*8 + kc];
        a[ks][2] = Qst[mrow*68 + ks*8 + kc + 4];
        a[ks][3] = Qst[(mrow+8)*68 + ks*8 + kc + 4];
    }
    float c[8][4];
#pragma unroll
    for (int nt = 0; nt < 8; nt++) { c[nt][0]=0.f; c[nt][1]=0.f; c[nt][2]=0.f; c[nt][3]=0.f; }
#pragma unroll
    for (int nt = 0; nt < 8; nt++) {
        int ncol = side*64 + nt*8 + qr;
#pragma unroll
        for (int ks = 0; ks < 8; ks++) {
            unsigned b0 = Ks[ncol*68 + ks*8 + kc];
            unsigned b1 = Ks[ncol*68 + ks*8 + kc + 4];
            MMA_TF32(c[nt][0],c[nt][1],c[nt][2],c[nt][3],
                     a[ks][0],a[ks][1],a[ks][2],a[ks][3], b0,b1);
        }
    }
    int i1 = mrow, i2 = mrow + 8;
#pragma unroll
    for (int nt = 0; nt < 8; nt++) {
        int j0 = side*64 + nt*8 + 2*kc;
        int d10 = i1 - j0;     d10 = d10 < 0 ? -d10 : d10;
        int d11 = i1 - j0 - 1; d11 = d11 < 0 ? -d11 : d11;
        int d20 = i2 - j0;     d20 = d20 < 0 ? -d20 : d20;
        int d21 = i2 - j0 - 1; d21 = d21 < 0 ? -d21 : d21;
        Ps[i1*132 + j0]     = c[nt][0]*scale + biasr[d10];
        Ps[i1*132 + j0 + 1] = c[nt][1]*scale + biasr[d11];
        Ps[i2*132 + j0]     = c[nt][2]*scale + biasr[d20];
        Ps[i2*132 + j0 + 1] = c[nt][3]*scale + biasr[d21];
    }
    __syncthreads();

    // ---- phase 4: softmax ----
    for (int rr = 0; rr < 8; rr++) {
        int i = w*8 + rr;
        float v0 = Ps[i*132 + lane], v1 = Ps[i*132 + lane + 32],
              v2 = Ps[i*132 + lane + 64], v3 = Ps[i*132 + lane + 96];
        float mx = fmaxf(fmaxf(v0, v1), fmaxf(v2, v3));
#pragma unroll
        for (int off = 16; off > 0; off >>= 1) mx = fmaxf(mx, __shfl_xor_sync(0xffffffff, mx, off));
        float e0 = __expf(v0 - mx), e1 = __expf(v1 - mx), e2 = __expf(v2 - mx), e3 = __expf(v3 - mx);
        float su = (e0 + e1) + (e2 + e3);
#pragma unroll
        for (int off = 16; off > 0; off >>= 1) su += __shfl_xor_sync(0xffffffff, su, off);
        float inv = 1.0f / su;
        Pu[i*132 + lane]      = f2tf32(e0 * inv);
        Pu[i*132 + lane + 32] = f2tf32(e1 * inv);
        Pu[i*132 + lane + 64] = f2tf32(e2 * inv);
        Pu[i*132 + lane + 96] = f2tf32(e3 * inv);
    }
    __syncthreads();

    // ---- phase 5: out = P @ V ----
    float c2[4][4];
#pragma unroll
    for (int nt = 0; nt < 4; nt++) { c2[nt][0]=0.f; c2[nt][1]=0.f; c2[nt][2]=0.f; c2[nt][3]=0.f; }
#pragma unroll
    for (int ks = 0; ks < 16; ks++) {
        unsigned a0 = Pu[mrow*132 + ks*8 + kc];
        unsigned a1 = Pu[(mrow+8)*132 + ks*8 + kc];
        unsigned a2 = Pu[mrow*132 + ks*8 + kc + 4];
        unsigned a3 = Pu[(mrow+8)*132 + ks*8 + kc + 4];
#pragma unroll
        for (int nt = 0; nt < 4; nt++) {
            int dcol = side*32 + nt*8 + qr;
            unsigned b0 = Vt[dcol*129 + ks*8 + kc];
            unsigned b1 = Vt[dcol*129 + ks*8 + kc + 4];
            MMA_TF32(c2[nt][0],c2[nt][1],c2[nt][2],c2[nt][3], a0,a1,a2,a3, b0,b1);
        }
    }
#pragma unroll
    for (int nt = 0; nt < 4; nt++) {
        int d = side*32 + nt*8 + 2*kc;
        float2 o0; o0.x = c2[nt][0]; o0.y = c2[nt][1];
        float2 o1; o1.x = c2[nt][2]; o1.y = c2[nt][3];
        *(float2*)(g_ALN + ((size_t)(b*Tt + mrow)*Nn + n)*Dd + d)     = o0;
        *(float2*)(g_ALN + ((size_t)(b*Tt + mrow + 8)*Nn + n)*Dd + d) = o1;
    }
}

// ---------------- GCN + residual + LN1, 512 threads, adp+X prefetch ----------------
__global__ void __launch_bounds__(512, 2) k_gcn(const float* __restrict__ Wg,
                                                const float* __restrict__ bg,
                                                const float* __restrict__ ln1g,
                                                const float* __restrict__ ln1b) {
    extern __shared__ float sg[];
    unsigned* As  = (unsigned*)sg;
    unsigned* Bs  = As + 8704;
    unsigned* Tmp = As + 12864;
    unsigned* Wgs = As + 21568;
    float* h2 = sg;   // overlays As

    int tid = threadIdx.x;
    int blk = blockIdx.x;
    int bt = blk >> 1, half = blk & 1;
    int m0g = half * 128;
    int b = bt >> 7, t = bt & 127;
    const float* Xbt = g_ALN + (size_t)bt * 16384;

    int w = tid >> 5, lane = tid & 31;
    int qr = lane >> 2, kc = lane & 3;
    int wp = w >> 1, side = w & 1;
    int mrow = wp*16 + qr;

    for (int idx = tid; idx < 1024; idx += 512) {
        int r = idx >> 4, c4 = idx & 15;
        float4 wv = *(const float4*)(Wg + (size_t)r*64 + c4*4);
        uint4 pv; pv.x = f2tf32(wv.x); pv.y = f2tf32(wv.y);
        pv.z = f2tf32(wv.z); pv.w = f2tf32(wv.w);
        *(uint4*)(Wgs + r*68 + c4*4) = pv;
    }

    float c1[4][4];
#pragma unroll
    for (int nt = 0; nt < 4; nt++) { c1[nt][0]=0.f; c1[nt][1]=0.f; c1[nt][2]=0.f; c1[nt][3]=0.f; }

    // prefetch chunk 0: X rows and adp rows
    float4 pb[2];
    uint4 pa[4];
#pragma unroll
    for (int j = 0; j < 2; j++) {
        int idx = tid + j*512;
        int nn = idx >> 4, c4 = idx & 15;
        pb[j] = *(const float4*)(Xbt + (size_t)nn*64 + c4*4);
    }
#pragma unroll
    for (int j = 0; j < 4; j++) {
        int idx = tid + j*512;
        int r = idx >> 4, c4 = idx & 15;
        pa[j] = *(const uint4*)(g_ADPu + (size_t)(m0g + r)*256 + c4*4);
    }

    for (int ch = 0; ch < 4; ch++) {
        __syncthreads();
#pragma unroll
        for (int j = 0; j < 4; j++) {
            int idx = tid + j*512;
            int r = idx >> 4, c4 = idx & 15;
            *(uint4*)(As + r*68 + c4*4) = pa[j];
        }
#pragma unroll
        for (int j = 0; j < 2; j++) {
            int idx = tid + j*512;
            int nn = idx >> 4, c4 = idx & 15;
            Bs[(c4*4+0)*65 + nn] = f2tf32(pb[j].x);
            Bs[(c4*4+1)*65 + nn] = f2tf32(pb[j].y);
            Bs[(c4*4+2)*65 + nn] = f2tf32(pb[j].z);
            Bs[(c4*4+3)*65 + nn] = f2tf32(pb[j].w);
        }
        __syncthreads();
        if (ch < 3) {
#pragma unroll
            for (int j = 0; j < 2; j++) {
                int idx = tid + j*512;
                int nn = idx >> 4, c4 = idx & 15;
                pb[j] = *(const float4*)(Xbt + (size_t)((ch+1)*64 + nn)*64 + c4*4);
            }
#pragma unroll
            for (int j = 0; j < 4; j++) {
                int idx = tid + j*512;
                int r = idx >> 4, c4 = idx & 15;
                pa[j] = *(const uint4*)(g_ADPu + (size_t)(m0g + r)*256 + (ch+1)*64 + c4*4);
            }
        }
#pragma unroll
        for (int ks = 0; ks < 8; ks++) {
            unsigned a0 = As[mrow*68 + ks*8 + kc];
            unsigned a1 = As[(mrow+8)*68 + ks*8 + kc];
            unsigned a2 = As[mrow*68 + ks*8 + kc + 4];
            unsigned a3 = As[(mrow+8)*68 + ks*8 + kc + 4];
#pragma unroll
            for (int nt = 0; nt < 4; nt++) {
                int dcol = side*32 + nt*8 + qr;
                unsigned b0 = Bs[dcol*65 + ks*8 + kc];
                unsigned b1 = Bs[dcol*65 + ks*8 + kc + 4];
                MMA_TF32(c1[nt][0],c1[nt][1],c1[nt][2],c1[nt][3], a0,a1,a2,a3, b0,b1);
            }
        }
    }

#pragma unroll
    for (int nt = 0; nt < 4; nt++) {
        int d0 = side*32 + nt*8 + 2*kc;
        Tmp[mrow*68 + d0]       = f2tf32(c1[nt][0]);
        Tmp[mrow*68 + d0 + 1]   = f2tf32(c1[nt][1]);
        Tmp[(mrow+8)*68 + d0]     = f2tf32(c1[nt][2]);
        Tmp[(mrow+8)*68 + d0 + 1] = f2tf32(c1[nt][3]);
    }
    __syncthreads();

    float c2[4][4];
#pragma unroll
    for (int nt = 0; nt < 4; nt++) { c2[nt][0]=0.f; c2[nt][1]=0.f; c2[nt][2]=0.f; c2[nt][3]=0.f; }
#pragma unroll
    for (int ks = 0; ks < 8; ks++) {
        unsigned a0 = Tmp[mrow*68 + ks*8 + kc];
        unsigned a1 = Tmp[(mrow+8)*68 + ks*8 + kc];
        unsigned a2 = Tmp[mrow*68 + ks*8 + kc + 4];
        unsigned a3 = Tmp[(mrow+8)*68 + ks*8 + kc + 4];
#pragma unroll
        for (int nt = 0; nt < 4; nt++) {
            int ncol = side*32 + nt*8 + qr;
            unsigned b0 = Wgs[ncol*68 + ks*8 + kc];
            unsigned b1 = Wgs[ncol*68 + ks*8 + kc + 4];
            MMA_TF32(c2[nt][0],c2[nt][1],c2[nt][2],c2[nt][3], a0,a1,a2,a3, b0,b1);
        }
    }
    __syncthreads();

#pragma unroll
    for (int nt = 0; nt < 4; nt++) {
        int e0 = side*32 + nt*8 + 2*kc;
        float bx = bg[e0], by = bg[e0+1];
        h2[mrow*68 + e0]       = fmaxf(c2[nt][0] + bx, 0.f);
        h2[mrow*68 + e0 + 1]   = fmaxf(c2[nt][1] + by, 0.f);
        h2[(mrow+8)*68 + e0]     = fmaxf(c2[nt][2] + bx, 0.f);
        h2[(mrow+8)*68 + e0 + 1] = fmaxf(c2[nt][3] + by, 0.f);
    }
    __syncthreads();

    float gg0 = ln1g[lane], gg1 = ln1g[lane+32];
    float bb0 = ln1b[lane], bb1 = ln1b[lane+32];
    for (int mm = 0; mm < 8; mm++) {
        int m = w*8 + mm;
        const float* xr = Xbt + (size_t)(m0g + m)*64;
        float u0 = xr[lane]      + h2[m*68 + lane];
        float u1 = xr[lane + 32] + h2[m*68 + lane + 32];
        float su = u0 + u1;
#pragma unroll
        for (int off = 16; off > 0; off >>= 1) su += __shfl_xor_sync(0xffffffff, su, off);
        float mean = su * (1.0f/64.0f);
        float dd0 = u0 - mean, dd1 = u1 - mean;
        float q = dd0*dd0 + dd1*dd1;
#pragma unroll
        for (int off = 16; off > 0; off >>= 1) q += __shfl_xor_sync(0xffffffff, q, off);
        float rs = rsqrtf(q*(1.0f/64.0f) + 1e-5f);
        size_t o = ((size_t)(b*Nn + m0g + m)*Tt + t)*Dd;
        g_X1[o + lane]      = dd0*rs*gg0 + bb0;
        g_X1[o + lane + 32] = dd1*rs*gg1 + bb1;
    }
}

// ---------------- tensor-core GRU with full-chunk prefetch ----------------
__global__ void __launch_bounds__(256) k_gru_tc(const float* __restrict__ Whh,
                                                const float* __restrict__ bhh,
                                                const float* __restrict__ Wih,
                                                const float* __restrict__ bih,
                                                const float* __restrict__ ln2g,
                                                const float* __restrict__ ln2b,
                                                float* __restrict__ out) {
    extern __shared__ unsigned su_[];
    unsigned* Whs = su_;
    unsigned* Wis = su_ + 13056;
    unsigned* X1s = su_;
    float*    X1f = (float*)(su_ + 4352);
    unsigned* Hb0 = su_ + 8704;
    unsigned* Hb1 = su_ + 9792;
    float*    U4  = (float*)(su_ + 10880);

    int tid = threadIdx.x;
    int w = tid >> 5, lane = tid & 31;
    int qr = lane >> 2, kc = lane & 3;
    int s_base = blockIdx.x * 16;
    int b = s_base >> 8;
    int node0 = s_base & 255;

    for (int idx = tid; idx < 3072; idx += 256) {
        int r = idx >> 4, c4 = idx & 15;
        float4 wv = *(const float4*)(Whh + (size_t)r*64 + c4*4);
        uint4 pv; pv.x = f2tf32(wv.x); pv.y = f2tf32(wv.y);
        pv.z = f2tf32(wv.z); pv.w = f2tf32(wv.w);
        *(uint4*)(Whs + r*68 + c4*4) = pv;
        float4 iv = *(const float4*)(Wih + (size_t)r*64 + c4*4);
        uint4 qv; qv.x = f2tf32(iv.x); qv.y = f2tf32(iv.y);
        qv.z = f2tf32(iv.z); qv.w = f2tf32(iv.w);
        *(uint4*)(Wis + r*68 + c4*4) = qv;
    }
    __syncthreads();

    unsigned br_[8][2], bz_[8][2], bn_[8][2];
    unsigned wr_[8][2], wz_[8][2], wn_[8][2];
#pragma unroll
    for (int ks = 0; ks < 8; ks++) {
        int nr = (0*64 + w*8 + qr)*68 + ks*8 + kc;
        int nz = (1*64 + w*8 + qr)*68 + ks*8 + kc;
        int nn = (2*64 + w*8 + qr)*68 + ks*8 + kc;
        br_[ks][0] = Whs[nr]; br_[ks][1] = Whs[nr + 4];
        bz_[ks][0] = Whs[nz]; bz_[ks][1] = Whs[nz + 4];
        bn_[ks][0] = Whs[nn]; bn_[ks][1] = Whs[nn + 4];
        wr_[ks][0] = Wis[nr]; wr_[ks][1] = Wis[nr + 4];
        wz_[ks][0] = Wis[nz]; wz_[ks][1] = Wis[nz + 4];
        wn_[ks][0] = Wis[nn]; wn_[ks][1] = Wis[nn + 4];
    }
    __syncthreads();

    for (int idx = tid; idx < 1088; idx += 256) Hb0[idx] = 0;

    int col0 = w*8 + 2*kc;
    float2 bhr = *(const float2*)(bhh + col0);
    float2 bhz = *(const float2*)(bhh + 64 + col0);
    float2 bhn = *(const float2*)(bhh + 128 + col0);
    float2 bir = *(const float2*)(bih + col0);
    float2 biz = *(const float2*)(bih + 64 + col0);
    float2 bin_ = *(const float2*)(bih + 128 + col0);
    float g2a = ln2g[lane], g2b = ln2g[lane+32];
    float b2a = ln2b[lane], b2b = ln2b[lane+32];

    float h_old[4] = {0.f, 0.f, 0.f, 0.f};

    // prefetch FULL chunk 0
    float px[16];
#pragma unroll
    for (int i = 0; i < 16; i++) {
        int idx = tid + i*256;
        int s = idx >> 10, rem = idx & 1023, row = rem >> 6, col = rem & 63;
        px[i] = g_X1[(size_t)(s_base + row)*Tt*Dd + (size_t)s*Dd + col];
    }

    for (int tc = 0; tc < Tt; tc += 4) {
        __syncthreads();

        // store entire prefetched chunk (no exposed loads)
#pragma unroll
        for (int i = 0; i < 16; i++) {
            int idx = tid + i*256;
            int s = idx >> 10, rem = idx & 1023, row = rem >> 6, col = rem & 63;
            X1s[s*1088 + row*68 + col] = f2tf32(px[i]);
            X1f[s*1088 + row*68 + col] = px[i];
        }
        __syncthreads();

        // prefetch FULL next chunk (hidden behind gi mma + serial section)
        if (tc + 4 < Tt) {
#pragma unroll
            for (int i = 0; i < 16; i++) {
                int idx = tid + i*256;
                int s = idx >> 10, rem = idx & 1023, row = rem >> 6, col = rem & 63;
                px[i] = g_X1[(size_t)(s_base + row)*Tt*Dd + (size_t)(tc + 4 + s)*Dd + col];
            }
        }

        float gr_[4][4], gz_[4][4], gn_[4][4];
#pragma unroll
        for (int s = 0; s < 4; s++) {
            const unsigned* Xc = X1s + s*1088;
            unsigned ax[8][4];
#pragma unroll
            for (int ks = 0; ks < 8; ks++) {
                ax[ks][0] = Xc[qr*68 + ks*8 + kc];
                ax[ks][1] = Xc[(qr+8)*68 + ks*8 + kc];
                ax[ks][2] = Xc[qr*68 + ks*8 + kc + 4];
                ax[ks][3] = Xc[(qr+8)*68 + ks*8 + kc + 4];
            }
            gr_[s][0]=0.f; gr_[s][1]=0.f; gr_[s][2]=0.f; gr_[s][3]=0.f;
            gz_[s][0]=0.f; gz_[s][1]=0.f; gz_[s][2]=0.f; gz_[s][3]=0.f;
            gn_[s][0]=0.f; gn_[s][1]=0.f; gn_[s][2]=0.f; gn_[s][3]=0.f;
#pragma unroll
            for (int ks = 0; ks < 8; ks++) {
                MMA_TF32(gr_[s][0],gr_[s][1],gr_[s][2],gr_[s][3], ax[ks][0],ax[ks][1],ax[ks][2],ax[ks][3], wr_[ks][0],wr_[ks][1]);
                MMA_TF32(gz_[s][0],gz_[s][1],gz_[s][2],gz_[s][3], ax[ks][0],ax[ks][1],ax[ks][2],ax[ks][3], wz_[ks][0],wz_[ks][1]);
                MMA_TF32(gn_[s][0],gn_[s][1],gn_[s][2],gn_[s][3], ax[ks][0],ax[ks][1],ax[ks][2],ax[ks][3], wn_[ks][0],wn_[ks][1]);
            }
        }

#pragma unroll
        for (int s = 0; s < 4; s++) {
            int t = tc + s;
            unsigned* Hc = (t & 1) ? Hb1 : Hb0;
            unsigned* Hn = (t & 1) ? Hb0 : Hb1;
            float* Us = U4 + s*1088;
            const float* Xf = X1f + s*1088;

            float2 xa = *(const float2*)(Xf + qr*68 + col0);
            float2 xb = *(const float2*)(Xf + (qr+8)*68 + col0);

            float cr[4] = {0.f,0.f,0.f,0.f}, cz[4] = {0.f,0.f,0.f,0.f}, cn[4] = {0.f,0.f,0.f,0.f};
            {
                unsigned a[8][4];
#pragma unroll
                for (int ks = 0; ks < 8; ks++) {
                    a[ks][0] = Hc[qr*68 + ks*8 + kc];
                    a[ks][1] = Hc[(qr+8)*68 + ks*8 + kc];
                    a[ks][2] = Hc[qr*68 + ks*8 + kc + 4];
                    a[ks][3] = Hc[(qr+8)*68 + ks*8 + kc + 4];
                }
#pragma unroll
                for (int ks = 0; ks < 8; ks++) {
                    MMA_TF32(cr[0],cr[1],cr[2],cr[3], a[ks][0],a[ks][1],a[ks][2],a[ks][3], br_[ks][0],br_[ks][1]);
                    MMA_TF32(cz[0],cz[1],cz[2],cz[3], a[ks][0],a[ks][1],a[ks][2],a[ks][3], bz_[ks][0],bz_[ks][1]);
                    MMA_TF32(cn[0],cn[1],cn[2],cn[3], a[ks][0],a[ks][1],a[ks][2],a[ks][3], bn_[ks][0],bn_[ks][1]);
                }
            }

            float r0 = siga(gr_[s][0] + bir.x + cr[0] + bhr.x);
            float r1 = siga(gr_[s][1] + bir.y + cr[1] + bhr.y);
            float r2 = siga(gr_[s][2] + bir.x + cr[2] + bhr.x);
            float r3 = siga(gr_[s][3] + bir.y + cr[3] + bhr.y);
            float z0 = siga(gz_[s][0] + biz.x + cz[0] + bhz.x);
            float z1 = siga(gz_[s][1] + biz.y + cz[1] + bhz.y);
            float z2 = siga(gz_[s][2] + biz.x + cz[2] + bhz.x);
            float z3 = siga(gz_[s][3] + biz.y + cz[3] + bhz.y);
            float n0 = tanha(gn_[s][0] + bin_.x + r0*(cn[0] + bhn.x));
            float n1 = tanha(gn_[s][1] + bin_.y + r1*(cn[1] + bhn.y));
            float n2 = tanha(gn_[s][2] + bin_.x + r2*(cn[2] + bhn.x));
            float n3 = tanha(gn_[s][3] + bin_.y + r3*(cn[3] + bhn.y));
            float h0 = (1.f - z0)*n0 + z0*h_old[0];
            float h1 = (1.f - z1)*n1 + z1*h_old[1];
            float h2v = (1.f - z2)*n2 + z2*h_old[2];
            float h3 = (1.f - z3)*n3 + z3*h_old[3];
            h_old[0] = h0; h_old[1] = h1; h_old[2] = h2v; h_old[3] = h3;

            uint2 hp0; hp0.x = f2tf32(h0); hp0.y = f2tf32(h1);
            uint2 hp1; hp1.x = f2tf32(h2v); hp1.y = f2tf32(h3);
            *(uint2*)(Hn + qr*68 + col0)     = hp0;
            *(uint2*)(Hn + (qr+8)*68 + col0) = hp1;
            float2 up0; up0.x = xa.x + h0; up0.y = xa.y + h1;
            float2 up1; up1.x = xb.x + h2v; up1.y = xb.y + h3;
            *(float2*)(Us + qr*68 + col0)     = up0;
            *(float2*)(Us + (qr+8)*68 + col0) = up1;
            __syncthreads();
        }

#pragma unroll
        for (int rr = 0; rr < 8; rr++) {
            int inst = w*8 + rr;
            int s = inst >> 4, row = inst & 15;
            const float* Us = U4 + s*1088;
            const float* Xf = X1f + s*1088;
            float v0 = Us[row*68 + lane], v1 = Us[row*68 + lane + 32];
            float sv = v0 + v1, qv = v0*v0 + v1*v1;
#pragma unroll
            for (int off = 16; off > 0; off >>= 1) {
                sv += __shfl_xor_sync(0xffffffff, sv, off);
                qv += __shfl_xor_sync(0xffffffff, qv, off);
            }
            float mean = sv * (1.0f/64.0f);
            float var = qv*(1.0f/64.0f) - mean*mean;
            float rs = rsqrtf(var + 1e-5f);
            float x0v = Xf[row*68 + lane], x1v = Xf[row*68 + lane + 32];
            size_t oo = (size_t)b*Tt*Nn*Dd + (size_t)(tc + s)*Nn*Dd + (size_t)(node0 + row)*Dd;
            out[oo + lane]      = x0v + (v0 - mean)*rs*g2a + b2a;
            out[oo + lane + 32] = x1v + (v1 - mean)*rs*g2b + b2b;
        }
    }
}

// ---------------- launcher ----------------
extern "C" void kernel_launch(void* const* d_in, const int* in_sizes, int n_in,
                              void* d_out, int out_size) {
    (void)in_sizes; (void)n_in; (void)out_size;
    const float* H_i  = (const float*)d_in[0];
    const float* H_j  = (const float*)d_in[1];
    const float* Wq   = (const float*)d_in[2];
    const float* bq   = (const float*)d_in[3];
    const float* Wk   = (const float*)d_in[4];
    const float* bk   = (const float*)d_in[5];
    const float* Wv   = (const float*)d_in[6];
    const float* bv   = (const float*)d_in[7];
    const float* lgam = (const float*)d_in[8];
    const float* ltau = (const float*)d_in[9];
    const float* e1   = (const float*)d_in[10];
    const float* e2   = (const float*)d_in[11];
    const float* Wg   = (const float*)d_in[12];
    const float* bg   = (const float*)d_in[13];
    const float* ln1g = (const float*)d_in[14];
    const float* ln1b = (const float*)d_in[15];
    const float* Wih  = (const float*)d_in[16];
    const float* Whh  = (const float*)d_in[17];
    const float* bih  = (const float*)d_in[18];
    const float* bhh  = (const float*)d_in[19];
    const float* ln2g = (const float*)d_in[20];
    const float* ln2b = (const float*)d_in[21];
    float* out = (float*)d_out;

    const int ATTN_SMEM = 56256 * 4;   // 225024 B
    const int GCN_SMEM  = 25920 * 4;   // 103680 B
    const int GRU_SMEM  = 26112 * 4;   // 104448 B
    cudaFuncSetAttribute(k_attn, cudaFuncAttributeMaxDynamicSharedMemorySize, ATTN_SMEM);
    cudaFuncSetAttribute(k_gcn,  cudaFuncAttributeMaxDynamicSharedMemorySize, GCN_SMEM);
    cudaFuncSetAttribute(k_gru_tc, cudaFuncAttributeMaxDynamicSharedMemorySize, GRU_SMEM);

    k_adj<<<256, 256>>>(e1, e2);
    k_attn<<<Bb*Nn, 512, ATTN_SMEM>>>(H_i, H_j, Wq, bq, Wk, bk, Wv, bv, lgam, ltau);
    k_gcn<<<Bb*Tt*2, 512, GCN_SMEM>>>(Wg, bg, ln1g, ln1b);
    k_gru_tc<<<Bb*Nn/16, 256, GRU_SMEM>>>(Whh, bhh, Wih, bih, ln2g, ln2b, out);
}